// round 9
// baseline (speedup 1.0000x reference)
#include <cuda_runtime.h>
#include <cuda_fp16.h>
#include <math.h>

#define T_LEN 4096
#define TR_LEN 1024
#define DIM 1536
#define NH 12
#define DH 128

// ---------------- scratch (device globals; no allocation allowed) ----------------
__device__ float g_qlin[T_LEN * DIM];
__device__ float g_klin[T_LEN * DIM];
__device__ float g_vlin[T_LEN * DIM];
__device__ float g_krlin[TR_LEN * DIM];
__device__ float g_vrlin[TR_LEN * DIM];

__device__ __half g_hsh[T_LEN * DIM];
__device__ __half g_rhsh[TR_LEN * DIM];
__device__ __half g_wth[6 * DIM * DIM];   // Wq,Wk,Wv,Wkr,Wvr,Wo transposed [n][k]
__device__ __half g_qh[T_LEN * DIM];      // rms(q)*scale
__device__ __half g_qroph[T_LEN * DIM];   // rope(rms(q))*scale
__device__ __half g_kh[T_LEN * DIM];      // rope(rms(k))
__device__ __half g_vth[DIM * T_LEN];     // V transposed [h*DH + d][t]
__device__ __half g_krh[TR_LEN * DIM];    // rms(ref k)
__device__ __half g_vrth[DIM * TR_LEN];   // ref V transposed
__device__ __half g_attnh[T_LEN * DIM];   // attention output (half, fused ref+main)

// ---------------- PTX helpers ----------------
__device__ __forceinline__ void mma_f16(float& c0, float& c1, float& c2, float& c3,
                                        unsigned a0, unsigned a1, unsigned a2, unsigned a3,
                                        unsigned b0, unsigned b1) {
    asm volatile(
        "mma.sync.aligned.m16n8k16.row.col.f32.f16.f16.f32 "
        "{%0,%1,%2,%3},{%4,%5,%6,%7},{%8,%9},{%0,%1,%2,%3};"
        : "+f"(c0), "+f"(c1), "+f"(c2), "+f"(c3)
        : "r"(a0), "r"(a1), "r"(a2), "r"(a3), "r"(b0), "r"(b1));
}
__device__ __forceinline__ void ldsm4(unsigned& r0, unsigned& r1, unsigned& r2, unsigned& r3,
                                      unsigned addr) {
    asm volatile("ldmatrix.sync.aligned.m8n8.x4.shared.b16 {%0,%1,%2,%3}, [%4];"
                 : "=r"(r0), "=r"(r1), "=r"(r2), "=r"(r3) : "r"(addr));
}
__device__ __forceinline__ void cp16(void* dst_smem, const void* src) {
    unsigned s = (unsigned)__cvta_generic_to_shared(dst_smem);
    asm volatile("cp.async.cg.shared.global [%0], [%1], 16;" :: "r"(s), "l"(src));
}
__device__ __forceinline__ void cp_commit() { asm volatile("cp.async.commit_group;"); }
__device__ __forceinline__ void cp_wait0()  { asm volatile("cp.async.wait_group 0;"); }
__device__ __forceinline__ unsigned h2u(__half2 h) { return *(unsigned*)&h; }

// ---------------- float -> half conversion ----------------
__global__ __launch_bounds__(256) void cvt_h(
    const float* __restrict__ in, __half* __restrict__ out, int n, float scale)
{
    int i4 = (blockIdx.x * 256 + threadIdx.x) * 4;
    if (i4 >= n) return;
    float4 v = *(const float4*)(in + i4);
    __half2 h0 = __float22half2_rn(make_float2(v.x * scale, v.y * scale));
    __half2 h1 = __float22half2_rn(make_float2(v.z * scale, v.w * scale));
    uint2 u; u.x = h2u(h0); u.y = h2u(h1);
    *(uint2*)(out + i4) = u;
}

// ---------------- tiled transpose: float [R][C] -> half [C][R] ----------------
__global__ __launch_bounds__(256) void transpose_h(
    const float* __restrict__ in, __half* __restrict__ out, int R, int C)
{
    __shared__ float t[32][33];
    int c0 = blockIdx.x * 32, r0 = blockIdx.y * 32;
    int tx = threadIdx.x, ty = threadIdx.y;
#pragma unroll
    for (int yy = 0; yy < 32; yy += 8)
        t[ty + yy][tx] = in[(size_t)(r0 + ty + yy) * C + c0 + tx];
    __syncthreads();
#pragma unroll
    for (int yy = 0; yy < 32; yy += 8)
        out[(size_t)(c0 + ty + yy) * R + r0 + tx] = __float2half_rn(t[tx][ty + yy]);
}

// 6 weight transposes in one launch (z picks the matrix)
struct Src6 { const float* p[6]; };
__global__ __launch_bounds__(256) void transpose6_h(Src6 s, __half* __restrict__ dstbase)
{
    __shared__ float t[32][33];
    const float* in = s.p[blockIdx.z];
    __half* out = dstbase + (size_t)blockIdx.z * DIM * DIM;
    int c0 = blockIdx.x * 32, r0 = blockIdx.y * 32;
    int tx = threadIdx.x, ty = threadIdx.y;
#pragma unroll
    for (int yy = 0; yy < 32; yy += 8)
        t[ty + yy][tx] = in[(size_t)(r0 + ty + yy) * DIM + c0 + tx];
    __syncthreads();
#pragma unroll
    for (int yy = 0; yy < 32; yy += 8)
        out[(size_t)(c0 + ty + yy) * DIM + r0 + tx] = __float2half_rn(t[tx][ty + yy]);
}

// ================= GEMM (fp16 mma + ldmatrix), up to 3 outputs per launch =================
// ktile = 64 halves. Smem pitch 36 unsigned (72 halves). Block tile (MT*32) x 128.
// 256 threads: warps 2(m) x 4(n), warp tile (MT*16) x 32.
#define GP2 36
struct Gemm3 { const __half* W[3]; const float* b[3]; float* C[3]; };

template<int MT>
__global__ __launch_bounds__(256) void gemm_f16_multi(
    const __half* __restrict__ A, Gemm3 p)
{
    constexpr int TM = MT * 32;
    constexpr int OFF_A0 = 0;
    constexpr int OFF_A1 = TM * GP2;
    constexpr int OFF_B0 = 2 * TM * GP2;
    constexpr int OFF_B1 = OFF_B0 + 128 * GP2;

    extern __shared__ unsigned smu[];
    const int which = blockIdx.x / 12;
    const __half* Wt = p.W[which];
    const float* bias = p.b[which];
    float* C = p.C[which];

    const int bm = blockIdx.y * TM;
    const int bn = (blockIdx.x % 12) * 128;
    const int tid = threadIdx.x;
    const int lane = tid & 31, warp = tid >> 5;
    const int g = lane >> 2, l = lane & 3;
    const int wm = (warp >> 2) * (MT * 16);
    const int wn = (warp & 3) * 32;
    const unsigned sbase = (unsigned)__cvta_generic_to_shared(smu);

    // ldmatrix lane-address components
    const int bl_row  = (lane & 7) + ((lane & 16) ? 8 : 0);
    const int bl_colu = (lane & 8) ? 4 : 0;
    const unsigned a_lane = ((wm + (lane & 15)) * GP2 + ((lane & 16) ? 4 : 0)) * 4;
    const unsigned b_lane = ((wn + bl_row) * GP2 + bl_colu) * 4;

    float c[MT][4][4];
#pragma unroll
    for (int mt = 0; mt < MT; mt++)
#pragma unroll
        for (int nt = 0; nt < 4; nt++)
#pragma unroll
            for (int i = 0; i < 4; i++) c[mt][nt][i] = 0.f;

    auto issue = [&](int kt, int buf) {
        unsigned* Au = smu + (buf ? OFF_A1 : OFF_A0);
        unsigned* Bu = smu + (buf ? OFF_B1 : OFF_B0);
        const int k0 = kt * 64;
#pragma unroll
        for (int u = 0; u < MT; u++) {              // A: TM rows x 8 cp16
            int i = tid + u * 256;
            int r = i >> 3, c4 = i & 7;
            cp16(Au + r * GP2 + c4 * 4, A + (size_t)(bm + r) * DIM + k0 + c4 * 8);
        }
#pragma unroll
        for (int u = 0; u < 4; u++) {               // B: 128 rows x 8 cp16
            int i = tid + u * 256;
            int r = i >> 3, c4 = i & 7;
            cp16(Bu + r * GP2 + c4 * 4, Wt + (size_t)(bn + r) * DIM + k0 + c4 * 8);
        }
        cp_commit();
    };

    issue(0, 0);
    const int NKT = DIM / 64;  // 24
    for (int kt = 0; kt < NKT; kt++) {
        int buf = kt & 1;
        cp_wait0();
        __syncthreads();                            // buf^1 free before refill
        if (kt + 1 < NKT) issue(kt + 1, buf ^ 1);

        const unsigned abase = sbase + (buf ? OFF_A1 : OFF_A0) * 4 + a_lane;
        const unsigned bbase = sbase + (buf ? OFF_B1 : OFF_B0) * 4 + b_lane;

#pragma unroll
        for (int kk = 0; kk < 4; kk++) {
            unsigned a[MT][4];
#pragma unroll
            for (int mt = 0; mt < MT; mt++)
                ldsm4(a[mt][0], a[mt][1], a[mt][2], a[mt][3],
                      abase + (mt * 16 * GP2) * 4 + kk * 32);
            unsigned b[2][4];
#pragma unroll
            for (int nb = 0; nb < 2; nb++)
                ldsm4(b[nb][0], b[nb][1], b[nb][2], b[nb][3],
                      bbase + (nb * 16 * GP2) * 4 + kk * 32);
#pragma unroll
            for (int mt = 0; mt < MT; mt++) {
#pragma unroll
                for (int nb = 0; nb < 2; nb++) {
                    mma_f16(c[mt][2*nb][0], c[mt][2*nb][1], c[mt][2*nb][2], c[mt][2*nb][3],
                            a[mt][0], a[mt][1], a[mt][2], a[mt][3], b[nb][0], b[nb][1]);
                    mma_f16(c[mt][2*nb+1][0], c[mt][2*nb+1][1], c[mt][2*nb+1][2], c[mt][2*nb+1][3],
                            a[mt][0], a[mt][1], a[mt][2], a[mt][3], b[nb][2], b[nb][3]);
                }
            }
        }
    }

#pragma unroll
    for (int mt = 0; mt < MT; mt++) {
#pragma unroll
        for (int nt = 0; nt < 4; nt++) {
            int row = bm + wm + mt * 16 + g;
            int col = bn + wn + nt * 8 + 2 * l;
            float b0 = bias[col], b1 = bias[col + 1];
            C[(size_t)row * DIM + col]           = c[mt][nt][0] + b0;
            C[(size_t)row * DIM + col + 1]       = c[mt][nt][1] + b1;
            C[(size_t)(row + 8) * DIM + col]     = c[mt][nt][2] + b0;
            C[(size_t)(row + 8) * DIM + col + 1] = c[mt][nt][3] + b1;
        }
    }
}

#define GEMM_SMEM_M ((4 * 128 * GP2) * 4)                 // 73728 B
#define GEMM_SMEM_R ((2 * 64 * GP2 + 2 * 128 * GP2) * 4)  // 55296 B

// ---------------- RMSNorm ----------------
__global__ __launch_bounds__(256) void rmsnorm_kernel(
    const float* __restrict__ x, const float* __restrict__ g,
    float* __restrict__ out_f, __half* __restrict__ out_b, float bscale)
{
    const int row = blockIdx.x;
    const float* xr = x + (size_t)row * DIM;
    const int tid = threadIdx.x;

    float ss = 0.f;
    for (int i = tid; i < DIM; i += 256) {
        float v = xr[i];
        ss += v * v;
    }
#pragma unroll
    for (int off = 16; off; off >>= 1) ss += __shfl_xor_sync(0xffffffffu, ss, off);

    __shared__ float wsum[8];
    __shared__ float inv_s;
    if ((tid & 31) == 0) wsum[tid >> 5] = ss;
    __syncthreads();
    if (tid == 0) {
        float t = 0.f;
#pragma unroll
        for (int w = 0; w < 8; w++) t += wsum[w];
        inv_s = rsqrtf(t / (float)DIM + 1e-6f);
    }
    __syncthreads();
    float inv = inv_s;
    for (int i = tid; i < DIM; i += 256) {
        float v = xr[i] * inv * g[i];
        if (out_f) out_f[(size_t)row * DIM + i] = v;
        if (out_b) out_b[(size_t)row * DIM + i] = __float2half_rn(v * bscale);
    }
}

// ---------------- RoPE -> half ----------------
__global__ __launch_bounds__(256) void rope_kernel(
    const float* __restrict__ in, __half* __restrict__ out,
    const float* __restrict__ rc, const float* __restrict__ rs, float scale)
{
    int idx = blockIdx.x * 256 + threadIdx.x;
    if (idx >= T_LEN * (DIM / 2)) return;
    int t = idx / (DIM / 2);
    int p = idx % (DIM / 2);
    int h = p >> 6;
    int i = p & 63;
    size_t base = (size_t)t * DIM + h * DH + 2 * i;
    float e = in[base];
    float o = in[base + 1];
    float c = rc[t * (DH / 2) + i];
    float s = rs[t * (DH / 2) + i];
    *(__half2*)(out + base) =
        __float22half2_rn(make_float2((e * c - o * s) * scale, (e * s + o * c) * scale));
}

// ================= Fused flash attention (ref + main in one kernel) =================
#define AQ 68
#define ATT_Q  0
#define ATT_K0 (128 * AQ)
#define ATT_K1 (ATT_K0 + 128 * AQ)
#define ATT_V0 (ATT_K1 + 128 * AQ)
#define ATT_V1 (ATT_V0 + 128 * AQ)
#define ATT_SMEM ((ATT_V1 + 128 * AQ) * 4)   // 174080 B

__global__ __launch_bounds__(256) void attn_fused(
    const __half* __restrict__ Q0, const __half* __restrict__ K0p,
    const __half* __restrict__ V0p, int Tk0,
    const __half* __restrict__ Q1, const __half* __restrict__ K1p,
    const __half* __restrict__ V1p, int Tk1,
    __half* __restrict__ Outh)
{
    extern __shared__ unsigned smu[];

    const int h = blockIdx.y;
    const int q0 = blockIdx.x * 128;
    const int tid = threadIdx.x;
    const int lane = tid & 31, warp = tid >> 5;
    const int g = lane >> 2, l = lane & 3;
    const unsigned sbase = (unsigned)__cvta_generic_to_shared(smu);

    const int ql_row = lane & 15;
    const unsigned ql_addr = sbase + (ATT_Q + (warp * 16 + ql_row) * AQ
                                      + ((lane & 16) ? 4 : 0)) * 4;
    const int bl_row  = (lane & 7) + ((lane & 16) ? 8 : 0);
    const int bl_colu = (lane & 8) ? 4 : 0;

    auto issue_Q = [&](const __half* Qp) {
#pragma unroll
        for (int u = 0; u < 8; u++) {
            int i = tid + u * 256;
            int r = i >> 4, c4 = i & 15;
            cp16(smu + ATT_Q + r * AQ + c4 * 4,
                 Qp + (size_t)(q0 + r) * DIM + h * DH + c4 * 8);
        }
    };
    auto issue_tile = [&](const __half* Kp, const __half* Vt, int Tk, int t, int buf) {
        unsigned* Ku = smu + (buf ? ATT_K1 : ATT_K0);
        unsigned* Vu = smu + (buf ? ATT_V1 : ATT_V0);
        const size_t krow = (size_t)(t * 128) * DIM + h * DH;
#pragma unroll
        for (int u = 0; u < 8; u++) {
            int i = tid + u * 256;
            int r = i >> 4, c4 = i & 15;
            cp16(Ku + r * AQ + c4 * 4, Kp + krow + (size_t)r * DIM + c4 * 8);
        }
#pragma unroll
        for (int u = 0; u < 8; u++) {
            int i = tid + u * 256;
            int r = i >> 4, c4 = i & 15;
            cp16(Vu + r * AQ + c4 * 4,
                 Vt + (size_t)(h * DH + r) * Tk + t * 128 + c4 * 8);
        }
        cp_commit();
    };

    float o[16][4];
    float m0, m1, l0, l1;
    unsigned qa[8][4];
    unsigned stash[16][2];

#pragma unroll
    for (int ph = 0; ph < 2; ph++) {
        const __half* Qp = ph ? Q1 : Q0;
        const __half* Kp = ph ? K1p : K0p;
        const __half* Vp = ph ? V1p : V0p;
        const int Tk = ph ? Tk1 : Tk0;
        const int ntiles = Tk / 128;

#pragma unroll
        for (int nt = 0; nt < 16; nt++)
#pragma unroll
            for (int i = 0; i < 4; i++) o[nt][i] = 0.f;
        m0 = m1 = -1e30f;
        l0 = l1 = 0.f;

        issue_Q(Qp);
        issue_tile(Kp, Vp, Tk, 0, 0);

        for (int t = 0; t < ntiles; t++) {
            int buf = t & 1;
            cp_wait0();
            __syncthreads();
            if (t + 1 < ntiles) issue_tile(Kp, Vp, Tk, t + 1, buf ^ 1);

            if (t == 0) {
#pragma unroll
                for (int kk = 0; kk < 8; kk++)
                    ldsm4(qa[kk][0], qa[kk][1], qa[kk][2], qa[kk][3], ql_addr + kk * 32);
            }

            const unsigned koff = sbase + (buf ? ATT_K1 : ATT_K0) * 4;
            const unsigned voff = sbase + (buf ? ATT_V1 : ATT_V0) * 4;

#pragma unroll
            for (int st = 0; st < 2; st++) {
                float s[8][4];
#pragma unroll
                for (int nt = 0; nt < 8; nt++)
#pragma unroll
                    for (int i = 0; i < 4; i++) s[nt][i] = 0.f;

#pragma unroll
                for (int kk = 0; kk < 8; kk++) {
                    unsigned kb[4][4];
#pragma unroll
                    for (int j = 0; j < 4; j++)
                        ldsm4(kb[j][0], kb[j][1], kb[j][2], kb[j][3],
                              koff + ((st * 64 + j * 16 + bl_row) * AQ + kk * 8 + bl_colu) * 4);
#pragma unroll
                    for (int j = 0; j < 4; j++) {
                        mma_f16(s[2*j][0], s[2*j][1], s[2*j][2], s[2*j][3],
                                qa[kk][0], qa[kk][1], qa[kk][2], qa[kk][3], kb[j][0], kb[j][1]);
                        mma_f16(s[2*j+1][0], s[2*j+1][1], s[2*j+1][2], s[2*j+1][3],
                                qa[kk][0], qa[kk][1], qa[kk][2], qa[kk][3], kb[j][2], kb[j][3]);
                    }
                }

                float tm0 = -1e30f, tm1 = -1e30f;
#pragma unroll
                for (int nt = 0; nt < 8; nt++) {
                    tm0 = fmaxf(tm0, fmaxf(s[nt][0], s[nt][1]));
                    tm1 = fmaxf(tm1, fmaxf(s[nt][2], s[nt][3]));
                }
                tm0 = fmaxf(tm0, __shfl_xor_sync(0xffffffffu, tm0, 1));
                tm0 = fmaxf(tm0, __shfl_xor_sync(0xffffffffu, tm0, 2));
                tm1 = fmaxf(tm1, __shfl_xor_sync(0xffffffffu, tm1, 1));
                tm1 = fmaxf(tm1, __shfl_xor_sync(0xffffffffu, tm1, 2));
                float mn0 = fmaxf(m0, tm0), mn1 = fmaxf(m1, tm1);
                float al0 = __expf(m0 - mn0), al1 = __expf(m1 - mn1);
                m0 = mn0; m1 = mn1;

                unsigned pa[4][4];
                float sum0 = 0.f, sum1 = 0.f;
#pragma unroll
                for (int nt = 0; nt < 8; nt++) {
                    float p0 = __expf(s[nt][0] - mn0);
                    float p1 = __expf(s[nt][1] - mn0);
                    float p2 = __expf(s[nt][2] - mn1);
                    float p3 = __expf(s[nt][3] - mn1);
                    sum0 += p0 + p1;
                    sum1 += p2 + p3;
                    unsigned lo = h2u(__float22half2_rn(make_float2(p0, p1)));
                    unsigned hi = h2u(__float22half2_rn(make_float2(p2, p3)));
                    int kt = nt >> 1;
                    if ((nt & 1) == 0) { pa[kt][0] = lo; pa[kt][1] = hi; }
                    else               { pa[kt][2] = lo; pa[kt][3] = hi; }
                }
                sum0 += __shfl_xor_sync(0xffffffffu, sum0, 1);
                sum0 += __shfl_xor_sync(0xffffffffu, sum0, 2);
                sum1 += __shfl_xor_sync(0xffffffffu, sum1, 1);
                sum1 += __shfl_xor_sync(0xffffffffu, sum1, 2);
                l0 = l0 * al0 + sum0;
                l1 = l1 * al1 + sum1;
#pragma unroll
                for (int nt = 0; nt < 16; nt++) {
                    o[nt][0] *= al0; o[nt][1] *= al0;
                    o[nt][2] *= al1; o[nt][3] *= al1;
                }

#pragma unroll
                for (int kt = 0; kt < 4; kt++) {
                    unsigned vb[8][4];
#pragma unroll
                    for (int j = 0; j < 8; j++)
                        ldsm4(vb[j][0], vb[j][1], vb[j][2], vb[j][3],
                              voff + ((j * 16 + bl_row) * AQ + st * 32 + kt * 8 + bl_colu) * 4);
#pragma unroll
                    for (int j = 0; j < 8; j++) {
                        mma_f16(o[2*j][0], o[2*j][1], o[2*j][2], o[2*j][3],
                                pa[kt][0], pa[kt][1], pa[kt][2], pa[kt][3], vb[j][0], vb[j][1]);
                        mma_f16(o[2*j+1][0], o[2*j+1][1], o[2*j+1][2], o[2*j+1][3],
                                pa[kt][0], pa[kt][1], pa[kt][2], pa[kt][3], vb[j][2], vb[j][3]);
                    }
                }
            }
        }

        if (ph == 0) {
            float inv0 = 1.f / l0, inv1 = 1.f / l1;
#pragma unroll
            for (int nt = 0; nt < 16; nt++) {
                stash[nt][0] = h2u(__float22half2_rn(
                    make_float2(o[nt][0] * inv0, o[nt][1] * inv0)));
                stash[nt][1] = h2u(__float22half2_rn(
                    make_float2(o[nt][2] * inv1, o[nt][3] * inv1)));
            }
        }
    }

    float inv0 = 1.f / l0, inv1 = 1.f / l1;
    int row0 = q0 + warp * 16 + g;
    int row1 = row0 + 8;
#pragma unroll
    for (int nt = 0; nt < 16; nt++) {
        int col = h * DH + nt * 8 + 2 * l;
        float2 r0 = __half22float2(*(__half2*)&stash[nt][0]);
        float2 r1 = __half22float2(*(__half2*)&stash[nt][1]);
        __half2 w0 = __float22half2_rn(
            make_float2(r0.x + o[nt][0] * inv0, r0.y + o[nt][1] * inv0));
        __half2 w1 = __float22half2_rn(
            make_float2(r1.x + o[nt][2] * inv1, r1.y + o[nt][3] * inv1));
        *(__half2*)(Outh + (size_t)row0 * DIM + col) = w0;
        *(__half2*)(Outh + (size_t)row1 * DIM + col) = w1;
    }
}

// ---------------- launch ----------------
extern "C" void kernel_launch(void* const* d_in, const int* in_sizes, int n_in,
                              void* d_out, int out_size)
{
    const float* hs   = (const float*)d_in[0];
    const float* rhs  = (const float*)d_in[1];
    const float* rcos = (const float*)d_in[2];
    const float* rsin = (const float*)d_in[3];
    const float* Wq   = (const float*)d_in[4];
    const float* bq   = (const float*)d_in[5];
    const float* Wk   = (const float*)d_in[6];
    const float* bk   = (const float*)d_in[7];
    const float* Wv   = (const float*)d_in[8];
    const float* bv   = (const float*)d_in[9];
    const float* Wkr  = (const float*)d_in[10];
    const float* bkr  = (const float*)d_in[11];
    const float* Wvr  = (const float*)d_in[12];
    const float* bvr  = (const float*)d_in[13];
    const float* Wo   = (const float*)d_in[14];
    const float* bo   = (const float*)d_in[15];
    const float* gq   = (const float*)d_in[16];
    const float* gk   = (const float*)d_in[17];
    float* out = (float*)d_out;

    float *qlin, *klin, *vlin, *krlin, *vrlin;
    __half *hsh, *rhsh, *wth, *qh, *qroph, *kh, *vth, *krh, *vrth, *attnh;
    cudaGetSymbolAddress((void**)&qlin,  g_qlin);
    cudaGetSymbolAddress((void**)&klin,  g_klin);
    cudaGetSymbolAddress((void**)&vlin,  g_vlin);
    cudaGetSymbolAddress((void**)&krlin, g_krlin);
    cudaGetSymbolAddress((void**)&vrlin, g_vrlin);
    cudaGetSymbolAddress((void**)&hsh,   g_hsh);
    cudaGetSymbolAddress((void**)&rhsh,  g_rhsh);
    cudaGetSymbolAddress((void**)&wth,   g_wth);
    cudaGetSymbolAddress((void**)&qh,    g_qh);
    cudaGetSymbolAddress((void**)&qroph, g_qroph);
    cudaGetSymbolAddress((void**)&kh,    g_kh);
    cudaGetSymbolAddress((void**)&vth,   g_vth);
    cudaGetSymbolAddress((void**)&krh,   g_krh);
    cudaGetSymbolAddress((void**)&vrth,  g_vrth);
    cudaGetSymbolAddress((void**)&attnh, g_attnh);

    cudaFuncSetAttribute(attn_fused,
                         cudaFuncAttributeMaxDynamicSharedMemorySize, ATT_SMEM);
    cudaFuncSetAttribute(gemm_f16_multi<4>,
                         cudaFuncAttributeMaxDynamicSharedMemorySize, GEMM_SMEM_M);
    cudaFuncSetAttribute(gemm_f16_multi<2>,
                         cudaFuncAttributeMaxDynamicSharedMemorySize, GEMM_SMEM_R);

    const float scale = 0.08838834764831845f;  // 1/sqrt(128)
    const size_t NW = (size_t)DIM * DIM;
    const int NT = T_LEN * DIM, NR = TR_LEN * DIM;
    const int CB = 256 * 4;

    // ---- activations -> half ----
    cvt_h<<<(NT + CB - 1) / CB, 256>>>(hs,  hsh,  NT, 1.f);
    cvt_h<<<(NR + CB - 1) / CB, 256>>>(rhs, rhsh, NR, 1.f);

    // ---- all 6 weight transposes in one launch ----
    Src6 wsrc;
    wsrc.p[0] = Wq; wsrc.p[1] = Wk; wsrc.p[2] = Wv;
    wsrc.p[3] = Wkr; wsrc.p[4] = Wvr; wsrc.p[5] = Wo;
    transpose6_h<<<dim3(DIM / 32, DIM / 32, 6), dim3(32, 8)>>>(wsrc, wth);

    // ---- projections: main QKV in one launch, ref KV in one launch ----
    Gemm3 pm;
    pm.W[0] = wth + 0 * NW; pm.b[0] = bq; pm.C[0] = qlin;
    pm.W[1] = wth + 1 * NW; pm.b[1] = bk; pm.C[1] = klin;
    pm.W[2] = wth + 2 * NW; pm.b[2] = bv; pm.C[2] = vlin;
    gemm_f16_multi<4><<<dim3(36, T_LEN / 128), 256, GEMM_SMEM_M>>>(hsh, pm);

    Gemm3 pr;
    pr.W[0] = wth + 3 * NW; pr.b[0] = bkr; pr.C[0] = krlin;
    pr.W[1] = wth + 4 * NW; pr.b[1] = bvr; pr.C[1] = vrlin;
    pr.W[2] = wth + 3 * NW; pr.b[2] = bkr; pr.C[2] = krlin;  // unused slot
    gemm_f16_multi<2><<<dim3(24, TR_LEN / 64), 256, GEMM_SMEM_R>>>(rhsh, pr);

    // ---- V -> transposed half [h*DH+d][t] ----
    dim3 tb(32, 8);
    transpose_h<<<dim3(DIM / 32, T_LEN / 32),  tb>>>(vlin,  vth,  T_LEN,  DIM);
    transpose_h<<<dim3(DIM / 32, TR_LEN / 32), tb>>>(vrlin, vrth, TR_LEN, DIM);

    // ---- RMSNorms ----
    rmsnorm_kernel<<<T_LEN, 256>>>(qlin,  gq, qlin, qh, scale);
    rmsnorm_kernel<<<T_LEN, 256>>>(klin,  gk, klin, nullptr, 1.f);
    rmsnorm_kernel<<<TR_LEN, 256>>>(krlin, gk, nullptr, krh, 1.f);

    // ---- RoPE -> half ----
    int rope_blocks = (T_LEN * (DIM / 2) + 255) / 256;
    rope_kernel<<<rope_blocks, 256>>>(qlin, qroph, rcos, rsin, scale);
    rope_kernel<<<rope_blocks, 256>>>(klin, kh,    rcos, rsin, 1.f);

    // ---- fused attention (ref + main), half output ----
    dim3 attn_grid(T_LEN / 128, NH);  // (32, 12)
    attn_fused<<<attn_grid, 256, ATT_SMEM>>>(qh, krh, vrth, TR_LEN,
                                             qroph, kh, vth, T_LEN, attnh);

    // ---- output projection ----
    Gemm3 po;
    po.W[0] = wth + 5 * NW; po.b[0] = bo; po.C[0] = out;
    po.W[1] = po.W[0]; po.b[1] = po.b[0]; po.C[1] = out;  // unused
    po.W[2] = po.W[0]; po.b[2] = po.b[0]; po.C[2] = out;  // unused
    gemm_f16_multi<4><<<dim3(12, T_LEN / 128), 256, GEMM_SMEM_M>>>(attnh, po);
}

// round 10
// speedup vs baseline: 1.4000x; 1.4000x over previous
#include <cuda_runtime.h>
#include <cuda_fp16.h>
#include <math.h>

#define T_LEN 4096
#define TR_LEN 1024
#define DIM 1536
#define NH 12
#define DH 128

// ---------------- scratch (device globals; no allocation allowed) ----------------
__device__ float g_qlin[T_LEN * DIM];
__device__ float g_klin[T_LEN * DIM];
__device__ float g_vlin[T_LEN * DIM];
__device__ float g_krlin[TR_LEN * DIM];
__device__ float g_vrlin[TR_LEN * DIM];

__device__ __half g_hsh[T_LEN * DIM];
__device__ __half g_rhsh[TR_LEN * DIM];
__device__ __half g_wth[6 * DIM * DIM];   // Wq,Wk,Wv,Wkr,Wvr,Wo transposed [n][k]
__device__ __half g_qh[T_LEN * DIM];      // rms(q)*scale (unroped, ref attn)
__device__ __half g_qroph[T_LEN * DIM];   // rope(rms(q))*scale
__device__ __half g_kh[T_LEN * DIM];      // rope(rms(k))
__device__ __half g_vth[DIM * T_LEN];     // V transposed [h*DH + d][t]
__device__ __half g_krh[TR_LEN * DIM];    // rms(ref k)
__device__ __half g_vrth[DIM * TR_LEN];   // ref V transposed
__device__ __half g_attnh[T_LEN * DIM];   // attention output (half, fused ref+main)

// ---------------- PTX helpers ----------------
__device__ __forceinline__ void mma_f16(float& c0, float& c1, float& c2, float& c3,
                                        unsigned a0, unsigned a1, unsigned a2, unsigned a3,
                                        unsigned b0, unsigned b1) {
    asm volatile(
        "mma.sync.aligned.m16n8k16.row.col.f32.f16.f16.f32 "
        "{%0,%1,%2,%3},{%4,%5,%6,%7},{%8,%9},{%0,%1,%2,%3};"
        : "+f"(c0), "+f"(c1), "+f"(c2), "+f"(c3)
        : "r"(a0), "r"(a1), "r"(a2), "r"(a3), "r"(b0), "r"(b1));
}
__device__ __forceinline__ void ldsm4(unsigned& r0, unsigned& r1, unsigned& r2, unsigned& r3,
                                      unsigned addr) {
    asm volatile("ldmatrix.sync.aligned.m8n8.x4.shared.b16 {%0,%1,%2,%3}, [%4];"
                 : "=r"(r0), "=r"(r1), "=r"(r2), "=r"(r3) : "r"(addr));
}
__device__ __forceinline__ void cp16(void* dst_smem, const void* src) {
    unsigned s = (unsigned)__cvta_generic_to_shared(dst_smem);
    asm volatile("cp.async.cg.shared.global [%0], [%1], 16;" :: "r"(s), "l"(src));
}
__device__ __forceinline__ void cp_commit() { asm volatile("cp.async.commit_group;"); }
__device__ __forceinline__ void cp_wait1()  { asm volatile("cp.async.wait_group 1;"); }
__device__ __forceinline__ void cp_wait0()  { asm volatile("cp.async.wait_group 0;"); }
__device__ __forceinline__ unsigned h2u(__half2 h) { return *(unsigned*)&h; }

// ---------------- float -> half conversion ----------------
__global__ __launch_bounds__(256) void cvt_h(
    const float* __restrict__ in, __half* __restrict__ out, int n, float scale)
{
    int i4 = (blockIdx.x * 256 + threadIdx.x) * 4;
    if (i4 >= n) return;
    float4 v = *(const float4*)(in + i4);
    __half2 h0 = __float22half2_rn(make_float2(v.x * scale, v.y * scale));
    __half2 h1 = __float22half2_rn(make_float2(v.z * scale, v.w * scale));
    uint2 u; u.x = h2u(h0); u.y = h2u(h1);
    *(uint2*)(out + i4) = u;
}

// ---------------- tiled transpose: float [R][C] -> half [C][R] ----------------
__global__ __launch_bounds__(256) void transpose_h(
    const float* __restrict__ in, __half* __restrict__ out, int R, int C)
{
    __shared__ float t[32][33];
    int c0 = blockIdx.x * 32, r0 = blockIdx.y * 32;
    int tx = threadIdx.x, ty = threadIdx.y;
#pragma unroll
    for (int yy = 0; yy < 32; yy += 8)
        t[ty + yy][tx] = in[(size_t)(r0 + ty + yy) * C + c0 + tx];
    __syncthreads();
#pragma unroll
    for (int yy = 0; yy < 32; yy += 8)
        out[(size_t)(c0 + ty + yy) * R + r0 + tx] = __float2half_rn(t[tx][ty + yy]);
}

// 6 weight transposes in one launch (z picks the matrix)
struct Src6 { const float* p[6]; };
__global__ __launch_bounds__(256) void transpose6_h(Src6 s, __half* __restrict__ dstbase)
{
    __shared__ float t[32][33];
    const float* in = s.p[blockIdx.z];
    __half* out = dstbase + (size_t)blockIdx.z * DIM * DIM;
    int c0 = blockIdx.x * 32, r0 = blockIdx.y * 32;
    int tx = threadIdx.x, ty = threadIdx.y;
#pragma unroll
    for (int yy = 0; yy < 32; yy += 8)
        t[ty + yy][tx] = in[(size_t)(r0 + ty + yy) * DIM + c0 + tx];
    __syncthreads();
#pragma unroll
    for (int yy = 0; yy < 32; yy += 8)
        out[(size_t)(c0 + ty + yy) * DIM + r0 + tx] = __float2half_rn(t[tx][ty + yy]);
}

// ================= GEMM (fp16 mma, 3-stage cp.async), up to 3 outputs per launch =========
// R8-proven inner loop (scalar LDS fragments, ktile=32, pitch 20u) + 3-stage pipeline.
#define GP 20   // smem pitch in unsigned (40 halves)
struct Gemm3 { const __half* W[3]; const float* b[3]; float* C[3]; };

template<int MT>
__global__ __launch_bounds__(256) void gemm_f16_multi(
    const __half* __restrict__ A, Gemm3 p)
{
    constexpr int TM = MT * 32;
    constexpr int ASTG = TM * GP;     // A stage size (u)
    constexpr int BSTG = 128 * GP;    // B stage size (u)
    constexpr int OFF_B = 3 * ASTG;

    extern __shared__ unsigned smu[];
    const int which = blockIdx.x / 12;
    const __half* Wt = p.W[which];
    const float* bias = p.b[which];
    float* C = p.C[which];

    const int bm = blockIdx.y * TM;
    const int bn = (blockIdx.x % 12) * 128;
    const int tid = threadIdx.x;
    const int lane = tid & 31, warp = tid >> 5;
    const int g = lane >> 2, l = lane & 3;
    const int wm = (warp >> 2) * (MT * 16);
    const int wn = (warp & 3) * 32;

    float c[MT][4][4];
#pragma unroll
    for (int mt = 0; mt < MT; mt++)
#pragma unroll
        for (int nt = 0; nt < 4; nt++)
#pragma unroll
            for (int i = 0; i < 4; i++) c[mt][nt][i] = 0.f;

    auto issue = [&](int kt, int stg) {
        unsigned* Au = smu + stg * ASTG;
        unsigned* Bu = smu + OFF_B + stg * BSTG;
        const int k0 = kt * 32;
#pragma unroll
        for (int u = 0; u < MT / 2; u++) {          // A: TM rows x 4 cp16
            int i = tid + u * 256;
            int r = i >> 2, c4 = i & 3;
            cp16(Au + r * GP + c4 * 4, A + (size_t)(bm + r) * DIM + k0 + c4 * 8);
        }
#pragma unroll
        for (int u = 0; u < 2; u++) {               // B: 128 rows x 4 cp16
            int i = tid + u * 256;
            int r = i >> 2, c4 = i & 3;
            cp16(Bu + r * GP + c4 * 4, Wt + (size_t)(bn + r) * DIM + k0 + c4 * 8);
        }
        cp_commit();
    };

    const int NKT = DIM / 32;  // 48
    issue(0, 0);
    issue(1, 1);
    for (int kt = 0; kt < NKT; kt++) {
        int stg = kt % 3;
        if (kt + 1 < NKT) cp_wait1();   // tile kt landed; tile kt+1 may be in flight
        else              cp_wait0();
        __syncthreads();                // stage (kt+2)%3 fully consumed (at iter kt-1)
        if (kt + 2 < NKT) issue(kt + 2, (kt + 2) % 3);

        const unsigned* As = smu + stg * ASTG;
        const unsigned* Bs = smu + OFF_B + stg * BSTG;

#pragma unroll
        for (int kk = 0; kk < 2; kk++) {
            unsigned a[MT][4];
#pragma unroll
            for (int mt = 0; mt < MT; mt++) {
                int row = wm + mt * 16;
                a[mt][0] = As[(row + g)     * GP + kk * 8 + l];
                a[mt][1] = As[(row + g + 8) * GP + kk * 8 + l];
                a[mt][2] = As[(row + g)     * GP + kk * 8 + l + 4];
                a[mt][3] = As[(row + g + 8) * GP + kk * 8 + l + 4];
            }
            unsigned b[4][2];
#pragma unroll
            for (int nt = 0; nt < 4; nt++) {
                int col = wn + nt * 8;
                b[nt][0] = Bs[(col + g) * GP + kk * 8 + l];
                b[nt][1] = Bs[(col + g) * GP + kk * 8 + l + 4];
            }
#pragma unroll
            for (int mt = 0; mt < MT; mt++)
#pragma unroll
                for (int nt = 0; nt < 4; nt++)
                    mma_f16(c[mt][nt][0], c[mt][nt][1], c[mt][nt][2], c[mt][nt][3],
                            a[mt][0], a[mt][1], a[mt][2], a[mt][3],
                            b[nt][0], b[nt][1]);
        }
    }

#pragma unroll
    for (int mt = 0; mt < MT; mt++) {
#pragma unroll
        for (int nt = 0; nt < 4; nt++) {
            int row = bm + wm + mt * 16 + g;
            int col = bn + wn + nt * 8 + 2 * l;
            float b0 = bias[col], b1 = bias[col + 1];
            C[(size_t)row * DIM + col]           = c[mt][nt][0] + b0;
            C[(size_t)row * DIM + col + 1]       = c[mt][nt][1] + b1;
            C[(size_t)(row + 8) * DIM + col]     = c[mt][nt][2] + b0;
            C[(size_t)(row + 8) * DIM + col + 1] = c[mt][nt][3] + b1;
        }
    }
}

#define GEMM_SMEM_M ((3 * 128 * GP + 3 * 128 * GP) * 4)   // 61440 B
#define GEMM_SMEM_R ((3 * 64 * GP + 3 * 128 * GP) * 4)    // 46080 B

// ---------------- RMSNorm (plain): optional half out ----------------
__global__ __launch_bounds__(256) void rmsnorm_kernel(
    const float* __restrict__ x, const float* __restrict__ g,
    __half* __restrict__ out_b, float bscale)
{
    const int row = blockIdx.x;
    const float* xr = x + (size_t)row * DIM;
    const int tid = threadIdx.x;

    float ss = 0.f;
    for (int i = tid; i < DIM; i += 256) {
        float v = xr[i];
        ss += v * v;
    }
#pragma unroll
    for (int off = 16; off; off >>= 1) ss += __shfl_xor_sync(0xffffffffu, ss, off);

    __shared__ float wsum[8];
    __shared__ float inv_s;
    if ((tid & 31) == 0) wsum[tid >> 5] = ss;
    __syncthreads();
    if (tid == 0) {
        float t = 0.f;
#pragma unroll
        for (int w = 0; w < 8; w++) t += wsum[w];
        inv_s = rsqrtf(t / (float)DIM + 1e-6f);
    }
    __syncthreads();
    float inv = inv_s;
    for (int i = tid; i < DIM; i += 256) {
        float v = xr[i] * inv * g[i];
        out_b[(size_t)row * DIM + i] = __float2half_rn(v * bscale);
    }
}

// ---------------- Fused RMSNorm + RoPE: emits optional unroped half + roped half ----------------
__global__ __launch_bounds__(256) void rmsrope_kernel(
    const float* __restrict__ x, const float* __restrict__ g,
    const float* __restrict__ rc, const float* __restrict__ rs,
    __half* __restrict__ out_plain, __half* __restrict__ out_rope, float scale)
{
    const int row = blockIdx.x;
    const float* xr = x + (size_t)row * DIM;
    const int tid = threadIdx.x;

    float ss = 0.f;
    for (int i = tid; i < DIM; i += 256) {
        float v = xr[i];
        ss += v * v;
    }
#pragma unroll
    for (int off = 16; off; off >>= 1) ss += __shfl_xor_sync(0xffffffffu, ss, off);

    __shared__ float wsum[8];
    __shared__ float inv_s;
    if ((tid & 31) == 0) wsum[tid >> 5] = ss;
    __syncthreads();
    if (tid == 0) {
        float t = 0.f;
#pragma unroll
        for (int w = 0; w < 8; w++) t += wsum[w];
        inv_s = rsqrtf(t / (float)DIM + 1e-6f);
    }
    __syncthreads();
    float inv = inv_s;

    for (int p = tid; p < DIM / 2; p += 256) {
        int i = p & 63;                   // pair index within head
        int d = (p >> 6) * DH + 2 * i;    // element offset within row
        float e = xr[d]     * inv * g[d];
        float o = xr[d + 1] * inv * g[d + 1];
        if (out_plain)
            *(__half2*)(out_plain + (size_t)row * DIM + d) =
                __float22half2_rn(make_float2(e * scale, o * scale));
        float c = rc[row * (DH / 2) + i];
        float s = rs[row * (DH / 2) + i];
        *(__half2*)(out_rope + (size_t)row * DIM + d) =
            __float22half2_rn(make_float2((e * c - o * s) * scale, (e * s + o * c) * scale));
    }
}

// ================= Fused flash attention (ref + main in one kernel) — R8-proven =================
#define AQ 68
#define ATT_Q  0
#define ATT_K0 (128 * AQ)
#define ATT_K1 (ATT_K0 + 128 * AQ)
#define ATT_V0 (ATT_K1 + 128 * AQ)
#define ATT_V1 (ATT_V0 + 128 * AQ)
#define ATT_SMEM ((ATT_V1 + 128 * AQ) * 4)   // 174080 B

__global__ __launch_bounds__(256) void attn_fused(
    const __half* __restrict__ Q0, const __half* __restrict__ K0p,
    const __half* __restrict__ V0p, int Tk0,
    const __half* __restrict__ Q1, const __half* __restrict__ K1p,
    const __half* __restrict__ V1p, int Tk1,
    __half* __restrict__ Outh)
{
    extern __shared__ unsigned smu[];

    const int h = blockIdx.y;
    const int q0 = blockIdx.x * 128;
    const int tid = threadIdx.x;
    const int lane = tid & 31, warp = tid >> 5;
    const int g = lane >> 2, l = lane & 3;
    const unsigned sbase = (unsigned)__cvta_generic_to_shared(smu);

    const int ql_row = lane & 15;
    const unsigned ql_addr = sbase + (ATT_Q + (warp * 16 + ql_row) * AQ
                                      + ((lane & 16) ? 4 : 0)) * 4;
    const int bl_row  = (lane & 7) + ((lane & 16) ? 8 : 0);
    const int bl_colu = (lane & 8) ? 4 : 0;

    auto issue_Q = [&](const __half* Qp) {
#pragma unroll
        for (int u = 0; u < 8; u++) {
            int i = tid + u * 256;
            int r = i >> 4, c4 = i & 15;
            cp16(smu + ATT_Q + r * AQ + c4 * 4,
                 Qp + (size_t)(q0 + r) * DIM + h * DH + c4 * 8);
        }
    };
    auto issue_tile = [&](const __half* Kp, const __half* Vt, int Tk, int t, int buf) {
        unsigned* Ku = smu + (buf ? ATT_K1 : ATT_K0);
        unsigned* Vu = smu + (buf ? ATT_V1 : ATT_V0);
        const size_t krow = (size_t)(t * 128) * DIM + h * DH;
#pragma unroll
        for (int u = 0; u < 8; u++) {
            int i = tid + u * 256;
            int r = i >> 4, c4 = i & 15;
            cp16(Ku + r * AQ + c4 * 4, Kp + krow + (size_t)r * DIM + c4 * 8);
        }
#pragma unroll
        for (int u = 0; u < 8; u++) {
            int i = tid + u * 256;
            int r = i >> 4, c4 = i & 15;
            cp16(Vu + r * AQ + c4 * 4,
                 Vt + (size_t)(h * DH + r) * Tk + t * 128 + c4 * 8);
        }
        cp_commit();
    };

    float o[16][4];
    float m0, m1, l0, l1;
    unsigned qa[8][4];
    unsigned stash[16][2];

#pragma unroll
    for (int ph = 0; ph < 2; ph++) {
        const __half* Qp = ph ? Q1 : Q0;
        const __half* Kp = ph ? K1p : K0p;
        const __half* Vp = ph ? V1p : V0p;
        const int Tk = ph ? Tk1 : Tk0;
        const int ntiles = Tk / 128;

#pragma unroll
        for (int nt = 0; nt < 16; nt++)
#pragma unroll
            for (int i = 0; i < 4; i++) o[nt][i] = 0.f;
        m0 = m1 = -1e30f;
        l0 = l1 = 0.f;

        issue_Q(Qp);
        issue_tile(Kp, Vp, Tk, 0, 0);

        for (int t = 0; t < ntiles; t++) {
            int buf = t & 1;
            cp_wait0();
            __syncthreads();
            if (t + 1 < ntiles) issue_tile(Kp, Vp, Tk, t + 1, buf ^ 1);

            if (t == 0) {
#pragma unroll
                for (int kk = 0; kk < 8; kk++)
                    ldsm4(qa[kk][0], qa[kk][1], qa[kk][2], qa[kk][3], ql_addr + kk * 32);
            }

            const unsigned koff = sbase + (buf ? ATT_K1 : ATT_K0) * 4;
            const unsigned voff = sbase + (buf ? ATT_V1 : ATT_V0) * 4;

#pragma unroll
            for (int st = 0; st < 2; st++) {
                float s[8][4];
#pragma unroll
                for (int nt = 0; nt < 8; nt++)
#pragma unroll
                    for (int i = 0; i < 4; i++) s[nt][i] = 0.f;

#pragma unroll
                for (int kk = 0; kk < 8; kk++) {
                    unsigned kb[4][4];
#pragma unroll
                    for (int j = 0; j < 4; j++)
                        ldsm4(kb[j][0], kb[j][1], kb[j][2], kb[j][3],
                              koff + ((st * 64 + j * 16 + bl_row) * AQ + kk * 8 + bl_colu) * 4);
#pragma unroll
                    for (int j = 0; j < 4; j++) {
                        mma_f16(s[2*j][0], s[2*j][1], s[2*j][2], s[2*j][3],
                                qa[kk][0], qa[kk][1], qa[kk][2], qa[kk][3], kb[j][0], kb[j][1]);
                        mma_f16(s[2*j+1][0], s[2*j+1][1], s[2*j+1][2], s[2*j+1][3],
                                qa[kk][0], qa[kk][1], qa[kk][2], qa[kk][3], kb[j][2], kb[j][3]);
                    }
                }

                float tm0 = -1e30f, tm1 = -1e30f;
#pragma unroll
                for (int nt = 0; nt < 8; nt++) {
                    tm0 = fmaxf(tm0, fmaxf(s[nt][0], s[nt][1]));
                    tm1 = fmaxf(tm1, fmaxf(s[nt][2], s[nt][3]));
                }
                tm0 = fmaxf(tm0, __shfl_xor_sync(0xffffffffu, tm0, 1));
                tm0 = fmaxf(tm0, __shfl_xor_sync(0xffffffffu, tm0, 2));
                tm1 = fmaxf(tm1, __shfl_xor_sync(0xffffffffu, tm1, 1));
                tm1 = fmaxf(tm1, __shfl_xor_sync(0xffffffffu, tm1, 2));
                float mn0 = fmaxf(m0, tm0), mn1 = fmaxf(m1, tm1);
                float al0 = __expf(m0 - mn0), al1 = __expf(m1 - mn1);
                m0 = mn0; m1 = mn1;

                unsigned pa[4][4];
                float sum0 = 0.f, sum1 = 0.f;
#pragma unroll
                for (int nt = 0; nt < 8; nt++) {
                    float p0 = __expf(s[nt][0] - mn0);
                    float p1 = __expf(s[nt][1] - mn0);
                    float p2 = __expf(s[nt][2] - mn1);
                    float p3 = __expf(s[nt][3] - mn1);
                    sum0 += p0 + p1;
                    sum1 += p2 + p3;
                    unsigned lo = h2u(__float22half2_rn(make_float2(p0, p1)));
                    unsigned hi = h2u(__float22half2_rn(make_float2(p2, p3)));
                    int kt = nt >> 1;
                    if ((nt & 1) == 0) { pa[kt][0] = lo; pa[kt][1] = hi; }
                    else               { pa[kt][2] = lo; pa[kt][3] = hi; }
                }
                sum0 += __shfl_xor_sync(0xffffffffu, sum0, 1);
                sum0 += __shfl_xor_sync(0xffffffffu, sum0, 2);
                sum1 += __shfl_xor_sync(0xffffffffu, sum1, 1);
                sum1 += __shfl_xor_sync(0xffffffffu, sum1, 2);
                l0 = l0 * al0 + sum0;
                l1 = l1 * al1 + sum1;
#pragma unroll
                for (int nt = 0; nt < 16; nt++) {
                    o[nt][0] *= al0; o[nt][1] *= al0;
                    o[nt][2] *= al1; o[nt][3] *= al1;
                }

#pragma unroll
                for (int kt = 0; kt < 4; kt++) {
                    unsigned vb[8][4];
#pragma unroll
                    for (int j = 0; j < 8; j++)
                        ldsm4(vb[j][0], vb[j][1], vb[j][2], vb[j][3],
                              voff + ((j * 16 + bl_row) * AQ + st * 32 + kt * 8 + bl_colu) * 4);
#pragma unroll
                    for (int j = 0; j < 8; j++) {
                        mma_f16(o[2*j][0], o[2*j][1], o[2*j][2], o[2*j][3],
                                pa[kt][0], pa[kt][1], pa[kt][2], pa[kt][3], vb[j][0], vb[j][1]);
                        mma_f16(o[2*j+1][0], o[2*j+1][1], o[2*j+1][2], o[2*j+1][3],
                                pa[kt][0], pa[kt][1], pa[kt][2], pa[kt][3], vb[j][2], vb[j][3]);
                    }
                }
            }
        }

        if (ph == 0) {
            float inv0 = 1.f / l0, inv1 = 1.f / l1;
#pragma unroll
            for (int nt = 0; nt < 16; nt++) {
                stash[nt][0] = h2u(__float22half2_rn(
                    make_float2(o[nt][0] * inv0, o[nt][1] * inv0)));
                stash[nt][1] = h2u(__float22half2_rn(
                    make_float2(o[nt][2] * inv1, o[nt][3] * inv1)));
            }
        }
    }

    float inv0 = 1.f / l0, inv1 = 1.f / l1;
    int row0 = q0 + warp * 16 + g;
    int row1 = row0 + 8;
#pragma unroll
    for (int nt = 0; nt < 16; nt++) {
        int col = h * DH + nt * 8 + 2 * l;
        float2 r0 = __half22float2(*(__half2*)&stash[nt][0]);
        float2 r1 = __half22float2(*(__half2*)&stash[nt][1]);
        __half2 w0 = __float22half2_rn(
            make_float2(r0.x + o[nt][0] * inv0, r0.y + o[nt][1] * inv0));
        __half2 w1 = __float22half2_rn(
            make_float2(r1.x + o[nt][2] * inv1, r1.y + o[nt][3] * inv1));
        *(__half2*)(Outh + (size_t)row0 * DIM + col) = w0;
        *(__half2*)(Outh + (size_t)row1 * DIM + col) = w1;
    }
}

// ---------------- launch ----------------
extern "C" void kernel_launch(void* const* d_in, const int* in_sizes, int n_in,
                              void* d_out, int out_size)
{
    const float* hs   = (const float*)d_in[0];
    const float* rhs  = (const float*)d_in[1];
    const float* rcos = (const float*)d_in[2];
    const float* rsin = (const float*)d_in[3];
    const float* Wq   = (const float*)d_in[4];
    const float* bq   = (const float*)d_in[5];
    const float* Wk   = (const float*)d_in[6];
    const float* bk   = (const float*)d_in[7];
    const float* Wv   = (const float*)d_in[8];
    const float* bv   = (const float*)d_in[9];
    const float* Wkr  = (const float*)d_in[10];
    const float* bkr  = (const float*)d_in[11];
    const float* Wvr  = (const float*)d_in[12];
    const float* bvr  = (const float*)d_in[13];
    const float* Wo   = (const float*)d_in[14];
    const float* bo   = (const float*)d_in[15];
    const float* gq   = (const float*)d_in[16];
    const float* gk   = (const float*)d_in[17];
    float* out = (float*)d_out;

    float *qlin, *klin, *vlin, *krlin, *vrlin;
    __half *hsh, *rhsh, *wth, *qh, *qroph, *kh, *vth, *krh, *vrth, *attnh;
    cudaGetSymbolAddress((void**)&qlin,  g_qlin);
    cudaGetSymbolAddress((void**)&klin,  g_klin);
    cudaGetSymbolAddress((void**)&vlin,  g_vlin);
    cudaGetSymbolAddress((void**)&krlin, g_krlin);
    cudaGetSymbolAddress((void**)&vrlin, g_vrlin);
    cudaGetSymbolAddress((void**)&hsh,   g_hsh);
    cudaGetSymbolAddress((void**)&rhsh,  g_rhsh);
    cudaGetSymbolAddress((void**)&wth,   g_wth);
    cudaGetSymbolAddress((void**)&qh,    g_qh);
    cudaGetSymbolAddress((void**)&qroph, g_qroph);
    cudaGetSymbolAddress((void**)&kh,    g_kh);
    cudaGetSymbolAddress((void**)&vth,   g_vth);
    cudaGetSymbolAddress((void**)&krh,   g_krh);
    cudaGetSymbolAddress((void**)&vrth,  g_vrth);
    cudaGetSymbolAddress((void**)&attnh, g_attnh);

    cudaFuncSetAttribute(attn_fused,
                         cudaFuncAttributeMaxDynamicSharedMemorySize, ATT_SMEM);
    cudaFuncSetAttribute(gemm_f16_multi<4>,
                         cudaFuncAttributeMaxDynamicSharedMemorySize, GEMM_SMEM_M);
    cudaFuncSetAttribute(gemm_f16_multi<2>,
                         cudaFuncAttributeMaxDynamicSharedMemorySize, GEMM_SMEM_R);

    const float scale = 0.08838834764831845f;  // 1/sqrt(128)
    const size_t NW = (size_t)DIM * DIM;
    const int NT = T_LEN * DIM, NR = TR_LEN * DIM;
    const int CB = 256 * 4;

    // ---- activations -> half ----
    cvt_h<<<(NT + CB - 1) / CB, 256>>>(hs,  hsh,  NT, 1.f);
    cvt_h<<<(NR + CB - 1) / CB, 256>>>(rhs, rhsh, NR, 1.f);

    // ---- all 6 weight transposes in one launch ----
    Src6 wsrc;
    wsrc.p[0] = Wq; wsrc.p[1] = Wk; wsrc.p[2] = Wv;
    wsrc.p[3] = Wkr; wsrc.p[4] = Wvr; wsrc.p[5] = Wo;
    transpose6_h<<<dim3(DIM / 32, DIM / 32, 6), dim3(32, 8)>>>(wsrc, wth);

    // ---- projections: main QKV in one launch, ref KV in one launch ----
    Gemm3 pm;
    pm.W[0] = wth + 0 * NW; pm.b[0] = bq; pm.C[0] = qlin;
    pm.W[1] = wth + 1 * NW; pm.b[1] = bk; pm.C[1] = klin;
    pm.W[2] = wth + 2 * NW; pm.b[2] = bv; pm.C[2] = vlin;
    gemm_f16_multi<4><<<dim3(36, T_LEN / 128), 256, GEMM_SMEM_M>>>(hsh, pm);

    Gemm3 pr;
    pr.W[0] = wth + 3 * NW; pr.b[0] = bkr; pr.C[0] = krlin;
    pr.W[1] = wth + 4 * NW; pr.b[1] = bvr; pr.C[1] = vrlin;
    pr.W[2] = wth + 3 * NW; pr.b[2] = bkr; pr.C[2] = krlin;  // unused slot
    gemm_f16_multi<2><<<dim3(24, TR_LEN / 64), 256, GEMM_SMEM_R>>>(rhsh, pr);

    // ---- V -> transposed half [h*DH+d][t] ----
    dim3 tb(32, 8);
    transpose_h<<<dim3(DIM / 32, T_LEN / 32),  tb>>>(vlin,  vth,  T_LEN,  DIM);
    transpose_h<<<dim3(DIM / 32, TR_LEN / 32), tb>>>(vrlin, vrth, TR_LEN, DIM);

    // ---- fused RMSNorm+RoPE (q: both unroped & roped; k: roped only), ref k plain ----
    rmsrope_kernel<<<T_LEN, 256>>>(qlin, gq, rcos, rsin, qh, qroph, scale);
    rmsrope_kernel<<<T_LEN, 256>>>(klin, gk, rcos, rsin, nullptr, kh, 1.f);
    rmsnorm_kernel<<<TR_LEN, 256>>>(krlin, gk, krh, 1.f);

    // ---- fused attention (ref + main), half output ----
    dim3 attn_grid(T_LEN / 128, NH);  // (32, 12)
    attn_fused<<<attn_grid, 256, ATT_SMEM>>>(qh, krh, vrth, TR_LEN,
                                             qroph, kh, vth, T_LEN, attnh);

    // ---- output projection ----
    Gemm3 po;
    po.W[0] = wth + 5 * NW; po.b[0] = bo; po.C[0] = out;
    po.W[1] = po.W[0]; po.b[1] = po.b[0]; po.C[1] = out;  // unused
    po.W[2] = po.W[0]; po.b[2] = po.b[0]; po.C[2] = out;  // unused
    gemm_f16_multi<4><<<dim3(12, T_LEN / 128), 256, GEMM_SMEM_M>>>(attnh, po);
}

// round 12
// speedup vs baseline: 1.4670x; 1.0478x over previous
#include <cuda_runtime.h>
#include <cuda_fp16.h>
#include <math.h>

#define T_LEN 4096
#define TR_LEN 1024
#define DIM 1536
#define NH 12
#define DH 128

// ---------------- scratch (device globals; no allocation allowed) ----------------
__device__ float g_qlin[T_LEN * DIM];
__device__ float g_klin[T_LEN * DIM];
__device__ float g_krlin[TR_LEN * DIM];

__device__ __half g_hsh[T_LEN * DIM];
__device__ __half g_rhsh[TR_LEN * DIM];
__device__ __half g_wth[6 * DIM * DIM];   // Wq,Wk,Wv,Wkr,Wvr,Wo transposed [n][k]
__device__ __half g_vh[T_LEN * DIM];      // V (half, row-major from GEMM)
__device__ __half g_vrh[TR_LEN * DIM];    // ref V (half, row-major)
__device__ __half g_qh[T_LEN * DIM];      // rms(q)*scale (unroped, ref attn)
__device__ __half g_qroph[T_LEN * DIM];   // rope(rms(q))*scale
__device__ __half g_kh[T_LEN * DIM];      // rope(rms(k))
__device__ __half g_vth[DIM * T_LEN];     // V transposed [h*DH + d][t]
__device__ __half g_krh[TR_LEN * DIM];    // rms(ref k)
__device__ __half g_vrth[DIM * TR_LEN];   // ref V transposed
__device__ __half g_attnh[T_LEN * DIM];   // attention output (half, fused ref+main)

// ---------------- PTX helpers ----------------
__device__ __forceinline__ void mma_f16(float& c0, float& c1, float& c2, float& c3,
                                        unsigned a0, unsigned a1, unsigned a2, unsigned a3,
                                        unsigned b0, unsigned b1) {
    asm volatile(
        "mma.sync.aligned.m16n8k16.row.col.f32.f16.f16.f32 "
        "{%0,%1,%2,%3},{%4,%5,%6,%7},{%8,%9},{%0,%1,%2,%3};"
        : "+f"(c0), "+f"(c1), "+f"(c2), "+f"(c3)
        : "r"(a0), "r"(a1), "r"(a2), "r"(a3), "r"(b0), "r"(b1));
}
__device__ __forceinline__ void ldsm4(unsigned& r0, unsigned& r1, unsigned& r2, unsigned& r3,
                                      unsigned addr) {
    asm volatile("ldmatrix.sync.aligned.m8n8.x4.shared.b16 {%0,%1,%2,%3}, [%4];"
                 : "=r"(r0), "=r"(r1), "=r"(r2), "=r"(r3) : "r"(addr));
}
__device__ __forceinline__ void cp16(void* dst_smem, const void* src) {
    unsigned s = (unsigned)__cvta_generic_to_shared(dst_smem);
    asm volatile("cp.async.cg.shared.global [%0], [%1], 16;" :: "r"(s), "l"(src));
}
__device__ __forceinline__ void cp_commit() { asm volatile("cp.async.commit_group;"); }
__device__ __forceinline__ void cp_wait0()  { asm volatile("cp.async.wait_group 0;"); }
__device__ __forceinline__ unsigned h2u(__half2 h) { return *(unsigned*)&h; }

// ---------------- float -> half conversion ----------------
__global__ __launch_bounds__(256) void cvt_h(
    const float* __restrict__ in, __half* __restrict__ out, int n, float scale)
{
    int i4 = (blockIdx.x * 256 + threadIdx.x) * 4;
    if (i4 >= n) return;
    float4 v = *(const float4*)(in + i4);
    __half2 h0 = __float22half2_rn(make_float2(v.x * scale, v.y * scale));
    __half2 h1 = __float22half2_rn(make_float2(v.z * scale, v.w * scale));
    uint2 u; u.x = h2u(h0); u.y = h2u(h1);
    *(uint2*)(out + i4) = u;
}

// ---------------- tiled transpose: half [R][C] -> half [C][R] ----------------
__global__ __launch_bounds__(256) void transpose_hh(
    const __half* __restrict__ in, __half* __restrict__ out, int R, int C)
{
    __shared__ float t[32][33];
    int c0 = blockIdx.x * 32, r0 = blockIdx.y * 32;
    int tx = threadIdx.x, ty = threadIdx.y;
#pragma unroll
    for (int yy = 0; yy < 32; yy += 8)
        t[ty + yy][tx] = __half2float(in[(size_t)(r0 + ty + yy) * C + c0 + tx]);
    __syncthreads();
#pragma unroll
    for (int yy = 0; yy < 32; yy += 8)
        out[(size_t)(c0 + ty + yy) * R + r0 + tx] = __float2half_rn(t[tx][ty + yy]);
}

// 6 weight transposes in one launch (z picks the matrix)
struct Src6 { const float* p[6]; };
__global__ __launch_bounds__(256) void transpose6_h(Src6 s, __half* __restrict__ dstbase)
{
    __shared__ float t[32][33];
    const float* in = s.p[blockIdx.z];
    __half* out = dstbase + (size_t)blockIdx.z * DIM * DIM;
    int c0 = blockIdx.x * 32, r0 = blockIdx.y * 32;
    int tx = threadIdx.x, ty = threadIdx.y;
#pragma unroll
    for (int yy = 0; yy < 32; yy += 8)
        t[ty + yy][tx] = in[(size_t)(r0 + ty + yy) * DIM + c0 + tx];
    __syncthreads();
#pragma unroll
    for (int yy = 0; yy < 32; yy += 8)
        out[(size_t)(c0 + ty + yy) * DIM + r0 + tx] = __float2half_rn(t[tx][ty + yy]);
}

// ================= GEMM (fp16 mma, R8-proven loop), up to 5 outputs per launch =========
// Flat grid: first nMain*384 blocks are main tiles (A=Am, M=4096: 32x12 tiles per output),
// remaining blocks are ref tiles (A=Ar, M=1024: 8x12 tiles per output).
// Per-slot float or half output (isHalf). 128x128 tile, ktile 32, 2-stage cp.async.
#define GP 20   // smem pitch in unsigned (40 halves)
struct GemmJob { const __half* W[5]; const float* b[5]; void* C[5]; int isHalf[5]; };

__global__ __launch_bounds__(256) void gemm_f16_j(
    const __half* __restrict__ Am, const __half* __restrict__ Ar,
    GemmJob p, int nMain)
{
    constexpr int OFF_A0 = 0;
    constexpr int OFF_A1 = 128 * GP;
    constexpr int OFF_B0 = 2 * 128 * GP;
    constexpr int OFF_B1 = OFF_B0 + 128 * GP;

    extern __shared__ unsigned smu[];
    const int x = blockIdx.x;
    const int mainTiles = nMain * 384;
    const __half* A;
    int which, tile;
    if (x < mainTiles) { which = x / 384; tile = x % 384; A = Am; }
    else { int r = x - mainTiles; which = nMain + r / 96; tile = r % 96; A = Ar; }

    const __half* Wt = p.W[which];
    const float* bias = p.b[which];
    const int bm = (tile / 12) * 128;
    const int bn = (tile % 12) * 128;
    const int tid = threadIdx.x;
    const int lane = tid & 31, warp = tid >> 5;
    const int g = lane >> 2, l = lane & 3;
    const int wm = (warp >> 2) * 64;
    const int wn = (warp & 3) * 32;

    float c[4][4][4];
#pragma unroll
    for (int mt = 0; mt < 4; mt++)
#pragma unroll
        for (int nt = 0; nt < 4; nt++)
#pragma unroll
            for (int i = 0; i < 4; i++) c[mt][nt][i] = 0.f;

    auto issue = [&](int kt, int buf) {
        unsigned* Au = smu + (buf ? OFF_A1 : OFF_A0);
        unsigned* Bu = smu + (buf ? OFF_B1 : OFF_B0);
        const int k0 = kt * 32;
#pragma unroll
        for (int u = 0; u < 2; u++) {
            int i = tid + u * 256;
            int r = i >> 2, c4 = i & 3;
            cp16(Au + r * GP + c4 * 4, A + (size_t)(bm + r) * DIM + k0 + c4 * 8);
        }
#pragma unroll
        for (int u = 0; u < 2; u++) {
            int i = tid + u * 256;
            int r = i >> 2, c4 = i & 3;
            cp16(Bu + r * GP + c4 * 4, Wt + (size_t)(bn + r) * DIM + k0 + c4 * 8);
        }
        cp_commit();
    };

    issue(0, 0);
    const int NKT = DIM / 32;  // 48
    for (int kt = 0; kt < NKT; kt++) {
        int buf = kt & 1;
        cp_wait0();
        __syncthreads();
        if (kt + 1 < NKT) issue(kt + 1, buf ^ 1);

        const unsigned* As = smu + (buf ? OFF_A1 : OFF_A0);
        const unsigned* Bs = smu + (buf ? OFF_B1 : OFF_B0);

#pragma unroll
        for (int kk = 0; kk < 2; kk++) {
            unsigned a[4][4];
#pragma unroll
            for (int mt = 0; mt < 4; mt++) {
                int row = wm + mt * 16;
                a[mt][0] = As[(row + g)     * GP + kk * 8 + l];
                a[mt][1] = As[(row + g + 8) * GP + kk * 8 + l];
                a[mt][2] = As[(row + g)     * GP + kk * 8 + l + 4];
                a[mt][3] = As[(row + g + 8) * GP + kk * 8 + l + 4];
            }
            unsigned b[4][2];
#pragma unroll
            for (int nt = 0; nt < 4; nt++) {
                int col = wn + nt * 8;
                b[nt][0] = Bs[(col + g) * GP + kk * 8 + l];
                b[nt][1] = Bs[(col + g) * GP + kk * 8 + l + 4];
            }
#pragma unroll
            for (int mt = 0; mt < 4; mt++)
#pragma unroll
                for (int nt = 0; nt < 4; nt++)
                    mma_f16(c[mt][nt][0], c[mt][nt][1], c[mt][nt][2], c[mt][nt][3],
                            a[mt][0], a[mt][1], a[mt][2], a[mt][3],
                            b[nt][0], b[nt][1]);
        }
    }

    if (p.isHalf[which]) {
        __half* Ch = (__half*)p.C[which];
#pragma unroll
        for (int mt = 0; mt < 4; mt++) {
#pragma unroll
            for (int nt = 0; nt < 4; nt++) {
                int row = bm + wm + mt * 16 + g;
                int col = bn + wn + nt * 8 + 2 * l;
                float b0 = bias[col], b1 = bias[col + 1];
                *(__half2*)(Ch + (size_t)row * DIM + col) =
                    __float22half2_rn(make_float2(c[mt][nt][0] + b0, c[mt][nt][1] + b1));
                *(__half2*)(Ch + (size_t)(row + 8) * DIM + col) =
                    __float22half2_rn(make_float2(c[mt][nt][2] + b0, c[mt][nt][3] + b1));
            }
        }
    } else {
        float* C = (float*)p.C[which];
#pragma unroll
        for (int mt = 0; mt < 4; mt++) {
#pragma unroll
            for (int nt = 0; nt < 4; nt++) {
                int row = bm + wm + mt * 16 + g;
                int col = bn + wn + nt * 8 + 2 * l;
                float b0 = bias[col], b1 = bias[col + 1];
                C[(size_t)row * DIM + col]           = c[mt][nt][0] + b0;
                C[(size_t)row * DIM + col + 1]       = c[mt][nt][1] + b1;
                C[(size_t)(row + 8) * DIM + col]     = c[mt][nt][2] + b0;
                C[(size_t)(row + 8) * DIM + col + 1] = c[mt][nt][3] + b1;
            }
        }
    }
}

#define GEMM_SMEM ((4 * 128 * GP) * 4)   // 40960 B

// ---------------- RMSNorm (plain): half out ----------------
__global__ __launch_bounds__(256) void rmsnorm_kernel(
    const float* __restrict__ x, const float* __restrict__ g,
    __half* __restrict__ out_b, float bscale)
{
    const int row = blockIdx.x;
    const float* xr = x + (size_t)row * DIM;
    const int tid = threadIdx.x;

    float ss = 0.f;
    for (int i = tid; i < DIM; i += 256) {
        float v = xr[i];
        ss += v * v;
    }
#pragma unroll
    for (int off = 16; off; off >>= 1) ss += __shfl_xor_sync(0xffffffffu, ss, off);

    __shared__ float wsum[8];
    __shared__ float inv_s;
    if ((tid & 31) == 0) wsum[tid >> 5] = ss;
    __syncthreads();
    if (tid == 0) {
        float t = 0.f;
#pragma unroll
        for (int w = 0; w < 8; w++) t += wsum[w];
        inv_s = rsqrtf(t / (float)DIM + 1e-6f);
    }
    __syncthreads();
    float inv = inv_s;
    for (int i = tid; i < DIM; i += 256) {
        float v = xr[i] * inv * g[i];
        out_b[(size_t)row * DIM + i] = __float2half_rn(v * bscale);
    }
}

// ---------------- Fused RMSNorm + RoPE ----------------
__global__ __launch_bounds__(256) void rmsrope_kernel(
    const float* __restrict__ x, const float* __restrict__ g,
    const float* __restrict__ rc, const float* __restrict__ rs,
    __half* __restrict__ out_plain, __half* __restrict__ out_rope, float scale)
{
    const int row = blockIdx.x;
    const float* xr = x + (size_t)row * DIM;
    const int tid = threadIdx.x;

    float ss = 0.f;
    for (int i = tid; i < DIM; i += 256) {
        float v = xr[i];
        ss += v * v;
    }
#pragma unroll
    for (int off = 16; off; off >>= 1) ss += __shfl_xor_sync(0xffffffffu, ss, off);

    __shared__ float wsum[8];
    __shared__ float inv_s;
    if ((tid & 31) == 0) wsum[tid >> 5] = ss;
    __syncthreads();
    if (tid == 0) {
        float t = 0.f;
#pragma unroll
        for (int w = 0; w < 8; w++) t += wsum[w];
        inv_s = rsqrtf(t / (float)DIM + 1e-6f);
    }
    __syncthreads();
    float inv = inv_s;

    for (int p = tid; p < DIM / 2; p += 256) {
        int i = p & 63;
        int d = (p >> 6) * DH + 2 * i;
        float e = xr[d]     * inv * g[d];
        float o = xr[d + 1] * inv * g[d + 1];
        if (out_plain)
            *(__half2*)(out_plain + (size_t)row * DIM + d) =
                __float22half2_rn(make_float2(e * scale, o * scale));
        float c = rc[row * (DH / 2) + i];
        float s = rs[row * (DH / 2) + i];
        *(__half2*)(out_rope + (size_t)row * DIM + d) =
            __float22half2_rn(make_float2((e * c - o * s) * scale, (e * s + o * c) * scale));
    }
}

// ================= Fused flash attention (ref + main in one kernel) — R8/R10-proven ========
#define AQ 68
#define ATT_Q  0
#define ATT_K0 (128 * AQ)
#define ATT_K1 (ATT_K0 + 128 * AQ)
#define ATT_V0 (ATT_K1 + 128 * AQ)
#define ATT_V1 (ATT_V0 + 128 * AQ)
#define ATT_SMEM ((ATT_V1 + 128 * AQ) * 4)   // 174080 B

__global__ __launch_bounds__(256) void attn_fused(
    const __half* __restrict__ Q0, const __half* __restrict__ K0p,
    const __half* __restrict__ V0p, int Tk0,
    const __half* __restrict__ Q1, const __half* __restrict__ K1p,
    const __half* __restrict__ V1p, int Tk1,
    __half* __restrict__ Outh)
{
    extern __shared__ unsigned smu[];

    const int h = blockIdx.y;
    const int q0 = blockIdx.x * 128;
    const int tid = threadIdx.x;
    const int lane = tid & 31, warp = tid >> 5;
    const int g = lane >> 2, l = lane & 3;
    const unsigned sbase = (unsigned)__cvta_generic_to_shared(smu);

    const int ql_row = lane & 15;
    const unsigned ql_addr = sbase + (ATT_Q + (warp * 16 + ql_row) * AQ
                                      + ((lane & 16) ? 4 : 0)) * 4;
    const int bl_row  = (lane & 7) + ((lane & 16) ? 8 : 0);
    const int bl_colu = (lane & 8) ? 4 : 0;

    auto issue_Q = [&](const __half* Qp) {
#pragma unroll
        for (int u = 0; u < 8; u++) {
            int i = tid + u * 256;
            int r = i >> 4, c4 = i & 15;
            cp16(smu + ATT_Q + r * AQ + c4 * 4,
                 Qp + (size_t)(q0 + r) * DIM + h * DH + c4 * 8);
        }
    };
    auto issue_tile = [&](const __half* Kp, const __half* Vt, int Tk, int t, int buf) {
        unsigned* Ku = smu + (buf ? ATT_K1 : ATT_K0);
        unsigned* Vu = smu + (buf ? ATT_V1 : ATT_V0);
        const size_t krow = (size_t)(t * 128) * DIM + h * DH;
#pragma unroll
        for (int u = 0; u < 8; u++) {
            int i = tid + u * 256;
            int r = i >> 4, c4 = i & 15;
            cp16(Ku + r * AQ + c4 * 4, Kp + krow + (size_t)r * DIM + c4 * 8);
        }
#pragma unroll
        for (int u = 0; u < 8; u++) {
            int i = tid + u * 256;
            int r = i >> 4, c4 = i & 15;
            cp16(Vu + r * AQ + c4 * 4,
                 Vt + (size_t)(h * DH + r) * Tk + t * 128 + c4 * 8);
        }
        cp_commit();
    };

    float o[16][4];
    float m0, m1, l0, l1;
    unsigned qa[8][4];
    unsigned stash[16][2];

#pragma unroll
    for (int ph = 0; ph < 2; ph++) {
        const __half* Qp = ph ? Q1 : Q0;
        const __half* Kp = ph ? K1p : K0p;
        const __half* Vp = ph ? V1p : V0p;
        const int Tk = ph ? Tk1 : Tk0;
        const int ntiles = Tk / 128;

#pragma unroll
        for (int nt = 0; nt < 16; nt++)
#pragma unroll
            for (int i = 0; i < 4; i++) o[nt][i] = 0.f;
        m0 = m1 = -1e30f;
        l0 = l1 = 0.f;

        issue_Q(Qp);
        issue_tile(Kp, Vp, Tk, 0, 0);

        for (int t = 0; t < ntiles; t++) {
            int buf = t & 1;
            cp_wait0();
            __syncthreads();
            if (t + 1 < ntiles) issue_tile(Kp, Vp, Tk, t + 1, buf ^ 1);

            if (t == 0) {
#pragma unroll
                for (int kk = 0; kk < 8; kk++)
                    ldsm4(qa[kk][0], qa[kk][1], qa[kk][2], qa[kk][3], ql_addr + kk * 32);
            }

            const unsigned koff = sbase + (buf ? ATT_K1 : ATT_K0) * 4;
            const unsigned voff = sbase + (buf ? ATT_V1 : ATT_V0) * 4;

#pragma unroll
            for (int st = 0; st < 2; st++) {
                float s[8][4];
#pragma unroll
                for (int nt = 0; nt < 8; nt++)
#pragma unroll
                    for (int i = 0; i < 4; i++) s[nt][i] = 0.f;

#pragma unroll
                for (int kk = 0; kk < 8; kk++) {
                    unsigned kb[4][4];
#pragma unroll
                    for (int j = 0; j < 4; j++)
                        ldsm4(kb[j][0], kb[j][1], kb[j][2], kb[j][3],
                              koff + ((st * 64 + j * 16 + bl_row) * AQ + kk * 8 + bl_colu) * 4);
#pragma unroll
                    for (int j = 0; j < 4; j++) {
                        mma_f16(s[2*j][0], s[2*j][1], s[2*j][2], s[2*j][3],
                                qa[kk][0], qa[kk][1], qa[kk][2], qa[kk][3], kb[j][0], kb[j][1]);
                        mma_f16(s[2*j+1][0], s[2*j+1][1], s[2*j+1][2], s[2*j+1][3],
                                qa[kk][0], qa[kk][1], qa[kk][2], qa[kk][3], kb[j][2], kb[j][3]);
                    }
                }

                float tm0 = -1e30f, tm1 = -1e30f;
#pragma unroll
                for (int nt = 0; nt < 8; nt++) {
                    tm0 = fmaxf(tm0, fmaxf(s[nt][0], s[nt][1]));
                    tm1 = fmaxf(tm1, fmaxf(s[nt][2], s[nt][3]));
                }
                tm0 = fmaxf(tm0, __shfl_xor_sync(0xffffffffu, tm0, 1));
                tm0 = fmaxf(tm0, __shfl_xor_sync(0xffffffffu, tm0, 2));
                tm1 = fmaxf(tm1, __shfl_xor_sync(0xffffffffu, tm1, 1));
                tm1 = fmaxf(tm1, __shfl_xor_sync(0xffffffffu, tm1, 2));
                float mn0 = fmaxf(m0, tm0), mn1 = fmaxf(m1, tm1);
                float al0 = __expf(m0 - mn0), al1 = __expf(m1 - mn1);
                m0 = mn0; m1 = mn1;

                unsigned pa[4][4];
                float sum0 = 0.f, sum1 = 0.f;
#pragma unroll
                for (int nt = 0; nt < 8; nt++) {
                    float p0 = __expf(s[nt][0] - mn0);
                    float p1 = __expf(s[nt][1] - mn0);
                    float p2 = __expf(s[nt][2] - mn1);
                    float p3 = __expf(s[nt][3] - mn1);
                    sum0 += p0 + p1;
                    sum1 += p2 + p3;
                    unsigned lo = h2u(__float22half2_rn(make_float2(p0, p1)));
                    unsigned hi = h2u(__float22half2_rn(make_float2(p2, p3)));
                    int kt = nt >> 1;
                    if ((nt & 1) == 0) { pa[kt][0] = lo; pa[kt][1] = hi; }
                    else               { pa[kt][2] = lo; pa[kt][3] = hi; }
                }
                sum0 += __shfl_xor_sync(0xffffffffu, sum0, 1);
                sum0 += __shfl_xor_sync(0xffffffffu, sum0, 2);
                sum1 += __shfl_xor_sync(0xffffffffu, sum1, 1);
                sum1 += __shfl_xor_sync(0xffffffffu, sum1, 2);
                l0 = l0 * al0 + sum0;
                l1 = l1 * al1 + sum1;
#pragma unroll
                for (int nt = 0; nt < 16; nt++) {
                    o[nt][0] *= al0; o[nt][1] *= al0;
                    o[nt][2] *= al1; o[nt][3] *= al1;
                }

#pragma unroll
                for (int kt = 0; kt < 4; kt++) {
                    unsigned vb[8][4];
#pragma unroll
                    for (int j = 0; j < 8; j++)
                        ldsm4(vb[j][0], vb[j][1], vb[j][2], vb[j][3],
                              voff + ((j * 16 + bl_row) * AQ + st * 32 + kt * 8 + bl_colu) * 4);
#pragma unroll
                    for (int j = 0; j < 8; j++) {
                        mma_f16(o[2*j][0], o[2*j][1], o[2*j][2], o[2*j][3],
                                pa[kt][0], pa[kt][1], pa[kt][2], pa[kt][3], vb[j][0], vb[j][1]);
                        mma_f16(o[2*j+1][0], o[2*j+1][1], o[2*j+1][2], o[2*j+1][3],
                                pa[kt][0], pa[kt][1], pa[kt][2], pa[kt][3], vb[j][2], vb[j][3]);
                    }
                }
            }
        }

        if (ph == 0) {
            float inv0 = 1.f / l0, inv1 = 1.f / l1;
#pragma unroll
            for (int nt = 0; nt < 16; nt++) {
                stash[nt][0] = h2u(__float22half2_rn(
                    make_float2(o[nt][0] * inv0, o[nt][1] * inv0)));
                stash[nt][1] = h2u(__float22half2_rn(
                    make_float2(o[nt][2] * inv1, o[nt][3] * inv1)));
            }
        }
    }

    float inv0 = 1.f / l0, inv1 = 1.f / l1;
    int row0 = q0 + warp * 16 + g;
    int row1 = row0 + 8;
#pragma unroll
    for (int nt = 0; nt < 16; nt++) {
        int col = h * DH + nt * 8 + 2 * l;
        float2 r0 = __half22float2(*(__half2*)&stash[nt][0]);
        float2 r1 = __half22float2(*(__half2*)&stash[nt][1]);
        __half2 w0 = __float22half2_rn(
            make_float2(r0.x + o[nt][0] * inv0, r0.y + o[nt][1] * inv0));
        __half2 w1 = __float22half2_rn(
            make_float2(r1.x + o[nt][2] * inv1, r1.y + o[nt][3] * inv1));
        *(__half2*)(Outh + (size_t)row0 * DIM + col) = w0;
        *(__half2*)(Outh + (size_t)row1 * DIM + col) = w1;
    }
}

// ---------------- launch ----------------
extern "C" void kernel_launch(void* const* d_in, const int* in_sizes, int n_in,
                              void* d_out, int out_size)
{
    const float* hs   = (const float*)d_in[0];
    const float* rhs  = (const float*)d_in[1];
    const float* rcos = (const float*)d_in[2];
    const float* rsin = (const float*)d_in[3];
    const float* Wq   = (const float*)d_in[4];
    const float* bq   = (const float*)d_in[5];
    const float* Wk   = (const float*)d_in[6];
    const float* bk   = (const float*)d_in[7];
    const float* Wv   = (const float*)d_in[8];
    const float* bv   = (const float*)d_in[9];
    const float* Wkr  = (const float*)d_in[10];
    const float* bkr  = (const float*)d_in[11];
    const float* Wvr  = (const float*)d_in[12];
    const float* bvr  = (const float*)d_in[13];
    const float* Wo   = (const float*)d_in[14];
    const float* bo   = (const float*)d_in[15];
    const float* gq   = (const float*)d_in[16];
    const float* gk   = (const float*)d_in[17];
    float* out = (float*)d_out;

    float *qlin, *klin, *krlin;
    __half *hsh, *rhsh, *wth, *vh, *vrh, *qh, *qroph, *kh, *vth, *krh, *vrth, *attnh;
    cudaGetSymbolAddress((void**)&qlin,  g_qlin);
    cudaGetSymbolAddress((void**)&klin,  g_klin);
    cudaGetSymbolAddress((void**)&krlin, g_krlin);
    cudaGetSymbolAddress((void**)&hsh,   g_hsh);
    cudaGetSymbolAddress((void**)&rhsh,  g_rhsh);
    cudaGetSymbolAddress((void**)&wth,   g_wth);
    cudaGetSymbolAddress((void**)&vh,    g_vh);
    cudaGetSymbolAddress((void**)&vrh,   g_vrh);
    cudaGetSymbolAddress((void**)&qh,    g_qh);
    cudaGetSymbolAddress((void**)&qroph, g_qroph);
    cudaGetSymbolAddress((void**)&kh,    g_kh);
    cudaGetSymbolAddress((void**)&vth,   g_vth);
    cudaGetSymbolAddress((void**)&krh,   g_krh);
    cudaGetSymbolAddress((void**)&vrth,  g_vrth);
    cudaGetSymbolAddress((void**)&attnh, g_attnh);

    cudaFuncSetAttribute(attn_fused,
                         cudaFuncAttributeMaxDynamicSharedMemorySize, ATT_SMEM);

    const float scale = 0.08838834764831845f;  // 1/sqrt(128)
    const size_t NW = (size_t)DIM * DIM;
    const int NT = T_LEN * DIM, NR = TR_LEN * DIM;
    const int CB = 256 * 4;

    // ---- activations -> half ----
    cvt_h<<<(NT + CB - 1) / CB, 256>>>(hs,  hsh,  NT, 1.f);
    cvt_h<<<(NR + CB - 1) / CB, 256>>>(rhs, rhsh, NR, 1.f);

    // ---- all 6 weight transposes in one launch ----
    Src6 wsrc;
    wsrc.p[0] = Wq; wsrc.p[1] = Wk; wsrc.p[2] = Wv;
    wsrc.p[3] = Wkr; wsrc.p[4] = Wvr; wsrc.p[5] = Wo;
    transpose6_h<<<dim3(DIM / 32, DIM / 32, 6), dim3(32, 8)>>>(wsrc, wth);

    // ---- all 5 projections in ONE launch (QKV main + ref KV); V outputs half ----
    GemmJob pj;
    pj.W[0] = wth + 0 * NW; pj.b[0] = bq;  pj.C[0] = qlin;  pj.isHalf[0] = 0;
    pj.W[1] = wth + 1 * NW; pj.b[1] = bk;  pj.C[1] = klin;  pj.isHalf[1] = 0;
    pj.W[2] = wth + 2 * NW; pj.b[2] = bv;  pj.C[2] = vh;    pj.isHalf[2] = 1;
    pj.W[3] = wth + 3 * NW; pj.b[3] = bkr; pj.C[3] = krlin; pj.isHalf[3] = 0;
    pj.W[4] = wth + 4 * NW; pj.b[4] = bvr; pj.C[4] = vrh;   pj.isHalf[4] = 1;
    gemm_f16_j<<<3 * 384 + 2 * 96, 256, GEMM_SMEM>>>(hsh, rhsh, pj, 3);

    // ---- V -> transposed half [h*DH+d][t] ----
    dim3 tb(32, 8);
    transpose_hh<<<dim3(DIM / 32, T_LEN / 32),  tb>>>(vh,  vth,  T_LEN,  DIM);
    transpose_hh<<<dim3(DIM / 32, TR_LEN / 32), tb>>>(vrh, vrth, TR_LEN, DIM);

    // ---- fused RMSNorm+RoPE (q: both; k: roped only), ref k plain ----
    rmsrope_kernel<<<T_LEN, 256>>>(qlin, gq, rcos, rsin, qh, qroph, scale);
    rmsrope_kernel<<<T_LEN, 256>>>(klin, gk, rcos, rsin, nullptr, kh, 1.f);
    rmsnorm_kernel<<<TR_LEN, 256>>>(krlin, gk, krh, 1.f);

    // ---- fused attention (ref + main), half output ----
    dim3 attn_grid(T_LEN / 128, NH);  // (32, 12)
    attn_fused<<<attn_grid, 256, ATT_SMEM>>>(qh, krh, vrth, TR_LEN,
                                             qroph, kh, vth, T_LEN, attnh);

    // ---- output projection (same kernel, nMain=1) ----
    GemmJob po;
    po.W[0] = wth + 5 * NW; po.b[0] = bo; po.C[0] = out; po.isHalf[0] = 0;
    po.W[1] = po.W[0]; po.b[1] = po.b[0]; po.C[1] = out; po.isHalf[1] = 0;
    po.W[2] = po.W[0]; po.b[2] = po.b[0]; po.C[2] = out; po.isHalf[2] = 0;
    po.W[3] = po.W[0]; po.b[3] = po.b[0]; po.C[3] = out; po.isHalf[3] = 0;
    po.W[4] = po.W[0]; po.b[4] = po.b[0]; po.C[4] = out; po.isHalf[4] = 0;
    gemm_f16_j<<<384, 256, GEMM_SMEM>>>(attnh, attnh, po, 1);
}

// round 14
// speedup vs baseline: 1.4970x; 1.0204x over previous
#include <cuda_runtime.h>
#include <cuda_fp16.h>
#include <math.h>

#define T_LEN 4096
#define TR_LEN 1024
#define DIM 1536
#define NH 12
#define DH 128

// ---------------- scratch (device globals; no allocation allowed) ----------------
__device__ __half g_hsh[T_LEN * DIM];
__device__ __half g_rhsh[TR_LEN * DIM];
__device__ __half g_wth[6 * DIM * DIM];   // Wq,Wk,Wv,Wkr,Wvr,Wo transposed [n][k]
__device__ __half g_qlh[T_LEN * DIM];     // q_lin (half)
__device__ __half g_klh[T_LEN * DIM];     // k_lin (half)
__device__ __half g_krlh[TR_LEN * DIM];   // ref k_lin (half)
__device__ __half g_qh[T_LEN * DIM];      // rms(q)*scale (unroped, ref attn)
__device__ __half g_qroph[T_LEN * DIM];   // rope(rms(q))*scale
__device__ __half g_kh[T_LEN * DIM];      // rope(rms(k))
__device__ __half g_vth[DIM * T_LEN];     // V transposed [h*DH + d][t] (from GEMM)
__device__ __half g_krh[TR_LEN * DIM];    // rms(ref k)
__device__ __half g_vrth[DIM * TR_LEN];   // ref V transposed (from GEMM)
__device__ __half g_attnh[T_LEN * DIM];   // attention output (half, fused ref+main)

// ---------------- PTX helpers ----------------
__device__ __forceinline__ void mma_f16(float& c0, float& c1, float& c2, float& c3,
                                        unsigned a0, unsigned a1, unsigned a2, unsigned a3,
                                        unsigned b0, unsigned b1) {
    asm volatile(
        "mma.sync.aligned.m16n8k16.row.col.f32.f16.f16.f32 "
        "{%0,%1,%2,%3},{%4,%5,%6,%7},{%8,%9},{%0,%1,%2,%3};"
        : "+f"(c0), "+f"(c1), "+f"(c2), "+f"(c3)
        : "r"(a0), "r"(a1), "r"(a2), "r"(a3), "r"(b0), "r"(b1));
}
__device__ __forceinline__ void ldsm4(unsigned& r0, unsigned& r1, unsigned& r2, unsigned& r3,
                                      unsigned addr) {
    asm volatile("ldmatrix.sync.aligned.m8n8.x4.shared.b16 {%0,%1,%2,%3}, [%4];"
                 : "=r"(r0), "=r"(r1), "=r"(r2), "=r"(r3) : "r"(addr));
}
__device__ __forceinline__ void cp16(void* dst_smem, const void* src) {
    unsigned s = (unsigned)__cvta_generic_to_shared(dst_smem);
    asm volatile("cp.async.cg.shared.global [%0], [%1], 16;" :: "r"(s), "l"(src));
}
__device__ __forceinline__ void cp_commit() { asm volatile("cp.async.commit_group;"); }
__device__ __forceinline__ void cp_wait0()  { asm volatile("cp.async.wait_group 0;"); }
__device__ __forceinline__ unsigned h2u(__half2 h) { return *(unsigned*)&h; }

// ---------------- float -> half conversion ----------------
__global__ __launch_bounds__(256) void cvt_h(
    const float* __restrict__ in, __half* __restrict__ out, int n, float scale)
{
    int i4 = (blockIdx.x * 256 + threadIdx.x) * 4;
    if (i4 >= n) return;
    float4 v = *(const float4*)(in + i4);
    __half2 h0 = __float22half2_rn(make_float2(v.x * scale, v.y * scale));
    __half2 h1 = __float22half2_rn(make_float2(v.z * scale, v.w * scale));
    uint2 u; u.x = h2u(h0); u.y = h2u(h1);
    *(uint2*)(out + i4) = u;
}

// 6 weight transposes in one launch (z picks the matrix)
struct Src6 { const float* p[6]; };
__global__ __launch_bounds__(256) void transpose6_h(Src6 s, __half* __restrict__ dstbase)
{
    __shared__ float t[32][33];
    const float* in = s.p[blockIdx.z];
    __half* out = dstbase + (size_t)blockIdx.z * DIM * DIM;
    int c0 = blockIdx.x * 32, r0 = blockIdx.y * 32;
    int tx = threadIdx.x, ty = threadIdx.y;
#pragma unroll
    for (int yy = 0; yy < 32; yy += 8)
        t[ty + yy][tx] = in[(size_t)(r0 + ty + yy) * DIM + c0 + tx];
    __syncthreads();
#pragma unroll
    for (int yy = 0; yy < 32; yy += 8)
        out[(size_t)(c0 + ty + yy) * DIM + r0 + tx] = __float2half_rn(t[tx][ty + yy]);
}

// ================= GEMM (fp16 mma), up to 5 outputs per launch =================
// Flat grid: first nMain*384 blocks are main tiles (A=Am, M=4096), rest ref (A=Ar, M=1024).
// Output modes: 0 = float row-major, 1 = half row-major, 2 = half TRANSPOSED [n][m]
// (mode 2 stages the tile through smem post-loop; used for V -> vth directly).
#define GP 20   // smem pitch in unsigned (40 halves)
#define TP 136  // transpose-stage pitch in halves
struct GemmJob { const __half* W[5]; const float* b[5]; void* C[5]; int mode[5]; };

__global__ __launch_bounds__(256) void gemm_f16_j(
    const __half* __restrict__ Am, const __half* __restrict__ Ar,
    GemmJob p, int nMain)
{
    constexpr int OFF_A0 = 0;
    constexpr int OFF_A1 = 128 * GP;
    constexpr int OFF_B0 = 2 * 128 * GP;
    constexpr int OFF_B1 = OFF_B0 + 128 * GP;

    extern __shared__ unsigned smu[];
    const int x = blockIdx.x;
    const int mainTiles = nMain * 384;
    const __half* A;
    int which, tile, Mrows;
    if (x < mainTiles) { which = x / 384; tile = x % 384; A = Am; Mrows = T_LEN; }
    else { int r = x - mainTiles; which = nMain + r / 96; tile = r % 96; A = Ar; Mrows = TR_LEN; }

    const __half* Wt = p.W[which];
    const float* bias = p.b[which];
    const int bm = (tile / 12) * 128;
    const int bn = (tile % 12) * 128;
    const int tid = threadIdx.x;
    const int lane = tid & 31, warp = tid >> 5;
    const int g = lane >> 2, l = lane & 3;
    const int wm = (warp >> 2) * 64;
    const int wn = (warp & 3) * 32;

    float c[4][4][4];
#pragma unroll
    for (int mt = 0; mt < 4; mt++)
#pragma unroll
        for (int nt = 0; nt < 4; nt++)
#pragma unroll
            for (int i = 0; i < 4; i++) c[mt][nt][i] = 0.f;

    auto issue = [&](int kt, int buf) {
        unsigned* Au = smu + (buf ? OFF_A1 : OFF_A0);
        unsigned* Bu = smu + (buf ? OFF_B1 : OFF_B0);
        const int k0 = kt * 32;
#pragma unroll
        for (int u = 0; u < 2; u++) {
            int i = tid + u * 256;
            int r = i >> 2, c4 = i & 3;
            cp16(Au + r * GP + c4 * 4, A + (size_t)(bm + r) * DIM + k0 + c4 * 8);
        }
#pragma unroll
        for (int u = 0; u < 2; u++) {
            int i = tid + u * 256;
            int r = i >> 2, c4 = i & 3;
            cp16(Bu + r * GP + c4 * 4, Wt + (size_t)(bn + r) * DIM + k0 + c4 * 8);
        }
        cp_commit();
    };

    issue(0, 0);
    const int NKT = DIM / 32;  // 48
    for (int kt = 0; kt < NKT; kt++) {
        int buf = kt & 1;
        cp_wait0();
        __syncthreads();
        if (kt + 1 < NKT) issue(kt + 1, buf ^ 1);

        const unsigned* As = smu + (buf ? OFF_A1 : OFF_A0);
        const unsigned* Bs = smu + (buf ? OFF_B1 : OFF_B0);

#pragma unroll
        for (int kk = 0; kk < 2; kk++) {
            unsigned a[4][4];
#pragma unroll
            for (int mt = 0; mt < 4; mt++) {
                int row = wm + mt * 16;
                a[mt][0] = As[(row + g)     * GP + kk * 8 + l];
                a[mt][1] = As[(row + g + 8) * GP + kk * 8 + l];
                a[mt][2] = As[(row + g)     * GP + kk * 8 + l + 4];
                a[mt][3] = As[(row + g + 8) * GP + kk * 8 + l + 4];
            }
            unsigned b[4][2];
#pragma unroll
            for (int nt = 0; nt < 4; nt++) {
                int col = wn + nt * 8;
                b[nt][0] = Bs[(col + g) * GP + kk * 8 + l];
                b[nt][1] = Bs[(col + g) * GP + kk * 8 + l + 4];
            }
#pragma unroll
            for (int mt = 0; mt < 4; mt++)
#pragma unroll
                for (int nt = 0; nt < 4; nt++)
                    mma_f16(c[mt][nt][0], c[mt][nt][1], c[mt][nt][2], c[mt][nt][3],
                            a[mt][0], a[mt][1], a[mt][2], a[mt][3],
                            b[nt][0], b[nt][1]);
        }
    }

    const int mode = p.mode[which];
    if (mode == 2) {
        // Transposed half output: stage tile transposed in smem, write coalesced.
        __syncthreads();  // all warps done with As/Bs
        __half* Tt = (__half*)smu;
#pragma unroll
        for (int mt = 0; mt < 4; mt++) {
#pragma unroll
            for (int nt = 0; nt < 4; nt++) {
                int rrow = wm + mt * 16 + g;
                int ccol = wn + nt * 8 + 2 * l;
                float b0 = bias[bn + ccol], b1 = bias[bn + ccol + 1];
                Tt[ccol * TP + rrow]           = __float2half_rn(c[mt][nt][0] + b0);
                Tt[(ccol + 1) * TP + rrow]     = __float2half_rn(c[mt][nt][1] + b1);
                Tt[ccol * TP + rrow + 8]       = __float2half_rn(c[mt][nt][2] + b0);
                Tt[(ccol + 1) * TP + rrow + 8] = __float2half_rn(c[mt][nt][3] + b1);
            }
        }
        __syncthreads();
        __half* Ch = (__half*)p.C[which];
#pragma unroll
        for (int u = 0; u < 4; u++) {
            int i = tid + u * 256;
            int r = i >> 3, c16 = (i & 7) * 16;
            uint4 v0 = *(uint4*)(Tt + r * TP + c16);
            uint4 v1 = *(uint4*)(Tt + r * TP + c16 + 8);
            __half* dst = Ch + (size_t)(bn + r) * Mrows + bm + c16;
            *(uint4*)dst = v0;
            *(uint4*)(dst + 8) = v1;
        }
    } else if (mode == 1) {
        __half* Ch = (__half*)p.C[which];
#pragma unroll
        for (int mt = 0; mt < 4; mt++) {
#pragma unroll
            for (int nt = 0; nt < 4; nt++) {
                int row = bm + wm + mt * 16 + g;
                int col = bn + wn + nt * 8 + 2 * l;
                float b0 = bias[col], b1 = bias[col + 1];
                *(__half2*)(Ch + (size_t)row * DIM + col) =
                    __float22half2_rn(make_float2(c[mt][nt][0] + b0, c[mt][nt][1] + b1));
                *(__half2*)(Ch + (size_t)(row + 8) * DIM + col) =
                    __float22half2_rn(make_float2(c[mt][nt][2] + b0, c[mt][nt][3] + b1));
            }
        }
    } else {
        float* C = (float*)p.C[which];
#pragma unroll
        for (int mt = 0; mt < 4; mt++) {
#pragma unroll
            for (int nt = 0; nt < 4; nt++) {
                int row = bm + wm + mt * 16 + g;
                int col = bn + wn + nt * 8 + 2 * l;
                float b0 = bias[col], b1 = bias[col + 1];
                C[(size_t)row * DIM + col]           = c[mt][nt][0] + b0;
                C[(size_t)row * DIM + col + 1]       = c[mt][nt][1] + b1;
                C[(size_t)(row + 8) * DIM + col]     = c[mt][nt][2] + b0;
                C[(size_t)(row + 8) * DIM + col + 1] = c[mt][nt][3] + b1;
            }
        }
    }
}

#define GEMM_SMEM ((4 * 128 * GP) * 4)   // 40960 B (>= 128*TP*2 = 34816 for stage)

// ---------------- RMSNorm (half in, half out) ----------------
__global__ __launch_bounds__(256) void rmsnorm_kernel(
    const __half* __restrict__ x, const float* __restrict__ g,
    __half* __restrict__ out_b, float bscale)
{
    const int row = blockIdx.x;
    const __half* xr = x + (size_t)row * DIM;
    const int tid = threadIdx.x;

    float ss = 0.f;
    for (int i = tid; i < DIM; i += 256) {
        float v = __half2float(xr[i]);
        ss += v * v;
    }
#pragma unroll
    for (int off = 16; off; off >>= 1) ss += __shfl_xor_sync(0xffffffffu, ss, off);

    __shared__ float wsum[8];
    __shared__ float inv_s;
    if ((tid & 31) == 0) wsum[tid >> 5] = ss;
    __syncthreads();
    if (tid == 0) {
        float t = 0.f;
#pragma unroll
        for (int w = 0; w < 8; w++) t += wsum[w];
        inv_s = rsqrtf(t / (float)DIM + 1e-6f);
    }
    __syncthreads();
    float inv = inv_s;
    for (int i = tid; i < DIM; i += 256) {
        float v = __half2float(xr[i]) * inv * g[i];
        out_b[(size_t)row * DIM + i] = __float2half_rn(v * bscale);
    }
}

// ---------------- Fused RMSNorm + RoPE (half in) ----------------
__global__ __launch_bounds__(256) void rmsrope_kernel(
    const __half* __restrict__ x, const float* __restrict__ g,
    const float* __restrict__ rc, const float* __restrict__ rs,
    __half* __restrict__ out_plain, __half* __restrict__ out_rope, float scale)
{
    const int row = blockIdx.x;
    const __half* xr = x + (size_t)row * DIM;
    const int tid = threadIdx.x;

    float ss = 0.f;
    for (int i = tid; i < DIM; i += 256) {
        float v = __half2float(xr[i]);
        ss += v * v;
    }
#pragma unroll
    for (int off = 16; off; off >>= 1) ss += __shfl_xor_sync(0xffffffffu, ss, off);

    __shared__ float wsum[8];
    __shared__ float inv_s;
    if ((tid & 31) == 0) wsum[tid >> 5] = ss;
    __syncthreads();
    if (tid == 0) {
        float t = 0.f;
#pragma unroll
        for (int w = 0; w < 8; w++) t += wsum[w];
        inv_s = rsqrtf(t / (float)DIM + 1e-6f);
    }
    __syncthreads();
    float inv = inv_s;

    for (int p = tid; p < DIM / 2; p += 256) {
        int i = p & 63;
        int d = (p >> 6) * DH + 2 * i;
        float e = __half2float(xr[d])     * inv * g[d];
        float o = __half2float(xr[d + 1]) * inv * g[d + 1];
        if (out_plain)
            *(__half2*)(out_plain + (size_t)row * DIM + d) =
                __float22half2_rn(make_float2(e * scale, o * scale));
        float c = rc[row * (DH / 2) + i];
        float s = rs[row * (DH / 2) + i];
        *(__half2*)(out_rope + (size_t)row * DIM + d) =
            __float22half2_rn(make_float2((e * c - o * s) * scale, (e * s + o * c) * scale));
    }
}

// ================= Fused flash attention (ref + main in one kernel) — proven ========
#define AQ 68
#define ATT_Q  0
#define ATT_K0 (128 * AQ)
#define ATT_K1 (ATT_K0 + 128 * AQ)
#define ATT_V0 (ATT_K1 + 128 * AQ)
#define ATT_V1 (ATT_V0 + 128 * AQ)
#define ATT_SMEM ((ATT_V1 + 128 * AQ) * 4)   // 174080 B

__global__ __launch_bounds__(256) void attn_fused(
    const __half* __restrict__ Q0, const __half* __restrict__ K0p,
    const __half* __restrict__ V0p, int Tk0,
    const __half* __restrict__ Q1, const __half* __restrict__ K1p,
    const __half* __restrict__ V1p, int Tk1,
    __half* __restrict__ Outh)
{
    extern __shared__ unsigned smu[];

    const int h = blockIdx.y;
    const int q0 = blockIdx.x * 128;
    const int tid = threadIdx.x;
    const int lane = tid & 31, warp = tid >> 5;
    const int g = lane >> 2, l = lane & 3;
    const unsigned sbase = (unsigned)__cvta_generic_to_shared(smu);

    const int ql_row = lane & 15;
    const unsigned ql_addr = sbase + (ATT_Q + (warp * 16 + ql_row) * AQ
                                      + ((lane & 16) ? 4 : 0)) * 4;
    const int bl_row  = (lane & 7) + ((lane & 16) ? 8 : 0);
    const int bl_colu = (lane & 8) ? 4 : 0;

    auto issue_Q = [&](const __half* Qp) {
#pragma unroll
        for (int u = 0; u < 8; u++) {
            int i = tid + u * 256;
            int r = i >> 4, c4 = i & 15;
            cp16(smu + ATT_Q + r * AQ + c4 * 4,
                 Qp + (size_t)(q0 + r) * DIM + h * DH + c4 * 8);
        }
    };
    auto issue_tile = [&](const __half* Kp, const __half* Vt, int Tk, int t, int buf) {
        unsigned* Ku = smu + (buf ? ATT_K1 : ATT_K0);
        unsigned* Vu = smu + (buf ? ATT_V1 : ATT_V0);
        const size_t krow = (size_t)(t * 128) * DIM + h * DH;
#pragma unroll
        for (int u = 0; u < 8; u++) {
            int i = tid + u * 256;
            int r = i >> 4, c4 = i & 15;
            cp16(Ku + r * AQ + c4 * 4, Kp + krow + (size_t)r * DIM + c4 * 8);
        }
#pragma unroll
        for (int u = 0; u < 8; u++) {
            int i = tid + u * 256;
            int r = i >> 4, c4 = i & 15;
            cp16(Vu + r * AQ + c4 * 4,
                 Vt + (size_t)(h * DH + r) * Tk + t * 128 + c4 * 8);
        }
        cp_commit();
    };

    float o[16][4];
    float m0, m1, l0, l1;
    unsigned qa[8][4];
    unsigned stash[16][2];

#pragma unroll
    for (int ph = 0; ph < 2; ph++) {
        const __half* Qp = ph ? Q1 : Q0;
        const __half* Kp = ph ? K1p : K0p;
        const __half* Vp = ph ? V1p : V0p;
        const int Tk = ph ? Tk1 : Tk0;
        const int ntiles = Tk / 128;

#pragma unroll
        for (int nt = 0; nt < 16; nt++)
#pragma unroll
            for (int i = 0; i < 4; i++) o[nt][i] = 0.f;
        m0 = m1 = -1e30f;
        l0 = l1 = 0.f;

        issue_Q(Qp);
        issue_tile(Kp, Vp, Tk, 0, 0);

        for (int t = 0; t < ntiles; t++) {
            int buf = t & 1;
            cp_wait0();
            __syncthreads();
            if (t + 1 < ntiles) issue_tile(Kp, Vp, Tk, t + 1, buf ^ 1);

            if (t == 0) {
#pragma unroll
                for (int kk = 0; kk < 8; kk++)
                    ldsm4(qa[kk][0], qa[kk][1], qa[kk][2], qa[kk][3], ql_addr + kk * 32);
            }

            const unsigned koff = sbase + (buf ? ATT_K1 : ATT_K0) * 4;
            const unsigned voff = sbase + (buf ? ATT_V1 : ATT_V0) * 4;

#pragma unroll
            for (int st = 0; st < 2; st++) {
                float s[8][4];
#pragma unroll
                for (int nt = 0; nt < 8; nt++)
#pragma unroll
                    for (int i = 0; i < 4; i++) s[nt][i] = 0.f;

#pragma unroll
                for (int kk = 0; kk < 8; kk++) {
                    unsigned kb[4][4];
#pragma unroll
                    for (int j = 0; j < 4; j++)
                        ldsm4(kb[j][0], kb[j][1], kb[j][2], kb[j][3],
                              koff + ((st * 64 + j * 16 + bl_row) * AQ + kk * 8 + bl_colu) * 4);
#pragma unroll
                    for (int j = 0; j < 4; j++) {
                        mma_f16(s[2*j][0], s[2*j][1], s[2*j][2], s[2*j][3],
                                qa[kk][0], qa[kk][1], qa[kk][2], qa[kk][3], kb[j][0], kb[j][1]);
                        mma_f16(s[2*j+1][0], s[2*j+1][1], s[2*j+1][2], s[2*j+1][3],
                                qa[kk][0], qa[kk][1], qa[kk][2], qa[kk][3], kb[j][2], kb[j][3]);
                    }
                }

                float tm0 = -1e30f, tm1 = -1e30f;
#pragma unroll
                for (int nt = 0; nt < 8; nt++) {
                    tm0 = fmaxf(tm0, fmaxf(s[nt][0], s[nt][1]));
                    tm1 = fmaxf(tm1, fmaxf(s[nt][2], s[nt][3]));
                }
                tm0 = fmaxf(tm0, __shfl_xor_sync(0xffffffffu, tm0, 1));
                tm0 = fmaxf(tm0, __shfl_xor_sync(0xffffffffu, tm0, 2));
                tm1 = fmaxf(tm1, __shfl_xor_sync(0xffffffffu, tm1, 1));
                tm1 = fmaxf(tm1, __shfl_xor_sync(0xffffffffu, tm1, 2));
                float mn0 = fmaxf(m0, tm0), mn1 = fmaxf(m1, tm1);
                float al0 = __expf(m0 - mn0), al1 = __expf(m1 - mn1);
                m0 = mn0; m1 = mn1;

                unsigned pa[4][4];
                float sum0 = 0.f, sum1 = 0.f;
#pragma unroll
                for (int nt = 0; nt < 8; nt++) {
                    float p0 = __expf(s[nt][0] - mn0);
                    float p1 = __expf(s[nt][1] - mn0);
                    float p2 = __expf(s[nt][2] - mn1);
                    float p3 = __expf(s[nt][3] - mn1);
                    sum0 += p0 + p1;
                    sum1 += p2 + p3;
                    unsigned lo = h2u(__float22half2_rn(make_float2(p0, p1)));
                    unsigned hi = h2u(__float22half2_rn(make_float2(p2, p3)));
                    int kt = nt >> 1;
                    if ((nt & 1) == 0) { pa[kt][0] = lo; pa[kt][1] = hi; }
                    else               { pa[kt][2] = lo; pa[kt][3] = hi; }
                }
                sum0 += __shfl_xor_sync(0xffffffffu, sum0, 1);
                sum0 += __shfl_xor_sync(0xffffffffu, sum0, 2);
                sum1 += __shfl_xor_sync(0xffffffffu, sum1, 1);
                sum1 += __shfl_xor_sync(0xffffffffu, sum1, 2);
                l0 = l0 * al0 + sum0;
                l1 = l1 * al1 + sum1;
#pragma unroll
                for (int nt = 0; nt < 16; nt++) {
                    o[nt][0] *= al0; o[nt][1] *= al0;
                    o[nt][2] *= al1; o[nt][3] *= al1;
                }

#pragma unroll
                for (int kt = 0; kt < 4; kt++) {
                    unsigned vb[8][4];
#pragma unroll
                    for (int j = 0; j < 8; j++)
                        ldsm4(vb[j][0], vb[j][1], vb[j][2], vb[j][3],
                              voff + ((j * 16 + bl_row) * AQ + st * 32 + kt * 8 + bl_colu) * 4);
#pragma unroll
                    for (int j = 0; j < 8; j++) {
                        mma_f16(o[2*j][0], o[2*j][1], o[2*j][2], o[2*j][3],
                                pa[kt][0], pa[kt][1], pa[kt][2], pa[kt][3], vb[j][0], vb[j][1]);
                        mma_f16(o[2*j+1][0], o[2*j+1][1], o[2*j+1][2], o[2*j+1][3],
                                pa[kt][0], pa[kt][1], pa[kt][2], pa[kt][3], vb[j][2], vb[j][3]);
                    }
                }
            }
        }

        if (ph == 0) {
            float inv0 = 1.f / l0, inv1 = 1.f / l1;
#pragma unroll
            for (int nt = 0; nt < 16; nt++) {
                stash[nt][0] = h2u(__float22half2_rn(
                    make_float2(o[nt][0] * inv0, o[nt][1] * inv0)));
                stash[nt][1] = h2u(__float22half2_rn(
                    make_float2(o[nt][2] * inv1, o[nt][3] * inv1)));
            }
        }
    }

    float inv0 = 1.f / l0, inv1 = 1.f / l1;
    int row0 = q0 + warp * 16 + g;
    int row1 = row0 + 8;
#pragma unroll
    for (int nt = 0; nt < 16; nt++) {
        int col = h * DH + nt * 8 + 2 * l;
        float2 r0 = __half22float2(*(__half2*)&stash[nt][0]);
        float2 r1 = __half22float2(*(__half2*)&stash[nt][1]);
        __half2 w0 = __float22half2_rn(
            make_float2(r0.x + o[nt][0] * inv0, r0.y + o[nt][1] * inv0));
        __half2 w1 = __float22half2_rn(
            make_float2(r1.x + o[nt][2] * inv1, r1.y + o[nt][3] * inv1));
        *(__half2*)(Outh + (size_t)row0 * DIM + col) = w0;
        *(__half2*)(Outh + (size_t)row1 * DIM + col) = w1;
    }
}

// ---------------- launch ----------------
extern "C" void kernel_launch(void* const* d_in, const int* in_sizes, int n_in,
                              void* d_out, int out_size)
{
    const float* hs   = (const float*)d_in[0];
    const float* rhs  = (const float*)d_in[1];
    const float* rcos = (const float*)d_in[2];
    const float* rsin = (const float*)d_in[3];
    const float* Wq   = (const float*)d_in[4];
    const float* bq   = (const float*)d_in[5];
    const float* Wk   = (const float*)d_in[6];
    const float* bk   = (const float*)d_in[7];
    const float* Wv   = (const float*)d_in[8];
    const float* bv   = (const float*)d_in[9];
    const float* Wkr  = (const float*)d_in[10];
    const float* bkr  = (const float*)d_in[11];
    const float* Wvr  = (const float*)d_in[12];
    const float* bvr  = (const float*)d_in[13];
    const float* Wo   = (const float*)d_in[14];
    const float* bo   = (const float*)d_in[15];
    const float* gq   = (const float*)d_in[16];
    const float* gk   = (const float*)d_in[17];
    float* out = (float*)d_out;

    __half *hsh, *rhsh, *wth, *qlh, *klh, *krlh, *qh, *qroph, *kh, *vth, *krh, *vrth, *attnh;
    cudaGetSymbolAddress((void**)&hsh,   g_hsh);
    cudaGetSymbolAddress((void**)&rhsh,  g_rhsh);
    cudaGetSymbolAddress((void**)&wth,   g_wth);
    cudaGetSymbolAddress((void**)&qlh,   g_qlh);
    cudaGetSymbolAddress((void**)&klh,   g_klh);
    cudaGetSymbolAddress((void**)&krlh,  g_krlh);
    cudaGetSymbolAddress((void**)&qh,    g_qh);
    cudaGetSymbolAddress((void**)&qroph, g_qroph);
    cudaGetSymbolAddress((void**)&kh,    g_kh);
    cudaGetSymbolAddress((void**)&vth,   g_vth);
    cudaGetSymbolAddress((void**)&krh,   g_krh);
    cudaGetSymbolAddress((void**)&vrth,  g_vrth);
    cudaGetSymbolAddress((void**)&attnh, g_attnh);

    cudaFuncSetAttribute(attn_fused,
                         cudaFuncAttributeMaxDynamicSharedMemorySize, ATT_SMEM);

    const float scale = 0.08838834764831845f;  // 1/sqrt(128)
    const size_t NW = (size_t)DIM * DIM;
    const int NT = T_LEN * DIM, NR = TR_LEN * DIM;
    const int CB = 256 * 4;

    // ---- activations -> half ----
    cvt_h<<<(NT + CB - 1) / CB, 256>>>(hs,  hsh,  NT, 1.f);
    cvt_h<<<(NR + CB - 1) / CB, 256>>>(rhs, rhsh, NR, 1.f);

    // ---- all 6 weight transposes in one launch ----
    Src6 wsrc;
    wsrc.p[0] = Wq; wsrc.p[1] = Wk; wsrc.p[2] = Wv;
    wsrc.p[3] = Wkr; wsrc.p[4] = Wvr; wsrc.p[5] = Wo;
    transpose6_h<<<dim3(DIM / 32, DIM / 32, 6), dim3(32, 8)>>>(wsrc, wth);

    // ---- all 5 projections in ONE launch; q/k half, V directly transposed half ----
    GemmJob pj;
    pj.W[0] = wth + 0 * NW; pj.b[0] = bq;  pj.C[0] = qlh;  pj.mode[0] = 1;
    pj.W[1] = wth + 1 * NW; pj.b[1] = bk;  pj.C[1] = klh;  pj.mode[1] = 1;
    pj.W[2] = wth + 2 * NW; pj.b[2] = bv;  pj.C[2] = vth;  pj.mode[2] = 2;
    pj.W[3] = wth + 3 * NW; pj.b[3] = bkr; pj.C[3] = krlh; pj.mode[3] = 1;
    pj.W[4] = wth + 4 * NW; pj.b[4] = bvr; pj.C[4] = vrth; pj.mode[4] = 2;
    gemm_f16_j<<<3 * 384 + 2 * 96, 256, GEMM_SMEM>>>(hsh, rhsh, pj, 3);

    // ---- fused RMSNorm+RoPE (q: both; k: roped only), ref k plain ----
    rmsrope_kernel<<<T_LEN, 256>>>(qlh, gq, rcos, rsin, qh, qroph, scale);
    rmsrope_kernel<<<T_LEN, 256>>>(klh, gk, rcos, rsin, nullptr, kh, 1.f);
    rmsnorm_kernel<<<TR_LEN, 256>>>(krlh, gk, krh, 1.f);

    // ---- fused attention (ref + main), half output ----
    dim3 attn_grid(T_LEN / 128, NH);  // (32, 12)
    attn_fused<<<attn_grid, 256, ATT_SMEM>>>(qh, krh, vrth, TR_LEN,
                                             qroph, kh, vth, T_LEN, attnh);

    // ---- output projection (same kernel, nMain=1, float out) ----
    GemmJob po;
    po.W[0] = wth + 5 * NW; po.b[0] = bo; po.C[0] = out; po.mode[0] = 0;
    po.W[1] = po.W[0]; po.b[1] = po.b[0]; po.C[1] = out; po.mode[1] = 0;
    po.W[2] = po.W[0]; po.b[2] = po.b[0]; po.C[2] = out; po.mode[2] = 0;
    po.W[3] = po.W[0]; po.b[3] = po.b[0]; po.C[3] = out; po.mode[3] = 0;
    po.W[4] = po.W[0]; po.b[4] = po.b[0]; po.C[4] = out; po.mode[4] = 0;
    gemm_f16_j<<<384, 256, GEMM_SMEM>>>(attnh, attnh, po, 1);
}

// round 15
// speedup vs baseline: 1.5113x; 1.0096x over previous
#include <cuda_runtime.h>
#include <cuda_fp16.h>
#include <math.h>

#define T_LEN 4096
#define TR_LEN 1024
#define DIM 1536
#define NH 12
#define DH 128

// ---------------- scratch (device globals; no allocation allowed) ----------------
__device__ __half g_hsh[T_LEN * DIM];
__device__ __half g_rhsh[TR_LEN * DIM];
__device__ __half g_wth[6 * DIM * DIM];   // Wq,Wk,Wv,Wkr,Wvr,Wo transposed [n][k]
__device__ __half g_qlh[T_LEN * DIM];     // q_lin (half)
__device__ __half g_klh[T_LEN * DIM];     // k_lin (half)
__device__ __half g_krlh[TR_LEN * DIM];   // ref k_lin (half)
__device__ __half g_qh[T_LEN * DIM];      // rms(q)*scale (unroped, ref attn)
__device__ __half g_qroph[T_LEN * DIM];   // rope(rms(q))*scale
__device__ __half g_kh[T_LEN * DIM];      // rope(rms(k))
__device__ __half g_vth[DIM * T_LEN];     // V transposed [h*DH + d][t] (from GEMM)
__device__ __half g_krh[TR_LEN * DIM];    // rms(ref k)
__device__ __half g_vrth[DIM * TR_LEN];   // ref V transposed (from GEMM)
__device__ __half g_attnh[T_LEN * DIM];   // attention output (half, fused ref+main)

// ---------------- PTX helpers ----------------
__device__ __forceinline__ void mma_f16(float& c0, float& c1, float& c2, float& c3,
                                        unsigned a0, unsigned a1, unsigned a2, unsigned a3,
                                        unsigned b0, unsigned b1) {
    asm volatile(
        "mma.sync.aligned.m16n8k16.row.col.f32.f16.f16.f32 "
        "{%0,%1,%2,%3},{%4,%5,%6,%7},{%8,%9},{%0,%1,%2,%3};"
        : "+f"(c0), "+f"(c1), "+f"(c2), "+f"(c3)
        : "r"(a0), "r"(a1), "r"(a2), "r"(a3), "r"(b0), "r"(b1));
}
__device__ __forceinline__ void ldsm4(unsigned& r0, unsigned& r1, unsigned& r2, unsigned& r3,
                                      unsigned addr) {
    asm volatile("ldmatrix.sync.aligned.m8n8.x4.shared.b16 {%0,%1,%2,%3}, [%4];"
                 : "=r"(r0), "=r"(r1), "=r"(r2), "=r"(r3) : "r"(addr));
}
__device__ __forceinline__ void cp16(void* dst_smem, const void* src) {
    unsigned s = (unsigned)__cvta_generic_to_shared(dst_smem);
    asm volatile("cp.async.cg.shared.global [%0], [%1], 16;" :: "r"(s), "l"(src));
}
__device__ __forceinline__ void cp_commit() { asm volatile("cp.async.commit_group;"); }
__device__ __forceinline__ void cp_wait0()  { asm volatile("cp.async.wait_group 0;"); }
__device__ __forceinline__ unsigned h2u(__half2 h) { return *(unsigned*)&h; }

// ---------------- float -> half conversion (hs + rhs in one launch) ----------------
#define CVT_MAIN_BLK ((T_LEN * DIM) / 1024)   // 6144 elems/blk? no: 1024 per block
__global__ __launch_bounds__(256) void cvt2(
    const float* __restrict__ a, __half* __restrict__ outa, int na,
    const float* __restrict__ b, __half* __restrict__ outb)
{
    int nBlkA = na / 1024;
    const float* in;
    __half* out;
    int base;
    if (blockIdx.x < nBlkA) { in = a; out = outa; base = blockIdx.x * 1024; }
    else { in = b; out = outb; base = (blockIdx.x - nBlkA) * 1024; }
    int i4 = base + threadIdx.x * 4;
    float4 v = *(const float4*)(in + i4);
    __half2 h0 = __float22half2_rn(make_float2(v.x, v.y));
    __half2 h1 = __float22half2_rn(make_float2(v.z, v.w));
    uint2 u; u.x = h2u(h0); u.y = h2u(h1);
    *(uint2*)(out + i4) = u;
}

// 6 weight transposes in one launch (z picks the matrix)
struct Src6 { const float* p[6]; };
__global__ __launch_bounds__(256) void transpose6_h(Src6 s, __half* __restrict__ dstbase)
{
    __shared__ float t[32][33];
    const float* in = s.p[blockIdx.z];
    __half* out = dstbase + (size_t)blockIdx.z * DIM * DIM;
    int c0 = blockIdx.x * 32, r0 = blockIdx.y * 32;
    int tx = threadIdx.x, ty = threadIdx.y;
#pragma unroll
    for (int yy = 0; yy < 32; yy += 8)
        t[ty + yy][tx] = in[(size_t)(r0 + ty + yy) * DIM + c0 + tx];
    __syncthreads();
#pragma unroll
    for (int yy = 0; yy < 32; yy += 8)
        out[(size_t)(c0 + ty + yy) * DIM + r0 + tx] = __float2half_rn(t[tx][ty + yy]);
}

// ================= GEMM (fp16 mma), up to 5 outputs per launch =================
// Flat grid: first nMain*384 blocks are main tiles (A=Am, M=4096), rest ref (A=Ar, M=1024).
// Output modes: 0 = float row-major, 1 = half row-major, 2 = half TRANSPOSED [n][m].
#define GP 20   // smem pitch in unsigned (40 halves)
#define TP 136  // transpose-stage pitch in halves
struct GemmJob { const __half* W[5]; const float* b[5]; void* C[5]; int mode[5]; };

__global__ __launch_bounds__(256) void gemm_f16_j(
    const __half* __restrict__ Am, const __half* __restrict__ Ar,
    GemmJob p, int nMain)
{
    constexpr int OFF_A0 = 0;
    constexpr int OFF_A1 = 128 * GP;
    constexpr int OFF_B0 = 2 * 128 * GP;
    constexpr int OFF_B1 = OFF_B0 + 128 * GP;

    extern __shared__ unsigned smu[];
    const int x = blockIdx.x;
    const int mainTiles = nMain * 384;
    const __half* A;
    int which, tile, Mrows;
    if (x < mainTiles) { which = x / 384; tile = x % 384; A = Am; Mrows = T_LEN; }
    else { int r = x - mainTiles; which = nMain + r / 96; tile = r % 96; A = Ar; Mrows = TR_LEN; }

    const __half* Wt = p.W[which];
    const float* bias = p.b[which];
    const int bm = (tile / 12) * 128;
    const int bn = (tile % 12) * 128;
    const int tid = threadIdx.x;
    const int lane = tid & 31, warp = tid >> 5;
    const int g = lane >> 2, l = lane & 3;
    const int wm = (warp >> 2) * 64;
    const int wn = (warp & 3) * 32;

    float c[4][4][4];
#pragma unroll
    for (int mt = 0; mt < 4; mt++)
#pragma unroll
        for (int nt = 0; nt < 4; nt++)
#pragma unroll
            for (int i = 0; i < 4; i++) c[mt][nt][i] = 0.f;

    auto issue = [&](int kt, int buf) {
        unsigned* Au = smu + (buf ? OFF_A1 : OFF_A0);
        unsigned* Bu = smu + (buf ? OFF_B1 : OFF_B0);
        const int k0 = kt * 32;
#pragma unroll
        for (int u = 0; u < 2; u++) {
            int i = tid + u * 256;
            int r = i >> 2, c4 = i & 3;
            cp16(Au + r * GP + c4 * 4, A + (size_t)(bm + r) * DIM + k0 + c4 * 8);
        }
#pragma unroll
        for (int u = 0; u < 2; u++) {
            int i = tid + u * 256;
            int r = i >> 2, c4 = i & 3;
            cp16(Bu + r * GP + c4 * 4, Wt + (size_t)(bn + r) * DIM + k0 + c4 * 8);
        }
        cp_commit();
    };

    issue(0, 0);
    const int NKT = DIM / 32;  // 48
    for (int kt = 0; kt < NKT; kt++) {
        int buf = kt & 1;
        cp_wait0();
        __syncthreads();
        if (kt + 1 < NKT) issue(kt + 1, buf ^ 1);

        const unsigned* As = smu + (buf ? OFF_A1 : OFF_A0);
        const unsigned* Bs = smu + (buf ? OFF_B1 : OFF_B0);

#pragma unroll
        for (int kk = 0; kk < 2; kk++) {
            unsigned a[4][4];
#pragma unroll
            for (int mt = 0; mt < 4; mt++) {
                int row = wm + mt * 16;
                a[mt][0] = As[(row + g)     * GP + kk * 8 + l];
                a[mt][1] = As[(row + g + 8) * GP + kk * 8 + l];
                a[mt][2] = As[(row + g)     * GP + kk * 8 + l + 4];
                a[mt][3] = As[(row + g + 8) * GP + kk * 8 + l + 4];
            }
            unsigned b[4][2];
#pragma unroll
            for (int nt = 0; nt < 4; nt++) {
                int col = wn + nt * 8;
                b[nt][0] = Bs[(col + g) * GP + kk * 8 + l];
                b[nt][1] = Bs[(col + g) * GP + kk * 8 + l + 4];
            }
#pragma unroll
            for (int mt = 0; mt < 4; mt++)
#pragma unroll
                for (int nt = 0; nt < 4; nt++)
                    mma_f16(c[mt][nt][0], c[mt][nt][1], c[mt][nt][2], c[mt][nt][3],
                            a[mt][0], a[mt][1], a[mt][2], a[mt][3],
                            b[nt][0], b[nt][1]);
        }
    }

    const int mode = p.mode[which];
    if (mode == 2) {
        __syncthreads();
        __half* Tt = (__half*)smu;
#pragma unroll
        for (int mt = 0; mt < 4; mt++) {
#pragma unroll
            for (int nt = 0; nt < 4; nt++) {
                int rrow = wm + mt * 16 + g;
                int ccol = wn + nt * 8 + 2 * l;
                float b0 = bias[bn + ccol], b1 = bias[bn + ccol + 1];
                Tt[ccol * TP + rrow]           = __float2half_rn(c[mt][nt][0] + b0);
                Tt[(ccol + 1) * TP + rrow]     = __float2half_rn(c[mt][nt][1] + b1);
                Tt[ccol * TP + rrow + 8]       = __float2half_rn(c[mt][nt][2] + b0);
                Tt[(ccol + 1) * TP + rrow + 8] = __float2half_rn(c[mt][nt][3] + b1);
            }
        }
        __syncthreads();
        __half* Ch = (__half*)p.C[which];
#pragma unroll
        for (int u = 0; u < 4; u++) {
            int i = tid + u * 256;
            int r = i >> 3, c16 = (i & 7) * 16;
            uint4 v0 = *(uint4*)(Tt + r * TP + c16);
            uint4 v1 = *(uint4*)(Tt + r * TP + c16 + 8);
            __half* dst = Ch + (size_t)(bn + r) * Mrows + bm + c16;
            *(uint4*)dst = v0;
            *(uint4*)(dst + 8) = v1;
        }
    } else if (mode == 1) {
        __half* Ch = (__half*)p.C[which];
#pragma unroll
        for (int mt = 0; mt < 4; mt++) {
#pragma unroll
            for (int nt = 0; nt < 4; nt++) {
                int row = bm + wm + mt * 16 + g;
                int col = bn + wn + nt * 8 + 2 * l;
                float b0 = bias[col], b1 = bias[col + 1];
                *(__half2*)(Ch + (size_t)row * DIM + col) =
                    __float22half2_rn(make_float2(c[mt][nt][0] + b0, c[mt][nt][1] + b1));
                *(__half2*)(Ch + (size_t)(row + 8) * DIM + col) =
                    __float22half2_rn(make_float2(c[mt][nt][2] + b0, c[mt][nt][3] + b1));
            }
        }
    } else {
        float* C = (float*)p.C[which];
#pragma unroll
        for (int mt = 0; mt < 4; mt++) {
#pragma unroll
            for (int nt = 0; nt < 4; nt++) {
                int row = bm + wm + mt * 16 + g;
                int col = bn + wn + nt * 8 + 2 * l;
                float b0 = bias[col], b1 = bias[col + 1];
                C[(size_t)row * DIM + col]           = c[mt][nt][0] + b0;
                C[(size_t)row * DIM + col + 1]       = c[mt][nt][1] + b1;
                C[(size_t)(row + 8) * DIM + col]     = c[mt][nt][2] + b0;
                C[(size_t)(row + 8) * DIM + col + 1] = c[mt][nt][3] + b1;
            }
        }
    }
}

#define GEMM_SMEM ((4 * 128 * GP) * 4)   // 40960 B

// ---------------- unified norm stage: q rmsrope / k rmsrope / ref-k rmsnorm ----------------
__device__ __forceinline__ float row_inv_rms(const __half* xr, int tid) {
    float ss = 0.f;
    for (int i = tid; i < DIM; i += 256) {
        float v = __half2float(xr[i]);
        ss += v * v;
    }
#pragma unroll
    for (int off = 16; off; off >>= 1) ss += __shfl_xor_sync(0xffffffffu, ss, off);
    __shared__ float wsum[8];
    __shared__ float inv_s;
    if ((tid & 31) == 0) wsum[tid >> 5] = ss;
    __syncthreads();
    if (tid == 0) {
        float t = 0.f;
#pragma unroll
        for (int w = 0; w < 8; w++) t += wsum[w];
        inv_s = rsqrtf(t / (float)DIM + 1e-6f);
    }
    __syncthreads();
    return inv_s;
}

__global__ __launch_bounds__(256) void norm_all(
    const __half* __restrict__ qlh, const __half* __restrict__ klh,
    const __half* __restrict__ krlh,
    const float* __restrict__ gq, const float* __restrict__ gk,
    const float* __restrict__ rc, const float* __restrict__ rs,
    __half* __restrict__ qh, __half* __restrict__ qroph,
    __half* __restrict__ kh, __half* __restrict__ krh, float scale)
{
    const int b = blockIdx.x;
    const int tid = threadIdx.x;

    if (b < 2 * T_LEN) {
        // rmsrope path: q (with plain output, scaled) or k (rope only, unscaled)
        const int isQ = (b < T_LEN);
        const int row = isQ ? b : b - T_LEN;
        const __half* xr = (isQ ? qlh : klh) + (size_t)row * DIM;
        const float* g = isQ ? gq : gk;
        const float sc = isQ ? scale : 1.f;
        __half* outp = isQ ? qh : nullptr;
        __half* outr = isQ ? qroph : kh;
        float inv = row_inv_rms(xr, tid);
        for (int p = tid; p < DIM / 2; p += 256) {
            int i = p & 63;
            int d = (p >> 6) * DH + 2 * i;
            float e = __half2float(xr[d])     * inv * g[d];
            float o = __half2float(xr[d + 1]) * inv * g[d + 1];
            if (outp)
                *(__half2*)(outp + (size_t)row * DIM + d) =
                    __float22half2_rn(make_float2(e * sc, o * sc));
            float c = rc[row * (DH / 2) + i];
            float s = rs[row * (DH / 2) + i];
            *(__half2*)(outr + (size_t)row * DIM + d) =
                __float22half2_rn(make_float2((e * c - o * s) * sc, (e * s + o * c) * sc));
        }
    } else {
        // plain rmsnorm for ref k
        const int row = b - 2 * T_LEN;
        const __half* xr = krlh + (size_t)row * DIM;
        float inv = row_inv_rms(xr, tid);
        for (int i = tid; i < DIM; i += 256) {
            float v = __half2float(xr[i]) * inv * gk[i];
            krh[(size_t)row * DIM + i] = __float2half_rn(v);
        }
    }
}

// ================= Fused flash attention (ref + main in one kernel) — proven ========
#define AQ 68
#define ATT_Q  0
#define ATT_K0 (128 * AQ)
#define ATT_K1 (ATT_K0 + 128 * AQ)
#define ATT_V0 (ATT_K1 + 128 * AQ)
#define ATT_V1 (ATT_V0 + 128 * AQ)
#define ATT_SMEM ((ATT_V1 + 128 * AQ) * 4)   // 174080 B

__global__ __launch_bounds__(256) void attn_fused(
    const __half* __restrict__ Q0, const __half* __restrict__ K0p,
    const __half* __restrict__ V0p, int Tk0,
    const __half* __restrict__ Q1, const __half* __restrict__ K1p,
    const __half* __restrict__ V1p, int Tk1,
    __half* __restrict__ Outh)
{
    extern __shared__ unsigned smu[];

    const int h = blockIdx.y;
    const int q0 = blockIdx.x * 128;
    const int tid = threadIdx.x;
    const int lane = tid & 31, warp = tid >> 5;
    const int g = lane >> 2, l = lane & 3;
    const unsigned sbase = (unsigned)__cvta_generic_to_shared(smu);

    const int ql_row = lane & 15;
    const unsigned ql_addr = sbase + (ATT_Q + (warp * 16 + ql_row) * AQ
                                      + ((lane & 16) ? 4 : 0)) * 4;
    const int bl_row  = (lane & 7) + ((lane & 16) ? 8 : 0);
    const int bl_colu = (lane & 8) ? 4 : 0;

    auto issue_Q = [&](const __half* Qp) {
#pragma unroll
        for (int u = 0; u < 8; u++) {
            int i = tid + u * 256;
            int r = i >> 4, c4 = i & 15;
            cp16(smu + ATT_Q + r * AQ + c4 * 4,
                 Qp + (size_t)(q0 + r) * DIM + h * DH + c4 * 8);
        }
    };
    auto issue_tile = [&](const __half* Kp, const __half* Vt, int Tk, int t, int buf) {
        unsigned* Ku = smu + (buf ? ATT_K1 : ATT_K0);
        unsigned* Vu = smu + (buf ? ATT_V1 : ATT_V0);
        const size_t krow = (size_t)(t * 128) * DIM + h * DH;
#pragma unroll
        for (int u = 0; u < 8; u++) {
            int i = tid + u * 256;
            int r = i >> 4, c4 = i & 15;
            cp16(Ku + r * AQ + c4 * 4, Kp + krow + (size_t)r * DIM + c4 * 8);
        }
#pragma unroll
        for (int u = 0; u < 8; u++) {
            int i = tid + u * 256;
            int r = i >> 4, c4 = i & 15;
            cp16(Vu + r * AQ + c4 * 4,
                 Vt + (size_t)(h * DH + r) * Tk + t * 128 + c4 * 8);
        }
        cp_commit();
    };

    float o[16][4];
    float m0, m1, l0, l1;
    unsigned qa[8][4];
    unsigned stash[16][2];

#pragma unroll
    for (int ph = 0; ph < 2; ph++) {
        const __half* Qp = ph ? Q1 : Q0;
        const __half* Kp = ph ? K1p : K0p;
        const __half* Vp = ph ? V1p : V0p;
        const int Tk = ph ? Tk1 : Tk0;
        const int ntiles = Tk / 128;

#pragma unroll
        for (int nt = 0; nt < 16; nt++)
#pragma unroll
            for (int i = 0; i < 4; i++) o[nt][i] = 0.f;
        m0 = m1 = -1e30f;
        l0 = l1 = 0.f;

        issue_Q(Qp);
        issue_tile(Kp, Vp, Tk, 0, 0);

        for (int t = 0; t < ntiles; t++) {
            int buf = t & 1;
            cp_wait0();
            __syncthreads();
            if (t + 1 < ntiles) issue_tile(Kp, Vp, Tk, t + 1, buf ^ 1);

            if (t == 0) {
#pragma unroll
                for (int kk = 0; kk < 8; kk++)
                    ldsm4(qa[kk][0], qa[kk][1], qa[kk][2], qa[kk][3], ql_addr + kk * 32);
            }

            const unsigned koff = sbase + (buf ? ATT_K1 : ATT_K0) * 4;
            const unsigned voff = sbase + (buf ? ATT_V1 : ATT_V0) * 4;

#pragma unroll
            for (int st = 0; st < 2; st++) {
                float s[8][4];
#pragma unroll
                for (int nt = 0; nt < 8; nt++)
#pragma unroll
                    for (int i = 0; i < 4; i++) s[nt][i] = 0.f;

#pragma unroll
                for (int kk = 0; kk < 8; kk++) {
                    unsigned kb[4][4];
#pragma unroll
                    for (int j = 0; j < 4; j++)
                        ldsm4(kb[j][0], kb[j][1], kb[j][2], kb[j][3],
                              koff + ((st * 64 + j * 16 + bl_row) * AQ + kk * 8 + bl_colu) * 4);
#pragma unroll
                    for (int j = 0; j < 4; j++) {
                        mma_f16(s[2*j][0], s[2*j][1], s[2*j][2], s[2*j][3],
                                qa[kk][0], qa[kk][1], qa[kk][2], qa[kk][3], kb[j][0], kb[j][1]);
                        mma_f16(s[2*j+1][0], s[2*j+1][1], s[2*j+1][2], s[2*j+1][3],
                                qa[kk][0], qa[kk][1], qa[kk][2], qa[kk][3], kb[j][2], kb[j][3]);
                    }
                }

                float tm0 = -1e30f, tm1 = -1e30f;
#pragma unroll
                for (int nt = 0; nt < 8; nt++) {
                    tm0 = fmaxf(tm0, fmaxf(s[nt][0], s[nt][1]));
                    tm1 = fmaxf(tm1, fmaxf(s[nt][2], s[nt][3]));
                }
                tm0 = fmaxf(tm0, __shfl_xor_sync(0xffffffffu, tm0, 1));
                tm0 = fmaxf(tm0, __shfl_xor_sync(0xffffffffu, tm0, 2));
                tm1 = fmaxf(tm1, __shfl_xor_sync(0xffffffffu, tm1, 1));
                tm1 = fmaxf(tm1, __shfl_xor_sync(0xffffffffu, tm1, 2));
                float mn0 = fmaxf(m0, tm0), mn1 = fmaxf(m1, tm1);
                float al0 = __expf(m0 - mn0), al1 = __expf(m1 - mn1);
                m0 = mn0; m1 = mn1;

                unsigned pa[4][4];
                float sum0 = 0.f, sum1 = 0.f;
#pragma unroll
                for (int nt = 0; nt < 8; nt++) {
                    float p0 = __expf(s[nt][0] - mn0);
                    float p1 = __expf(s[nt][1] - mn0);
                    float p2 = __expf(s[nt][2] - mn1);
                    float p3 = __expf(s[nt][3] - mn1);
                    sum0 += p0 + p1;
                    sum1 += p2 + p3;
                    unsigned lo = h2u(__float22half2_rn(make_float2(p0, p1)));
                    unsigned hi = h2u(__float22half2_rn(make_float2(p2, p3)));
                    int kt = nt >> 1;
                    if ((nt & 1) == 0) { pa[kt][0] = lo; pa[kt][1] = hi; }
                    else               { pa[kt][2] = lo; pa[kt][3] = hi; }
                }
                sum0 += __shfl_xor_sync(0xffffffffu, sum0, 1);
                sum0 += __shfl_xor_sync(0xffffffffu, sum0, 2);
                sum1 += __shfl_xor_sync(0xffffffffu, sum1, 1);
                sum1 += __shfl_xor_sync(0xffffffffu, sum1, 2);
                l0 = l0 * al0 + sum0;
                l1 = l1 * al1 + sum1;
#pragma unroll
                for (int nt = 0; nt < 16; nt++) {
                    o[nt][0] *= al0; o[nt][1] *= al0;
                    o[nt][2] *= al1; o[nt][3] *= al1;
                }

#pragma unroll
                for (int kt = 0; kt < 4; kt++) {
                    unsigned vb[8][4];
#pragma unroll
                    for (int j = 0; j < 8; j++)
                        ldsm4(vb[j][0], vb[j][1], vb[j][2], vb[j][3],
                              voff + ((j * 16 + bl_row) * AQ + st * 32 + kt * 8 + bl_colu) * 4);
#pragma unroll
                    for (int j = 0; j < 8; j++) {
                        mma_f16(o[2*j][0], o[2*j][1], o[2*j][2], o[2*j][3],
                                pa[kt][0], pa[kt][1], pa[kt][2], pa[kt][3], vb[j][0], vb[j][1]);
                        mma_f16(o[2*j+1][0], o[2*j+1][1], o[2*j+1][2], o[2*j+1][3],
                                pa[kt][0], pa[kt][1], pa[kt][2], pa[kt][3], vb[j][2], vb[j][3]);
                    }
                }
            }
        }

        if (ph == 0) {
            float inv0 = 1.f / l0, inv1 = 1.f / l1;
#pragma unroll
            for (int nt = 0; nt < 16; nt++) {
                stash[nt][0] = h2u(__float22half2_rn(
                    make_float2(o[nt][0] * inv0, o[nt][1] * inv0)));
                stash[nt][1] = h2u(__float22half2_rn(
                    make_float2(o[nt][2] * inv1, o[nt][3] * inv1)));
            }
        }
    }

    float inv0 = 1.f / l0, inv1 = 1.f / l1;
    int row0 = q0 + warp * 16 + g;
    int row1 = row0 + 8;
#pragma unroll
    for (int nt = 0; nt < 16; nt++) {
        int col = h * DH + nt * 8 + 2 * l;
        float2 r0 = __half22float2(*(__half2*)&stash[nt][0]);
        float2 r1 = __half22float2(*(__half2*)&stash[nt][1]);
        __half2 w0 = __float22half2_rn(
            make_float2(r0.x + o[nt][0] * inv0, r0.y + o[nt][1] * inv0));
        __half2 w1 = __float22half2_rn(
            make_float2(r1.x + o[nt][2] * inv1, r1.y + o[nt][3] * inv1));
        *(__half2*)(Outh + (size_t)row0 * DIM + col) = w0;
        *(__half2*)(Outh + (size_t)row1 * DIM + col) = w1;
    }
}

// ---------------- launch ----------------
extern "C" void kernel_launch(void* const* d_in, const int* in_sizes, int n_in,
                              void* d_out, int out_size)
{
    const float* hs   = (const float*)d_in[0];
    const float* rhs  = (const float*)d_in[1];
    const float* rcos = (const float*)d_in[2];
    const float* rsin = (const float*)d_in[3];
    const float* Wq   = (const float*)d_in[4];
    const float* bq   = (const float*)d_in[5];
    const float* Wk   = (const float*)d_in[6];
    const float* bk   = (const float*)d_in[7];
    const float* Wv   = (const float*)d_in[8];
    const float* bv   = (const float*)d_in[9];
    const float* Wkr  = (const float*)d_in[10];
    const float* bkr  = (const float*)d_in[11];
    const float* Wvr  = (const float*)d_in[12];
    const float* bvr  = (const float*)d_in[13];
    const float* Wo   = (const float*)d_in[14];
    const float* bo   = (const float*)d_in[15];
    const float* gq   = (const float*)d_in[16];
    const float* gk   = (const float*)d_in[17];
    float* out = (float*)d_out;

    __half *hsh, *rhsh, *wth, *qlh, *klh, *krlh, *qh, *qroph, *kh, *vth, *krh, *vrth, *attnh;
    cudaGetSymbolAddress((void**)&hsh,   g_hsh);
    cudaGetSymbolAddress((void**)&rhsh,  g_rhsh);
    cudaGetSymbolAddress((void**)&wth,   g_wth);
    cudaGetSymbolAddress((void**)&qlh,   g_qlh);
    cudaGetSymbolAddress((void**)&klh,   g_klh);
    cudaGetSymbolAddress((void**)&krlh,  g_krlh);
    cudaGetSymbolAddress((void**)&qh,    g_qh);
    cudaGetSymbolAddress((void**)&qroph, g_qroph);
    cudaGetSymbolAddress((void**)&kh,    g_kh);
    cudaGetSymbolAddress((void**)&vth,   g_vth);
    cudaGetSymbolAddress((void**)&krh,   g_krh);
    cudaGetSymbolAddress((void**)&vrth,  g_vrth);
    cudaGetSymbolAddress((void**)&attnh, g_attnh);

    cudaFuncSetAttribute(attn_fused,
                         cudaFuncAttributeMaxDynamicSharedMemorySize, ATT_SMEM);

    const float scale = 0.08838834764831845f;  // 1/sqrt(128)
    const size_t NW = (size_t)DIM * DIM;
    const int NT = T_LEN * DIM, NR = TR_LEN * DIM;

    // ---- activations -> half (one launch for hs + rhs) ----
    cvt2<<<NT / 1024 + NR / 1024, 256>>>(hs, hsh, NT, rhs, rhsh);

    // ---- all 6 weight transposes in one launch ----
    Src6 wsrc;
    wsrc.p[0] = Wq; wsrc.p[1] = Wk; wsrc.p[2] = Wv;
    wsrc.p[3] = Wkr; wsrc.p[4] = Wvr; wsrc.p[5] = Wo;
    transpose6_h<<<dim3(DIM / 32, DIM / 32, 6), dim3(32, 8)>>>(wsrc, wth);

    // ---- all 5 projections in ONE launch; q/k half, V directly transposed half ----
    GemmJob pj;
    pj.W[0] = wth + 0 * NW; pj.b[0] = bq;  pj.C[0] = qlh;  pj.mode[0] = 1;
    pj.W[1] = wth + 1 * NW; pj.b[1] = bk;  pj.C[1] = klh;  pj.mode[1] = 1;
    pj.W[2] = wth + 2 * NW; pj.b[2] = bv;  pj.C[2] = vth;  pj.mode[2] = 2;
    pj.W[3] = wth + 3 * NW; pj.b[3] = bkr; pj.C[3] = krlh; pj.mode[3] = 1;
    pj.W[4] = wth + 4 * NW; pj.b[4] = bvr; pj.C[4] = vrth; pj.mode[4] = 2;
    gemm_f16_j<<<3 * 384 + 2 * 96, 256, GEMM_SMEM>>>(hsh, rhsh, pj, 3);

    // ---- unified norm stage (q rmsrope + k rmsrope + ref-k rmsnorm, one launch) ----
    norm_all<<<2 * T_LEN + TR_LEN, 256>>>(qlh, klh, krlh, gq, gk, rcos, rsin,
                                          qh, qroph, kh, krh, scale);

    // ---- fused attention (ref + main), half output ----
    dim3 attn_grid(T_LEN / 128, NH);  // (32, 12)
    attn_fused<<<attn_grid, 256, ATT_SMEM>>>(qh, krh, vrth, TR_LEN,
                                             qroph, kh, vth, T_LEN, attnh);

    // ---- output projection (same kernel, nMain=1, float out) ----
    GemmJob po;
    po.W[0] = wth + 5 * NW; po.b[0] = bo; po.C[0] = out; po.mode[0] = 0;
    po.W[1] = po.W[0]; po.b[1] = po.b[0]; po.C[1] = out; po.mode[1] = 0;
    po.W[2] = po.W[0]; po.b[2] = po.b[0]; po.C[2] = out; po.mode[2] = 0;
    po.W[3] = po.W[0]; po.b[3] = po.b[0]; po.C[3] = out; po.mode[3] = 0;
    po.W[4] = po.W[0]; po.b[4] = po.b[0]; po.C[4] = out; po.mode[4] = 0;
    gemm_f16_j<<<384, 256, GEMM_SMEM>>>(attnh, attnh, po, 1);
}

// round 16
// speedup vs baseline: 1.5150x; 1.0025x over previous
#include <cuda_runtime.h>
#include <cuda_fp16.h>
#include <math.h>

#define T_LEN 4096
#define TR_LEN 1024
#define DIM 1536
#define NH 12
#define DH 128

// ---------------- scratch (device globals; no allocation allowed) ----------------
__device__ __half g_hsh[T_LEN * DIM];
__device__ __half g_rhsh[TR_LEN * DIM];
__device__ __half g_wth[6 * DIM * DIM];   // Wq,Wk,Wv,Wkr,Wvr,Wo transposed [n][k]
__device__ __half g_qlh[T_LEN * DIM];     // q_lin (half)
__device__ __half g_klh[T_LEN * DIM];     // k_lin (half)
__device__ __half g_krlh[TR_LEN * DIM];   // ref k_lin (half)
__device__ __half g_qh[T_LEN * DIM];      // rms(q)*scale (unroped, ref attn)
__device__ __half g_qroph[T_LEN * DIM];   // rope(rms(q))*scale
__device__ __half g_kh[T_LEN * DIM];      // rope(rms(k))
__device__ __half g_vth[DIM * T_LEN];     // V transposed [h*DH + d][t] (from GEMM)
__device__ __half g_krh[TR_LEN * DIM];    // rms(ref k)
__device__ __half g_vrth[DIM * TR_LEN];   // ref V transposed (from GEMM)
__device__ __half g_attnh[T_LEN * DIM];   // attention output (half, fused ref+main)

// ---------------- PTX helpers ----------------
__device__ __forceinline__ void mma_f16(float& c0, float& c1, float& c2, float& c3,
                                        unsigned a0, unsigned a1, unsigned a2, unsigned a3,
                                        unsigned b0, unsigned b1) {
    asm volatile(
        "mma.sync.aligned.m16n8k16.row.col.f32.f16.f16.f32 "
        "{%0,%1,%2,%3},{%4,%5,%6,%7},{%8,%9},{%0,%1,%2,%3};"
        : "+f"(c0), "+f"(c1), "+f"(c2), "+f"(c3)
        : "r"(a0), "r"(a1), "r"(a2), "r"(a3), "r"(b0), "r"(b1));
}
__device__ __forceinline__ void ldsm4(unsigned& r0, unsigned& r1, unsigned& r2, unsigned& r3,
                                      unsigned addr) {
    asm volatile("ldmatrix.sync.aligned.m8n8.x4.shared.b16 {%0,%1,%2,%3}, [%4];"
                 : "=r"(r0), "=r"(r1), "=r"(r2), "=r"(r3) : "r"(addr));
}
__device__ __forceinline__ void cp16(void* dst_smem, const void* src) {
    unsigned s = (unsigned)__cvta_generic_to_shared(dst_smem);
    asm volatile("cp.async.cg.shared.global [%0], [%1], 16;" :: "r"(s), "l"(src));
}
__device__ __forceinline__ void cp_commit() { asm volatile("cp.async.commit_group;"); }
__device__ __forceinline__ void cp_wait0()  { asm volatile("cp.async.wait_group 0;"); }
__device__ __forceinline__ unsigned h2u(__half2 h) { return *(unsigned*)&h; }

// ---------------- prep: 6 weight transposes + activation cvt in ONE launch ----------------
struct Src6 { const float* p[6]; };
#define TR_BLKS (48 * 48 * 6)   // 13824 transpose blocks

__global__ __launch_bounds__(256) void prep(
    Src6 s, __half* __restrict__ wth,
    const float* __restrict__ hs, __half* __restrict__ hsh, int na,
    const float* __restrict__ rhs, __half* __restrict__ rhsh)
{
    __shared__ float t[32][33];
    const int bx = blockIdx.x;
    const int tid = threadIdx.x;

    if (bx < TR_BLKS) {
        int z = bx / 2304, rem = bx % 2304;
        int c0 = (rem % 48) * 32, r0 = (rem / 48) * 32;
        const float* in = s.p[z];
        __half* out = wth + (size_t)z * DIM * DIM;
        int tx = tid & 31, ty = tid >> 5;
#pragma unroll
        for (int yy = 0; yy < 32; yy += 8)
            t[ty + yy][tx] = in[(size_t)(r0 + ty + yy) * DIM + c0 + tx];
        __syncthreads();
#pragma unroll
        for (int yy = 0; yy < 32; yy += 8)
            out[(size_t)(c0 + ty + yy) * DIM + r0 + tx] = __float2half_rn(t[tx][ty + yy]);
    } else {
        int b = bx - TR_BLKS;
        int nBlkA = na / 1024;
        const float* in;
        __half* out;
        int base;
        if (b < nBlkA) { in = hs; out = hsh; base = b * 1024; }
        else { in = rhs; out = rhsh; base = (b - nBlkA) * 1024; }
        int i4 = base + tid * 4;
        float4 v = *(const float4*)(in + i4);
        __half2 h0 = __float22half2_rn(make_float2(v.x, v.y));
        __half2 h1 = __float22half2_rn(make_float2(v.z, v.w));
        uint2 u; u.x = h2u(h0); u.y = h2u(h1);
        *(uint2*)(out + i4) = u;
    }
}

// ================= GEMM (fp16 mma), up to 5 outputs per launch =================
// Flat grid: first nMain*384 blocks are main tiles (A=Am, M=4096), rest ref (A=Ar, M=1024).
// Output modes: 0 = float row-major, 1 = half row-major, 2 = half TRANSPOSED [n][m].
#define GP 20   // smem pitch in unsigned (40 halves)
#define TP 136  // transpose-stage pitch in halves
struct GemmJob { const __half* W[5]; const float* b[5]; void* C[5]; int mode[5]; };

__global__ __launch_bounds__(256) void gemm_f16_j(
    const __half* __restrict__ Am, const __half* __restrict__ Ar,
    GemmJob p, int nMain)
{
    constexpr int OFF_A0 = 0;
    constexpr int OFF_A1 = 128 * GP;
    constexpr int OFF_B0 = 2 * 128 * GP;
    constexpr int OFF_B1 = OFF_B0 + 128 * GP;

    extern __shared__ unsigned smu[];
    const int x = blockIdx.x;
    const int mainTiles = nMain * 384;
    const __half* A;
    int which, tile, Mrows;
    if (x < mainTiles) { which = x / 384; tile = x % 384; A = Am; Mrows = T_LEN; }
    else { int r = x - mainTiles; which = nMain + r / 96; tile = r % 96; A = Ar; Mrows = TR_LEN; }

    const __half* Wt = p.W[which];
    const float* bias = p.b[which];
    const int bm = (tile / 12) * 128;
    const int bn = (tile % 12) * 128;
    const int tid = threadIdx.x;
    const int lane = tid & 31, warp = tid >> 5;
    const int g = lane >> 2, l = lane & 3;
    const int wm = (warp >> 2) * 64;
    const int wn = (warp & 3) * 32;

    float c[4][4][4];
#pragma unroll
    for (int mt = 0; mt < 4; mt++)
#pragma unroll
        for (int nt = 0; nt < 4; nt++)
#pragma unroll
            for (int i = 0; i < 4; i++) c[mt][nt][i] = 0.f;

    auto issue = [&](int kt, int buf) {
        unsigned* Au = smu + (buf ? OFF_A1 : OFF_A0);
        unsigned* Bu = smu + (buf ? OFF_B1 : OFF_B0);
        const int k0 = kt * 32;
#pragma unroll
        for (int u = 0; u < 2; u++) {
            int i = tid + u * 256;
            int r = i >> 2, c4 = i & 3;
            cp16(Au + r * GP + c4 * 4, A + (size_t)(bm + r) * DIM + k0 + c4 * 8);
        }
#pragma unroll
        for (int u = 0; u < 2; u++) {
            int i = tid + u * 256;
            int r = i >> 2, c4 = i & 3;
            cp16(Bu + r * GP + c4 * 4, Wt + (size_t)(bn + r) * DIM + k0 + c4 * 8);
        }
        cp_commit();
    };

    issue(0, 0);
    const int NKT = DIM / 32;  // 48
    for (int kt = 0; kt < NKT; kt++) {
        int buf = kt & 1;
        cp_wait0();
        __syncthreads();
        if (kt + 1 < NKT) issue(kt + 1, buf ^ 1);

        const unsigned* As = smu + (buf ? OFF_A1 : OFF_A0);
        const unsigned* Bs = smu + (buf ? OFF_B1 : OFF_B0);

#pragma unroll
        for (int kk = 0; kk < 2; kk++) {
            unsigned a[4][4];
#pragma unroll
            for (int mt = 0; mt < 4; mt++) {
                int row = wm + mt * 16;
                a[mt][0] = As[(row + g)     * GP + kk * 8 + l];
                a[mt][1] = As[(row + g + 8) * GP + kk * 8 + l];
                a[mt][2] = As[(row + g)     * GP + kk * 8 + l + 4];
                a[mt][3] = As[(row + g + 8) * GP + kk * 8 + l + 4];
            }
            unsigned b[4][2];
#pragma unroll
            for (int nt = 0; nt < 4; nt++) {
                int col = wn + nt * 8;
                b[nt][0] = Bs[(col + g) * GP + kk * 8 + l];
                b[nt][1] = Bs[(col + g) * GP + kk * 8 + l + 4];
            }
#pragma unroll
            for (int mt = 0; mt < 4; mt++)
#pragma unroll
                for (int nt = 0; nt < 4; nt++)
                    mma_f16(c[mt][nt][0], c[mt][nt][1], c[mt][nt][2], c[mt][nt][3],
                            a[mt][0], a[mt][1], a[mt][2], a[mt][3],
                            b[nt][0], b[nt][1]);
        }
    }

    const int mode = p.mode[which];
    if (mode == 2) {
        __syncthreads();
        __half* Tt = (__half*)smu;
#pragma unroll
        for (int mt = 0; mt < 4; mt++) {
#pragma unroll
            for (int nt = 0; nt < 4; nt++) {
                int rrow = wm + mt * 16 + g;
                int ccol = wn + nt * 8 + 2 * l;
                float b0 = bias[bn + ccol], b1 = bias[bn + ccol + 1];
                Tt[ccol * TP + rrow]           = __float2half_rn(c[mt][nt][0] + b0);
                Tt[(ccol + 1) * TP + rrow]     = __float2half_rn(c[mt][nt][1] + b1);
                Tt[ccol * TP + rrow + 8]       = __float2half_rn(c[mt][nt][2] + b0);
                Tt[(ccol + 1) * TP + rrow + 8] = __float2half_rn(c[mt][nt][3] + b1);
            }
        }
        __syncthreads();
        __half* Ch = (__half*)p.C[which];
#pragma unroll
        for (int u = 0; u < 4; u++) {
            int i = tid + u * 256;
            int r = i >> 3, c16 = (i & 7) * 16;
            uint4 v0 = *(uint4*)(Tt + r * TP + c16);
            uint4 v1 = *(uint4*)(Tt + r * TP + c16 + 8);
            __half* dst = Ch + (size_t)(bn + r) * Mrows + bm + c16;
            *(uint4*)dst = v0;
            *(uint4*)(dst + 8) = v1;
        }
    } else if (mode == 1) {
        __half* Ch = (__half*)p.C[which];
#pragma unroll
        for (int mt = 0; mt < 4; mt++) {
#pragma unroll
            for (int nt = 0; nt < 4; nt++) {
                int row = bm + wm + mt * 16 + g;
                int col = bn + wn + nt * 8 + 2 * l;
                float b0 = bias[col], b1 = bias[col + 1];
                *(__half2*)(Ch + (size_t)row * DIM + col) =
                    __float22half2_rn(make_float2(c[mt][nt][0] + b0, c[mt][nt][1] + b1));
                *(__half2*)(Ch + (size_t)(row + 8) * DIM + col) =
                    __float22half2_rn(make_float2(c[mt][nt][2] + b0, c[mt][nt][3] + b1));
            }
        }
    } else {
        float* C = (float*)p.C[which];
#pragma unroll
        for (int mt = 0; mt < 4; mt++) {
#pragma unroll
            for (int nt = 0; nt < 4; nt++) {
                int row = bm + wm + mt * 16 + g;
                int col = bn + wn + nt * 8 + 2 * l;
                float b0 = bias[col], b1 = bias[col + 1];
                C[(size_t)row * DIM + col]           = c[mt][nt][0] + b0;
                C[(size_t)row * DIM + col + 1]       = c[mt][nt][1] + b1;
                C[(size_t)(row + 8) * DIM + col]     = c[mt][nt][2] + b0;
                C[(size_t)(row + 8) * DIM + col + 1] = c[mt][nt][3] + b1;
            }
        }
    }
}

#define GEMM_SMEM ((4 * 128 * GP) * 4)   // 40960 B

// ---------------- unified norm stage (vectorized): q rmsrope / k rmsrope / ref-k rmsnorm ----
__device__ __forceinline__ float row_inv_rms(const __half* xr, int tid) {
    float ss = 0.f;
    for (int i = tid * 2; i < DIM; i += 512) {
        float2 v = __half22float2(*(const __half2*)(xr + i));
        ss += v.x * v.x + v.y * v.y;
    }
#pragma unroll
    for (int off = 16; off; off >>= 1) ss += __shfl_xor_sync(0xffffffffu, ss, off);
    __shared__ float wsum[8];
    __shared__ float inv_s;
    if ((tid & 31) == 0) wsum[tid >> 5] = ss;
    __syncthreads();
    if (tid == 0) {
        float t = 0.f;
#pragma unroll
        for (int w = 0; w < 8; w++) t += wsum[w];
        inv_s = rsqrtf(t / (float)DIM + 1e-6f);
    }
    __syncthreads();
    return inv_s;
}

__global__ __launch_bounds__(256) void norm_all(
    const __half* __restrict__ qlh, const __half* __restrict__ klh,
    const __half* __restrict__ krlh,
    const float* __restrict__ gq, const float* __restrict__ gk,
    const float* __restrict__ rc, const float* __restrict__ rs,
    __half* __restrict__ qh, __half* __restrict__ qroph,
    __half* __restrict__ kh, __half* __restrict__ krh, float scale)
{
    const int b = blockIdx.x;
    const int tid = threadIdx.x;

    if (b < 2 * T_LEN) {
        const int isQ = (b < T_LEN);
        const int row = isQ ? b : b - T_LEN;
        const __half* xr = (isQ ? qlh : klh) + (size_t)row * DIM;
        const float* g = isQ ? gq : gk;
        const float sc = isQ ? scale : 1.f;
        __half* outp = isQ ? qh : nullptr;
        __half* outr = isQ ? qroph : kh;
        float inv = row_inv_rms(xr, tid);
        const float* rcr = rc + row * (DH / 2);
        const float* rsr = rs + row * (DH / 2);
        for (int p = tid; p < DIM / 2; p += 256) {
            int i = p & 63;
            int d = (p >> 6) * DH + 2 * i;
            float2 xf = __half22float2(*(const __half2*)(xr + d));
            float2 gf = *(const float2*)(g + d);
            float e = xf.x * inv * gf.x;
            float o = xf.y * inv * gf.y;
            if (outp)
                *(__half2*)(outp + (size_t)row * DIM + d) =
                    __float22half2_rn(make_float2(e * sc, o * sc));
            float c = rcr[i];
            float s = rsr[i];
            *(__half2*)(outr + (size_t)row * DIM + d) =
                __float22half2_rn(make_float2((e * c - o * s) * sc, (e * s + o * c) * sc));
        }
    } else {
        const int row = b - 2 * T_LEN;
        const __half* xr = krlh + (size_t)row * DIM;
        float inv = row_inv_rms(xr, tid);
        for (int p = tid; p < DIM / 2; p += 256) {
            int d = 2 * p;
            float2 xf = __half22float2(*(const __half2*)(xr + d));
            float2 gf = *(const float2*)(gk + d);
            *(__half2*)(krh + (size_t)row * DIM + d) =
                __float22half2_rn(make_float2(xf.x * inv * gf.x, xf.y * inv * gf.y));
        }
    }
}

// ================= Fused flash attention (ref + main in one kernel) — proven ========
#define AQ 68
#define ATT_Q  0
#define ATT_K0 (128 * AQ)
#define ATT_K1 (ATT_K0 + 128 * AQ)
#define ATT_V0 (ATT_K1 + 128 * AQ)
#define ATT_V1 (ATT_V0 + 128 * AQ)
#define ATT_SMEM ((ATT_V1 + 128 * AQ) * 4)   // 174080 B

__global__ __launch_bounds__(256) void attn_fused(
    const __half* __restrict__ Q0, const __half* __restrict__ K0p,
    const __half* __restrict__ V0p, int Tk0,
    const __half* __restrict__ Q1, const __half* __restrict__ K1p,
    const __half* __restrict__ V1p, int Tk1,
    __half* __restrict__ Outh)
{
    extern __shared__ unsigned smu[];

    const int h = blockIdx.y;
    const int q0 = blockIdx.x * 128;
    const int tid = threadIdx.x;
    const int lane = tid & 31, warp = tid >> 5;
    const int g = lane >> 2, l = lane & 3;
    const unsigned sbase = (unsigned)__cvta_generic_to_shared(smu);

    const int ql_row = lane & 15;
    const unsigned ql_addr = sbase + (ATT_Q + (warp * 16 + ql_row) * AQ
                                      + ((lane & 16) ? 4 : 0)) * 4;
    const int bl_row  = (lane & 7) + ((lane & 16) ? 8 : 0);
    const int bl_colu = (lane & 8) ? 4 : 0;

    auto issue_Q = [&](const __half* Qp) {
#pragma unroll
        for (int u = 0; u < 8; u++) {
            int i = tid + u * 256;
            int r = i >> 4, c4 = i & 15;
            cp16(smu + ATT_Q + r * AQ + c4 * 4,
                 Qp + (size_t)(q0 + r) * DIM + h * DH + c4 * 8);
        }
    };
    auto issue_tile = [&](const __half* Kp, const __half* Vt, int Tk, int t, int buf) {
        unsigned* Ku = smu + (buf ? ATT_K1 : ATT_K0);
        unsigned* Vu = smu + (buf ? ATT_V1 : ATT_V0);
        const size_t krow = (size_t)(t * 128) * DIM + h * DH;
#pragma unroll
        for (int u = 0; u < 8; u++) {
            int i = tid + u * 256;
            int r = i >> 4, c4 = i & 15;
            cp16(Ku + r * AQ + c4 * 4, Kp + krow + (size_t)r * DIM + c4 * 8);
        }
#pragma unroll
        for (int u = 0; u < 8; u++) {
            int i = tid + u * 256;
            int r = i >> 4, c4 = i & 15;
            cp16(Vu + r * AQ + c4 * 4,
                 Vt + (size_t)(h * DH + r) * Tk + t * 128 + c4 * 8);
        }
        cp_commit();
    };

    float o[16][4];
    float m0, m1, l0, l1;
    unsigned qa[8][4];
    unsigned stash[16][2];

#pragma unroll
    for (int ph = 0; ph < 2; ph++) {
        const __half* Qp = ph ? Q1 : Q0;
        const __half* Kp = ph ? K1p : K0p;
        const __half* Vp = ph ? V1p : V0p;
        const int Tk = ph ? Tk1 : Tk0;
        const int ntiles = Tk / 128;

#pragma unroll
        for (int nt = 0; nt < 16; nt++)
#pragma unroll
            for (int i = 0; i < 4; i++) o[nt][i] = 0.f;
        m0 = m1 = -1e30f;
        l0 = l1 = 0.f;

        issue_Q(Qp);
        issue_tile(Kp, Vp, Tk, 0, 0);

        for (int t = 0; t < ntiles; t++) {
            int buf = t & 1;
            cp_wait0();
            __syncthreads();
            if (t + 1 < ntiles) issue_tile(Kp, Vp, Tk, t + 1, buf ^ 1);

            if (t == 0) {
#pragma unroll
                for (int kk = 0; kk < 8; kk++)
                    ldsm4(qa[kk][0], qa[kk][1], qa[kk][2], qa[kk][3], ql_addr + kk * 32);
            }

            const unsigned koff = sbase + (buf ? ATT_K1 : ATT_K0) * 4;
            const unsigned voff = sbase + (buf ? ATT_V1 : ATT_V0) * 4;

#pragma unroll
            for (int st = 0; st < 2; st++) {
                float s[8][4];
#pragma unroll
                for (int nt = 0; nt < 8; nt++)
#pragma unroll
                    for (int i = 0; i < 4; i++) s[nt][i] = 0.f;

#pragma unroll
                for (int kk = 0; kk < 8; kk++) {
                    unsigned kb[4][4];
#pragma unroll
                    for (int j = 0; j < 4; j++)
                        ldsm4(kb[j][0], kb[j][1], kb[j][2], kb[j][3],
                              koff + ((st * 64 + j * 16 + bl_row) * AQ + kk * 8 + bl_colu) * 4);
#pragma unroll
                    for (int j = 0; j < 4; j++) {
                        mma_f16(s[2*j][0], s[2*j][1], s[2*j][2], s[2*j][3],
                                qa[kk][0], qa[kk][1], qa[kk][2], qa[kk][3], kb[j][0], kb[j][1]);
                        mma_f16(s[2*j+1][0], s[2*j+1][1], s[2*j+1][2], s[2*j+1][3],
                                qa[kk][0], qa[kk][1], qa[kk][2], qa[kk][3], kb[j][2], kb[j][3]);
                    }
                }

                float tm0 = -1e30f, tm1 = -1e30f;
#pragma unroll
                for (int nt = 0; nt < 8; nt++) {
                    tm0 = fmaxf(tm0, fmaxf(s[nt][0], s[nt][1]));
                    tm1 = fmaxf(tm1, fmaxf(s[nt][2], s[nt][3]));
                }
                tm0 = fmaxf(tm0, __shfl_xor_sync(0xffffffffu, tm0, 1));
                tm0 = fmaxf(tm0, __shfl_xor_sync(0xffffffffu, tm0, 2));
                tm1 = fmaxf(tm1, __shfl_xor_sync(0xffffffffu, tm1, 1));
                tm1 = fmaxf(tm1, __shfl_xor_sync(0xffffffffu, tm1, 2));
                float mn0 = fmaxf(m0, tm0), mn1 = fmaxf(m1, tm1);
                float al0 = __expf(m0 - mn0), al1 = __expf(m1 - mn1);
                m0 = mn0; m1 = mn1;

                unsigned pa[4][4];
                float sum0 = 0.f, sum1 = 0.f;
#pragma unroll
                for (int nt = 0; nt < 8; nt++) {
                    float p0 = __expf(s[nt][0] - mn0);
                    float p1 = __expf(s[nt][1] - mn0);
                    float p2 = __expf(s[nt][2] - mn1);
                    float p3 = __expf(s[nt][3] - mn1);
                    sum0 += p0 + p1;
                    sum1 += p2 + p3;
                    unsigned lo = h2u(__float22half2_rn(make_float2(p0, p1)));
                    unsigned hi = h2u(__float22half2_rn(make_float2(p2, p3)));
                    int kt = nt >> 1;
                    if ((nt & 1) == 0) { pa[kt][0] = lo; pa[kt][1] = hi; }
                    else               { pa[kt][2] = lo; pa[kt][3] = hi; }
                }
                sum0 += __shfl_xor_sync(0xffffffffu, sum0, 1);
                sum0 += __shfl_xor_sync(0xffffffffu, sum0, 2);
                sum1 += __shfl_xor_sync(0xffffffffu, sum1, 1);
                sum1 += __shfl_xor_sync(0xffffffffu, sum1, 2);
                l0 = l0 * al0 + sum0;
                l1 = l1 * al1 + sum1;
#pragma unroll
                for (int nt = 0; nt < 16; nt++) {
                    o[nt][0] *= al0; o[nt][1] *= al0;
                    o[nt][2] *= al1; o[nt][3] *= al1;
                }

#pragma unroll
                for (int kt = 0; kt < 4; kt++) {
                    unsigned vb[8][4];
#pragma unroll
                    for (int j = 0; j < 8; j++)
                        ldsm4(vb[j][0], vb[j][1], vb[j][2], vb[j][3],
                              voff + ((j * 16 + bl_row) * AQ + st * 32 + kt * 8 + bl_colu) * 4);
#pragma unroll
                    for (int j = 0; j < 8; j++) {
                        mma_f16(o[2*j][0], o[2*j][1], o[2*j][2], o[2*j][3],
                                pa[kt][0], pa[kt][1], pa[kt][2], pa[kt][3], vb[j][0], vb[j][1]);
                        mma_f16(o[2*j+1][0], o[2*j+1][1], o[2*j+1][2], o[2*j+1][3],
                                pa[kt][0], pa[kt][1], pa[kt][2], pa[kt][3], vb[j][2], vb[j][3]);
                    }
                }
            }
        }

        if (ph == 0) {
            float inv0 = 1.f / l0, inv1 = 1.f / l1;
#pragma unroll
            for (int nt = 0; nt < 16; nt++) {
                stash[nt][0] = h2u(__float22half2_rn(
                    make_float2(o[nt][0] * inv0, o[nt][1] * inv0)));
                stash[nt][1] = h2u(__float22half2_rn(
                    make_float2(o[nt][2] * inv1, o[nt][3] * inv1)));
            }
        }
    }

    float inv0 = 1.f / l0, inv1 = 1.f / l1;
    int row0 = q0 + warp * 16 + g;
    int row1 = row0 + 8;
#pragma unroll
    for (int nt = 0; nt < 16; nt++) {
        int col = h * DH + nt * 8 + 2 * l;
        float2 r0 = __half22float2(*(__half2*)&stash[nt][0]);
        float2 r1 = __half22float2(*(__half2*)&stash[nt][1]);
        __half2 w0 = __float22half2_rn(
            make_float2(r0.x + o[nt][0] * inv0, r0.y + o[nt][1] * inv0));
        __half2 w1 = __float22half2_rn(
            make_float2(r1.x + o[nt][2] * inv1, r1.y + o[nt][3] * inv1));
        *(__half2*)(Outh + (size_t)row0 * DIM + col) = w0;
        *(__half2*)(Outh + (size_t)row1 * DIM + col) = w1;
    }
}

// ---------------- launch ----------------
extern "C" void kernel_launch(void* const* d_in, const int* in_sizes, int n_in,
                              void* d_out, int out_size)
{
    const float* hs   = (const float*)d_in[0];
    const float* rhs  = (const float*)d_in[1];
    const float* rcos = (const float*)d_in[2];
    const float* rsin = (const float*)d_in[3];
    const float* Wq   = (const float*)d_in[4];
    const float* bq   = (const float*)d_in[5];
    const float* Wk   = (const float*)d_in[6];
    const float* bk   = (const float*)d_in[7];
    const float* Wv   = (const float*)d_in[8];
    const float* bv   = (const float*)d_in[9];
    const float* Wkr  = (const float*)d_in[10];
    const float* bkr  = (const float*)d_in[11];
    const float* Wvr  = (const float*)d_in[12];
    const float* bvr  = (const float*)d_in[13];
    const float* Wo   = (const float*)d_in[14];
    const float* bo   = (const float*)d_in[15];
    const float* gq   = (const float*)d_in[16];
    const float* gk   = (const float*)d_in[17];
    float* out = (float*)d_out;

    __half *hsh, *rhsh, *wth, *qlh, *klh, *krlh, *qh, *qroph, *kh, *vth, *krh, *vrth, *attnh;
    cudaGetSymbolAddress((void**)&hsh,   g_hsh);
    cudaGetSymbolAddress((void**)&rhsh,  g_rhsh);
    cudaGetSymbolAddress((void**)&wth,   g_wth);
    cudaGetSymbolAddress((void**)&qlh,   g_qlh);
    cudaGetSymbolAddress((void**)&klh,   g_klh);
    cudaGetSymbolAddress((void**)&krlh,  g_krlh);
    cudaGetSymbolAddress((void**)&qh,    g_qh);
    cudaGetSymbolAddress((void**)&qroph, g_qroph);
    cudaGetSymbolAddress((void**)&kh,    g_kh);
    cudaGetSymbolAddress((void**)&vth,   g_vth);
    cudaGetSymbolAddress((void**)&krh,   g_krh);
    cudaGetSymbolAddress((void**)&vrth,  g_vrth);
    cudaGetSymbolAddress((void**)&attnh, g_attnh);

    cudaFuncSetAttribute(attn_fused,
                         cudaFuncAttributeMaxDynamicSharedMemorySize, ATT_SMEM);

    const float scale = 0.08838834764831845f;  // 1/sqrt(128)
    const size_t NW = (size_t)DIM * DIM;
    const int NT = T_LEN * DIM, NR = TR_LEN * DIM;

    // ---- prep: weight transposes + activation cvt in one launch ----
    Src6 wsrc;
    wsrc.p[0] = Wq; wsrc.p[1] = Wk; wsrc.p[2] = Wv;
    wsrc.p[3] = Wkr; wsrc.p[4] = Wvr; wsrc.p[5] = Wo;
    prep<<<TR_BLKS + NT / 1024 + NR / 1024, 256>>>(wsrc, wth, hs, hsh, NT, rhs, rhsh);

    // ---- all 5 projections in ONE launch; q/k half, V directly transposed half ----
    GemmJob pj;
    pj.W[0] = wth + 0 * NW; pj.b[0] = bq;  pj.C[0] = qlh;  pj.mode[0] = 1;
    pj.W[1] = wth + 1 * NW; pj.b[1] = bk;  pj.C[1] = klh;  pj.mode[1] = 1;
    pj.W[2] = wth + 2 * NW; pj.b[2] = bv;  pj.C[2] = vth;  pj.mode[2] = 2;
    pj.W[3] = wth + 3 * NW; pj.b[3] = bkr; pj.C[3] = krlh; pj.mode[3] = 1;
    pj.W[4] = wth + 4 * NW; pj.b[4] = bvr; pj.C[4] = vrth; pj.mode[4] = 2;
    gemm_f16_j<<<3 * 384 + 2 * 96, 256, GEMM_SMEM>>>(hsh, rhsh, pj, 3);

    // ---- unified norm stage (q rmsrope + k rmsrope + ref-k rmsnorm, one launch) ----
    norm_all<<<2 * T_LEN + TR_LEN, 256>>>(qlh, klh, krlh, gq, gk, rcos, rsin,
                                          qh, qroph, kh, krh, scale);

    // ---- fused attention (ref + main), half output ----
    dim3 attn_grid(T_LEN / 128, NH);  // (32, 12)
    attn_fused<<<attn_grid, 256, ATT_SMEM>>>(qh, krh, vrth, TR_LEN,
                                             qroph, kh, vth, T_LEN, attnh);

    // ---- output projection (same kernel, nMain=1, float out) ----
    GemmJob po;
    po.W[0] = wth + 5 * NW; po.b[0] = bo; po.C[0] = out; po.mode[0] = 0;
    po.W[1] = po.W[0]; po.b[1] = po.b[0]; po.C[1] = out; po.mode[1] = 0;
    po.W[2] = po.W[0]; po.b[2] = po.b[0]; po.C[2] = out; po.mode[2] = 0;
    po.W[3] = po.W[0]; po.b[3] = po.b[0]; po.C[3] = out; po.mode[3] = 0;
    po.W[4] = po.W[0]; po.b[4] = po.b[0]; po.C[4] = out; po.mode[4] = 0;
    gemm_f16_j<<<384, 256, GEMM_SMEM>>>(attnh, attnh, po, 1);
}

// round 17
// speedup vs baseline: 1.5152x; 1.0001x over previous
#include <cuda_runtime.h>
#include <cuda_fp16.h>
#include <math.h>

#define T_LEN 4096
#define TR_LEN 1024
#define DIM 1536
#define NH 12
#define DH 128

// ---------------- scratch (device globals; no allocation allowed) ----------------
__device__ __half g_hsh[T_LEN * DIM];
__device__ __half g_rhsh[TR_LEN * DIM];
__device__ __half g_wth[6 * DIM * DIM];   // Wq,Wk,Wv,Wkr,Wvr,Wo transposed [n][k]
__device__ __half g_qlh[T_LEN * DIM];     // q_lin (half)
__device__ __half g_klh[T_LEN * DIM];     // k_lin (half)
__device__ __half g_krlh[TR_LEN * DIM];   // ref k_lin (half)
__device__ __half g_qh[T_LEN * DIM];      // rms(q)*scale (unroped, ref attn)
__device__ __half g_qroph[T_LEN * DIM];   // rope(rms(q))*scale
__device__ __half g_kh[T_LEN * DIM];      // rope(rms(k))
__device__ __half g_vth[DIM * T_LEN];     // V transposed [h*DH + d][t] (from GEMM)
__device__ __half g_krh[TR_LEN * DIM];    // rms(ref k)
__device__ __half g_vrth[DIM * TR_LEN];   // ref V transposed (from GEMM)
__device__ __half g_attnh[T_LEN * DIM];   // attention output (half; ref staged then summed)

// ---------------- PTX helpers ----------------
__device__ __forceinline__ void mma_f16(float& c0, float& c1, float& c2, float& c3,
                                        unsigned a0, unsigned a1, unsigned a2, unsigned a3,
                                        unsigned b0, unsigned b1) {
    asm volatile(
        "mma.sync.aligned.m16n8k16.row.col.f32.f16.f16.f32 "
        "{%0,%1,%2,%3},{%4,%5,%6,%7},{%8,%9},{%0,%1,%2,%3};"
        : "+f"(c0), "+f"(c1), "+f"(c2), "+f"(c3)
        : "r"(a0), "r"(a1), "r"(a2), "r"(a3), "r"(b0), "r"(b1));
}
__device__ __forceinline__ void ldsm4(unsigned& r0, unsigned& r1, unsigned& r2, unsigned& r3,
                                      unsigned addr) {
    asm volatile("ldmatrix.sync.aligned.m8n8.x4.shared.b16 {%0,%1,%2,%3}, [%4];"
                 : "=r"(r0), "=r"(r1), "=r"(r2), "=r"(r3) : "r"(addr));
}
__device__ __forceinline__ void cp16(void* dst_smem, const void* src) {
    unsigned s = (unsigned)__cvta_generic_to_shared(dst_smem);
    asm volatile("cp.async.cg.shared.global [%0], [%1], 16;" :: "r"(s), "l"(src));
}
__device__ __forceinline__ void cp_commit() { asm volatile("cp.async.commit_group;"); }
__device__ __forceinline__ void cp_wait0()  { asm volatile("cp.async.wait_group 0;"); }
__device__ __forceinline__ unsigned h2u(__half2 h) { return *(unsigned*)&h; }

// ---------------- prep: 6 weight transposes + activation cvt in ONE launch ----------------
struct Src6 { const float* p[6]; };
#define TR_BLKS (48 * 48 * 6)   // 13824 transpose blocks

__global__ __launch_bounds__(256) void prep(
    Src6 s, __half* __restrict__ wth,
    const float* __restrict__ hs, __half* __restrict__ hsh, int na,
    const float* __restrict__ rhs, __half* __restrict__ rhsh)
{
    __shared__ float t[32][33];
    const int bx = blockIdx.x;
    const int tid = threadIdx.x;

    if (bx < TR_BLKS) {
        int z = bx / 2304, rem = bx % 2304;
        int c0 = (rem % 48) * 32, r0 = (rem / 48) * 32;
        const float* in = s.p[z];
        __half* out = wth + (size_t)z * DIM * DIM;
        int tx = tid & 31, ty = tid >> 5;
#pragma unroll
        for (int yy = 0; yy < 32; yy += 8)
            t[ty + yy][tx] = in[(size_t)(r0 + ty + yy) * DIM + c0 + tx];
        __syncthreads();
#pragma unroll
        for (int yy = 0; yy < 32; yy += 8)
            out[(size_t)(c0 + ty + yy) * DIM + r0 + tx] = __float2half_rn(t[tx][ty + yy]);
    } else {
        int b = bx - TR_BLKS;
        int nBlkA = na / 1024;
        const float* in;
        __half* out;
        int base;
        if (b < nBlkA) { in = hs; out = hsh; base = b * 1024; }
        else { in = rhs; out = rhsh; base = (b - nBlkA) * 1024; }
        int i4 = base + tid * 4;
        float4 v = *(const float4*)(in + i4);
        __half2 h0 = __float22half2_rn(make_float2(v.x, v.y));
        __half2 h1 = __float22half2_rn(make_float2(v.z, v.w));
        uint2 u; u.x = h2u(h0); u.y = h2u(h1);
        *(uint2*)(out + i4) = u;
    }
}

// ================= GEMM (fp16 mma), up to 5 outputs per launch =================
// Flat grid: first nMain*384 blocks are main tiles (A=Am, M=4096), rest ref (A=Ar, M=1024).
// Output modes: 0 = float row-major, 1 = half row-major, 2 = half TRANSPOSED [n][m].
#define GP 20   // smem pitch in unsigned (40 halves)
#define TP 136  // transpose-stage pitch in halves
struct GemmJob { const __half* W[5]; const float* b[5]; void* C[5]; int mode[5]; };

__global__ __launch_bounds__(256) void gemm_f16_j(
    const __half* __restrict__ Am, const __half* __restrict__ Ar,
    GemmJob p, int nMain)
{
    constexpr int OFF_A0 = 0;
    constexpr int OFF_A1 = 128 * GP;
    constexpr int OFF_B0 = 2 * 128 * GP;
    constexpr int OFF_B1 = OFF_B0 + 128 * GP;

    extern __shared__ unsigned smu[];
    const int x = blockIdx.x;
    const int mainTiles = nMain * 384;
    const __half* A;
    int which, tile, Mrows;
    if (x < mainTiles) { which = x / 384; tile = x % 384; A = Am; Mrows = T_LEN; }
    else { int r = x - mainTiles; which = nMain + r / 96; tile = r % 96; A = Ar; Mrows = TR_LEN; }

    const __half* Wt = p.W[which];
    const float* bias = p.b[which];
    const int bm = (tile / 12) * 128;
    const int bn = (tile % 12) * 128;
    const int tid = threadIdx.x;
    const int lane = tid & 31, warp = tid >> 5;
    const int g = lane >> 2, l = lane & 3;
    const int wm = (warp >> 2) * 64;
    const int wn = (warp & 3) * 32;

    float c[4][4][4];
#pragma unroll
    for (int mt = 0; mt < 4; mt++)
#pragma unroll
        for (int nt = 0; nt < 4; nt++)
#pragma unroll
            for (int i = 0; i < 4; i++) c[mt][nt][i] = 0.f;

    auto issue = [&](int kt, int buf) {
        unsigned* Au = smu + (buf ? OFF_A1 : OFF_A0);
        unsigned* Bu = smu + (buf ? OFF_B1 : OFF_B0);
        const int k0 = kt * 32;
#pragma unroll
        for (int u = 0; u < 2; u++) {
            int i = tid + u * 256;
            int r = i >> 2, c4 = i & 3;
            cp16(Au + r * GP + c4 * 4, A + (size_t)(bm + r) * DIM + k0 + c4 * 8);
        }
#pragma unroll
        for (int u = 0; u < 2; u++) {
            int i = tid + u * 256;
            int r = i >> 2, c4 = i & 3;
            cp16(Bu + r * GP + c4 * 4, Wt + (size_t)(bn + r) * DIM + k0 + c4 * 8);
        }
        cp_commit();
    };

    issue(0, 0);
    const int NKT = DIM / 32;  // 48
    for (int kt = 0; kt < NKT; kt++) {
        int buf = kt & 1;
        cp_wait0();
        __syncthreads();
        if (kt + 1 < NKT) issue(kt + 1, buf ^ 1);

        const unsigned* As = smu + (buf ? OFF_A1 : OFF_A0);
        const unsigned* Bs = smu + (buf ? OFF_B1 : OFF_B0);

#pragma unroll
        for (int kk = 0; kk < 2; kk++) {
            unsigned a[4][4];
#pragma unroll
            for (int mt = 0; mt < 4; mt++) {
                int row = wm + mt * 16;
                a[mt][0] = As[(row + g)     * GP + kk * 8 + l];
                a[mt][1] = As[(row + g + 8) * GP + kk * 8 + l];
                a[mt][2] = As[(row + g)     * GP + kk * 8 + l + 4];
                a[mt][3] = As[(row + g + 8) * GP + kk * 8 + l + 4];
            }
            unsigned b[4][2];
#pragma unroll
            for (int nt = 0; nt < 4; nt++) {
                int col = wn + nt * 8;
                b[nt][0] = Bs[(col + g) * GP + kk * 8 + l];
                b[nt][1] = Bs[(col + g) * GP + kk * 8 + l + 4];
            }
#pragma unroll
            for (int mt = 0; mt < 4; mt++)
#pragma unroll
                for (int nt = 0; nt < 4; nt++)
                    mma_f16(c[mt][nt][0], c[mt][nt][1], c[mt][nt][2], c[mt][nt][3],
                            a[mt][0], a[mt][1], a[mt][2], a[mt][3],
                            b[nt][0], b[nt][1]);
        }
    }

    const int mode = p.mode[which];
    if (mode == 2) {
        __syncthreads();
        __half* Tt = (__half*)smu;
#pragma unroll
        for (int mt = 0; mt < 4; mt++) {
#pragma unroll
            for (int nt = 0; nt < 4; nt++) {
                int rrow = wm + mt * 16 + g;
                int ccol = wn + nt * 8 + 2 * l;
                float b0 = bias[bn + ccol], b1 = bias[bn + ccol + 1];
                Tt[ccol * TP + rrow]           = __float2half_rn(c[mt][nt][0] + b0);
                Tt[(ccol + 1) * TP + rrow]     = __float2half_rn(c[mt][nt][1] + b1);
                Tt[ccol * TP + rrow + 8]       = __float2half_rn(c[mt][nt][2] + b0);
                Tt[(ccol + 1) * TP + rrow + 8] = __float2half_rn(c[mt][nt][3] + b1);
            }
        }
        __syncthreads();
        __half* Ch = (__half*)p.C[which];
#pragma unroll
        for (int u = 0; u < 4; u++) {
            int i = tid + u * 256;
            int r = i >> 3, c16 = (i & 7) * 16;
            uint4 v0 = *(uint4*)(Tt + r * TP + c16);
            uint4 v1 = *(uint4*)(Tt + r * TP + c16 + 8);
            __half* dst = Ch + (size_t)(bn + r) * Mrows + bm + c16;
            *(uint4*)dst = v0;
            *(uint4*)(dst + 8) = v1;
        }
    } else if (mode == 1) {
        __half* Ch = (__half*)p.C[which];
#pragma unroll
        for (int mt = 0; mt < 4; mt++) {
#pragma unroll
            for (int nt = 0; nt < 4; nt++) {
                int row = bm + wm + mt * 16 + g;
                int col = bn + wn + nt * 8 + 2 * l;
                float b0 = bias[col], b1 = bias[col + 1];
                *(__half2*)(Ch + (size_t)row * DIM + col) =
                    __float22half2_rn(make_float2(c[mt][nt][0] + b0, c[mt][nt][1] + b1));
                *(__half2*)(Ch + (size_t)(row + 8) * DIM + col) =
                    __float22half2_rn(make_float2(c[mt][nt][2] + b0, c[mt][nt][3] + b1));
            }
        }
    } else {
        float* C = (float*)p.C[which];
#pragma unroll
        for (int mt = 0; mt < 4; mt++) {
#pragma unroll
            for (int nt = 0; nt < 4; nt++) {
                int row = bm + wm + mt * 16 + g;
                int col = bn + wn + nt * 8 + 2 * l;
                float b0 = bias[col], b1 = bias[col + 1];
                C[(size_t)row * DIM + col]           = c[mt][nt][0] + b0;
                C[(size_t)row * DIM + col + 1]       = c[mt][nt][1] + b1;
                C[(size_t)(row + 8) * DIM + col]     = c[mt][nt][2] + b0;
                C[(size_t)(row + 8) * DIM + col + 1] = c[mt][nt][3] + b1;
            }
        }
    }
}

#define GEMM_SMEM ((4 * 128 * GP) * 4)   // 40960 B

// ---------------- unified norm stage (vectorized) ----------------
__device__ __forceinline__ float row_inv_rms(const __half* xr, int tid) {
    float ss = 0.f;
    for (int i = tid * 2; i < DIM; i += 512) {
        float2 v = __half22float2(*(const __half2*)(xr + i));
        ss += v.x * v.x + v.y * v.y;
    }
#pragma unroll
    for (int off = 16; off; off >>= 1) ss += __shfl_xor_sync(0xffffffffu, ss, off);
    __shared__ float wsum[8];
    __shared__ float inv_s;
    if ((tid & 31) == 0) wsum[tid >> 5] = ss;
    __syncthreads();
    if (tid == 0) {
        float t = 0.f;
#pragma unroll
        for (int w = 0; w < 8; w++) t += wsum[w];
        inv_s = rsqrtf(t / (float)DIM + 1e-6f);
    }
    __syncthreads();
    return inv_s;
}

__global__ __launch_bounds__(256) void norm_all(
    const __half* __restrict__ qlh, const __half* __restrict__ klh,
    const __half* __restrict__ krlh,
    const float* __restrict__ gq, const float* __restrict__ gk,
    const float* __restrict__ rc, const float* __restrict__ rs,
    __half* __restrict__ qh, __half* __restrict__ qroph,
    __half* __restrict__ kh, __half* __restrict__ krh, float scale)
{
    const int b = blockIdx.x;
    const int tid = threadIdx.x;

    if (b < 2 * T_LEN) {
        const int isQ = (b < T_LEN);
        const int row = isQ ? b : b - T_LEN;
        const __half* xr = (isQ ? qlh : klh) + (size_t)row * DIM;
        const float* g = isQ ? gq : gk;
        const float sc = isQ ? scale : 1.f;
        __half* outp = isQ ? qh : nullptr;
        __half* outr = isQ ? qroph : kh;
        float inv = row_inv_rms(xr, tid);
        const float* rcr = rc + row * (DH / 2);
        const float* rsr = rs + row * (DH / 2);
        for (int p = tid; p < DIM / 2; p += 256) {
            int i = p & 63;
            int d = (p >> 6) * DH + 2 * i;
            float2 xf = __half22float2(*(const __half2*)(xr + d));
            float2 gf = *(const float2*)(g + d);
            float e = xf.x * inv * gf.x;
            float o = xf.y * inv * gf.y;
            if (outp)
                *(__half2*)(outp + (size_t)row * DIM + d) =
                    __float22half2_rn(make_float2(e * sc, o * sc));
            float c = rcr[i];
            float s = rsr[i];
            *(__half2*)(outr + (size_t)row * DIM + d) =
                __float22half2_rn(make_float2((e * c - o * s) * sc, (e * s + o * c) * sc));
        }
    } else {
        const int row = b - 2 * T_LEN;
        const __half* xr = krlh + (size_t)row * DIM;
        float inv = row_inv_rms(xr, tid);
        for (int p = tid; p < DIM / 2; p += 256) {
            int d = 2 * p;
            float2 xf = __half22float2(*(const __half2*)(xr + d));
            float2 gf = *(const float2*)(gk + d);
            *(__half2*)(krh + (size_t)row * DIM + d) =
                __float22half2_rn(make_float2(xf.x * inv * gf.x, xf.y * inv * gf.y));
        }
    }
}

// ================= Fused flash attention (ref + main; ref staged via global) ========
#define AQ 68
#define ATT_Q  0
#define ATT_K0 (128 * AQ)
#define ATT_K1 (ATT_K0 + 128 * AQ)
#define ATT_V0 (ATT_K1 + 128 * AQ)
#define ATT_V1 (ATT_V0 + 128 * AQ)
#define ATT_SMEM ((ATT_V1 + 128 * AQ) * 4)   // 174080 B

__global__ __launch_bounds__(256) void attn_fused(
    const __half* __restrict__ Q0, const __half* __restrict__ K0p,
    const __half* __restrict__ V0p, int Tk0,
    const __half* __restrict__ Q1, const __half* __restrict__ K1p,
    const __half* __restrict__ V1p, int Tk1,
    __half* __restrict__ Outh)
{
    extern __shared__ unsigned smu[];

    const int h = blockIdx.y;
    const int q0 = blockIdx.x * 128;
    const int tid = threadIdx.x;
    const int lane = tid & 31, warp = tid >> 5;
    const int g = lane >> 2, l = lane & 3;
    const unsigned sbase = (unsigned)__cvta_generic_to_shared(smu);

    const int ql_row = lane & 15;
    const unsigned ql_addr = sbase + (ATT_Q + (warp * 16 + ql_row) * AQ
                                      + ((lane & 16) ? 4 : 0)) * 4;
    const int bl_row  = (lane & 7) + ((lane & 16) ? 8 : 0);
    const int bl_colu = (lane & 8) ? 4 : 0;

    auto issue_Q = [&](const __half* Qp) {
#pragma unroll
        for (int u = 0; u < 8; u++) {
            int i = tid + u * 256;
            int r = i >> 4, c4 = i & 15;
            cp16(smu + ATT_Q + r * AQ + c4 * 4,
                 Qp + (size_t)(q0 + r) * DIM + h * DH + c4 * 8);
        }
    };
    auto issue_tile = [&](const __half* Kp, const __half* Vt, int Tk, int t, int buf) {
        unsigned* Ku = smu + (buf ? ATT_K1 : ATT_K0);
        unsigned* Vu = smu + (buf ? ATT_V1 : ATT_V0);
        const size_t krow = (size_t)(t * 128) * DIM + h * DH;
#pragma unroll
        for (int u = 0; u < 8; u++) {
            int i = tid + u * 256;
            int r = i >> 4, c4 = i & 15;
            cp16(Ku + r * AQ + c4 * 4, Kp + krow + (size_t)r * DIM + c4 * 8);
        }
#pragma unroll
        for (int u = 0; u < 8; u++) {
            int i = tid + u * 256;
            int r = i >> 4, c4 = i & 15;
            cp16(Vu + r * AQ + c4 * 4,
                 Vt + (size_t)(h * DH + r) * Tk + t * 128 + c4 * 8);
        }
        cp_commit();
    };

    float o[16][4];
    float m0, m1, l0, l1;
    unsigned qa[8][4];

#pragma unroll
    for (int ph = 0; ph < 2; ph++) {
        const __half* Qp = ph ? Q1 : Q0;
        const __half* Kp = ph ? K1p : K0p;
        const __half* Vp = ph ? V1p : V0p;
        const int Tk = ph ? Tk1 : Tk0;
        const int ntiles = Tk / 128;

#pragma unroll
        for (int nt = 0; nt < 16; nt++)
#pragma unroll
            for (int i = 0; i < 4; i++) o[nt][i] = 0.f;
        m0 = m1 = -1e30f;
        l0 = l1 = 0.f;

        issue_Q(Qp);
        issue_tile(Kp, Vp, Tk, 0, 0);

        for (int t = 0; t < ntiles; t++) {
            int buf = t & 1;
            cp_wait0();
            __syncthreads();
            if (t + 1 < ntiles) issue_tile(Kp, Vp, Tk, t + 1, buf ^ 1);

            if (t == 0) {
#pragma unroll
                for (int kk = 0; kk < 8; kk++)
                    ldsm4(qa[kk][0], qa[kk][1], qa[kk][2], qa[kk][3], ql_addr + kk * 32);
            }

            const unsigned koff = sbase + (buf ? ATT_K1 : ATT_K0) * 4;
            const unsigned voff = sbase + (buf ? ATT_V1 : ATT_V0) * 4;

#pragma unroll
            for (int st = 0; st < 2; st++) {
                float s[8][4];
#pragma unroll
                for (int nt = 0; nt < 8; nt++)
#pragma unroll
                    for (int i = 0; i < 4; i++) s[nt][i] = 0.f;

#pragma unroll
                for (int kk = 0; kk < 8; kk++) {
                    unsigned kb[4][4];
#pragma unroll
                    for (int j = 0; j < 4; j++)
                        ldsm4(kb[j][0], kb[j][1], kb[j][2], kb[j][3],
                              koff + ((st * 64 + j * 16 + bl_row) * AQ + kk * 8 + bl_colu) * 4);
#pragma unroll
                    for (int j = 0; j < 4; j++) {
                        mma_f16(s[2*j][0], s[2*j][1], s[2*j][2], s[2*j][3],
                                qa[kk][0], qa[kk][1], qa[kk][2], qa[kk][3], kb[j][0], kb[j][1]);
                        mma_f16(s[2*j+1][0], s[2*j+1][1], s[2*j+1][2], s[2*j+1][3],
                                qa[kk][0], qa[kk][1], qa[kk][2], qa[kk][3], kb[j][2], kb[j][3]);
                    }
                }

                float tm0 = -1e30f, tm1 = -1e30f;
#pragma unroll
                for (int nt = 0; nt < 8; nt++) {
                    tm0 = fmaxf(tm0, fmaxf(s[nt][0], s[nt][1]));
                    tm1 = fmaxf(tm1, fmaxf(s[nt][2], s[nt][3]));
                }
                tm0 = fmaxf(tm0, __shfl_xor_sync(0xffffffffu, tm0, 1));
                tm0 = fmaxf(tm0, __shfl_xor_sync(0xffffffffu, tm0, 2));
                tm1 = fmaxf(tm1, __shfl_xor_sync(0xffffffffu, tm1, 1));
                tm1 = fmaxf(tm1, __shfl_xor_sync(0xffffffffu, tm1, 2));
                float mn0 = fmaxf(m0, tm0), mn1 = fmaxf(m1, tm1);
                float al0 = __expf(m0 - mn0), al1 = __expf(m1 - mn1);
                m0 = mn0; m1 = mn1;

                unsigned pa[4][4];
                float sum0 = 0.f, sum1 = 0.f;
#pragma unroll
                for (int nt = 0; nt < 8; nt++) {
                    float p0 = __expf(s[nt][0] - mn0);
                    float p1 = __expf(s[nt][1] - mn0);
                    float p2 = __expf(s[nt][2] - mn1);
                    float p3 = __expf(s[nt][3] - mn1);
                    sum0 += p0 + p1;
                    sum1 += p2 + p3;
                    unsigned lo = h2u(__float22half2_rn(make_float2(p0, p1)));
                    unsigned hi = h2u(__float22half2_rn(make_float2(p2, p3)));
                    int kt = nt >> 1;
                    if ((nt & 1) == 0) { pa[kt][0] = lo; pa[kt][1] = hi; }
                    else               { pa[kt][2] = lo; pa[kt][3] = hi; }
                }
                sum0 += __shfl_xor_sync(0xffffffffu, sum0, 1);
                sum0 += __shfl_xor_sync(0xffffffffu, sum0, 2);
                sum1 += __shfl_xor_sync(0xffffffffu, sum1, 1);
                sum1 += __shfl_xor_sync(0xffffffffu, sum1, 2);
                l0 = l0 * al0 + sum0;
                l1 = l1 * al1 + sum1;
#pragma unroll
                for (int nt = 0; nt < 16; nt++) {
                    o[nt][0] *= al0; o[nt][1] *= al0;
                    o[nt][2] *= al1; o[nt][3] *= al1;
                }

#pragma unroll
                for (int kt = 0; kt < 4; kt++) {
                    unsigned vb[8][4];
#pragma unroll
                    for (int j = 0; j < 8; j++)
                        ldsm4(vb[j][0], vb[j][1], vb[j][2], vb[j][3],
                              voff + ((j * 16 + bl_row) * AQ + st * 32 + kt * 8 + bl_colu) * 4);
#pragma unroll
                    for (int j = 0; j < 8; j++) {
                        mma_f16(o[2*j][0], o[2*j][1], o[2*j][2], o[2*j][3],
                                pa[kt][0], pa[kt][1], pa[kt][2], pa[kt][3], vb[j][0], vb[j][1]);
                        mma_f16(o[2*j+1][0], o[2*j+1][1], o[2*j+1][2], o[2*j+1][3],
                                pa[kt][0], pa[kt][1], pa[kt][2], pa[kt][3], vb[j][2], vb[j][3]);
                    }
                }
            }
        }

        if (ph == 0) {
            // Stage normalized ref output in GLOBAL memory (frees 32 regs vs stash).
            // Same thread re-reads the same addresses in the final epilogue.
            float inv0 = 1.f / l0, inv1 = 1.f / l1;
            int row0 = q0 + warp * 16 + g;
            int row1 = row0 + 8;
#pragma unroll
            for (int nt = 0; nt < 16; nt++) {
                int col = h * DH + nt * 8 + 2 * l;
                *(__half2*)(Outh + (size_t)row0 * DIM + col) =
                    __float22half2_rn(make_float2(o[nt][0] * inv0, o[nt][1] * inv0));
                *(__half2*)(Outh + (size_t)row1 * DIM + col) =
                    __float22half2_rn(make_float2(o[nt][2] * inv1, o[nt][3] * inv1));
            }
        }
    }

    float inv0 = 1.f / l0, inv1 = 1.f / l1;
    int row0 = q0 + warp * 16 + g;
    int row1 = row0 + 8;
#pragma unroll
    for (int nt = 0; nt < 16; nt++) {
        int col = h * DH + nt * 8 + 2 * l;
        __half2* p0 = (__half2*)(Outh + (size_t)row0 * DIM + col);
        __half2* p1 = (__half2*)(Outh + (size_t)row1 * DIM + col);
        float2 r0 = __half22float2(*p0);
        float2 r1 = __half22float2(*p1);
        *p0 = __float22half2_rn(
            make_float2(r0.x + o[nt][0] * inv0, r0.y + o[nt][1] * inv0));
        *p1 = __float22half2_rn(
            make_float2(r1.x + o[nt][2] * inv1, r1.y + o[nt][3] * inv1));
    }
}

// ---------------- launch ----------------
extern "C" void kernel_launch(void* const* d_in, const int* in_sizes, int n_in,
                              void* d_out, int out_size)
{
    const float* hs   = (const float*)d_in[0];
    const float* rhs  = (const float*)d_in[1];
    const float* rcos = (const float*)d_in[2];
    const float* rsin = (const float*)d_in[3];
    const float* Wq   = (const float*)d_in[4];
    const float* bq   = (const float*)d_in[5];
    const float* Wk   = (const float*)d_in[6];
    const float* bk   = (const float*)d_in[7];
    const float* Wv   = (const float*)d_in[8];
    const float* bv   = (const float*)d_in[9];
    const float* Wkr  = (const float*)d_in[10];
    const float* bkr  = (const float*)d_in[11];
    const float* Wvr  = (const float*)d_in[12];
    const float* bvr  = (const float*)d_in[13];
    const float* Wo   = (const float*)d_in[14];
    const float* bo   = (const float*)d_in[15];
    const float* gq   = (const float*)d_in[16];
    const float* gk   = (const float*)d_in[17];
    float* out = (float*)d_out;

    __half *hsh, *rhsh, *wth, *qlh, *klh, *krlh, *qh, *qroph, *kh, *vth, *krh, *vrth, *attnh;
    cudaGetSymbolAddress((void**)&hsh,   g_hsh);
    cudaGetSymbolAddress((void**)&rhsh,  g_rhsh);
    cudaGetSymbolAddress((void**)&wth,   g_wth);
    cudaGetSymbolAddress((void**)&qlh,   g_qlh);
    cudaGetSymbolAddress((void**)&klh,   g_klh);
    cudaGetSymbolAddress((void**)&krlh,  g_krlh);
    cudaGetSymbolAddress((void**)&qh,    g_qh);
    cudaGetSymbolAddress((void**)&qroph, g_qroph);
    cudaGetSymbolAddress((void**)&kh,    g_kh);
    cudaGetSymbolAddress((void**)&vth,   g_vth);
    cudaGetSymbolAddress((void**)&krh,   g_krh);
    cudaGetSymbolAddress((void**)&vrth,  g_vrth);
    cudaGetSymbolAddress((void**)&attnh, g_attnh);

    cudaFuncSetAttribute(attn_fused,
                         cudaFuncAttributeMaxDynamicSharedMemorySize, ATT_SMEM);

    const float scale = 0.08838834764831845f;  // 1/sqrt(128)
    const size_t NW = (size_t)DIM * DIM;
    const int NT = T_LEN * DIM, NR = TR_LEN * DIM;

    // ---- prep: weight transposes + activation cvt in one launch ----
    Src6 wsrc;
    wsrc.p[0] = Wq; wsrc.p[1] = Wk; wsrc.p[2] = Wv;
    wsrc.p[3] = Wkr; wsrc.p[4] = Wvr; wsrc.p[5] = Wo;
    prep<<<TR_BLKS + NT / 1024 + NR / 1024, 256>>>(wsrc, wth, hs, hsh, NT, rhs, rhsh);

    // ---- all 5 projections in ONE launch; q/k half, V directly transposed half ----
    GemmJob pj;
    pj.W[0] = wth + 0 * NW; pj.b[0] = bq;  pj.C[0] = qlh;  pj.mode[0] = 1;
    pj.W[1] = wth + 1 * NW; pj.b[1] = bk;  pj.C[1] = klh;  pj.mode[1] = 1;
    pj.W[2] = wth + 2 * NW; pj.b[2] = bv;  pj.C[2] = vth;  pj.mode[2] = 2;
    pj.W[3] = wth + 3 * NW; pj.b[3] = bkr; pj.C[3] = krlh; pj.mode[3] = 1;
    pj.W[4] = wth + 4 * NW; pj.b[4] = bvr; pj.C[4] = vrth; pj.mode[4] = 2;
    gemm_f16_j<<<3 * 384 + 2 * 96, 256, GEMM_SMEM>>>(hsh, rhsh, pj, 3);

    // ---- unified norm stage (one launch) ----
    norm_all<<<2 * T_LEN + TR_LEN, 256>>>(qlh, klh, krlh, gq, gk, rcos, rsin,
                                          qh, qroph, kh, krh, scale);

    // ---- fused attention (ref + main), half output ----
    dim3 attn_grid(T_LEN / 128, NH);  // (32, 12)
    attn_fused<<<attn_grid, 256, ATT_SMEM>>>(qh, krh, vrth, TR_LEN,
                                             qroph, kh, vth, T_LEN, attnh);

    // ---- output projection (same kernel, nMain=1, float out) ----
    GemmJob po;
    po.W[0] = wth + 5 * NW; po.b[0] = bo; po.C[0] = out; po.mode[0] = 0;
    po.W[1] = po.W[0]; po.b[1] = po.b[0]; po.C[1] = out; po.mode[1] = 0;
    po.W[2] = po.W[0]; po.b[2] = po.b[0]; po.C[2] = out; po.mode[2] = 0;
    po.W[3] = po.W[0]; po.b[3] = po.b[0]; po.C[3] = out; po.mode[3] = 0;
    po.W[4] = po.W[0]; po.b[4] = po.b[0]; po.C[4] = out; po.mode[4] = 0;
    gemm_f16_j<<<384, 256, GEMM_SMEM>>>(attnh, attnh, po, 1);
}